// round 10
// baseline (speedup 1.0000x reference)
#include <cuda_runtime.h>
#include <cuda_bf16.h>
#include <cuda_fp16.h>
#include <cstdint>
#include <math.h>

#define Bdim 2
#define Tdim 2048
#define Cdim 768
#define Hdim 12
#define Ddim 64
#define Ldim 6
#define Vdim 50257
#define Mdim (Bdim*Tdim)      /* 4096 */
#define C3   (3*Cdim)         /* 2304 */
#define Fdim (4*Cdim)         /* 3072 */

// ===================== device scratch (no allocations) ======================
__device__ float g_h  [Mdim*Cdim];
__device__ float g_rowloss[Mdim];

__device__ __half g_wqkv_h[Ldim*C3*Cdim];
__device__ __half g_wff1_h[Ldim*Fdim*Cdim];
__device__ __half g_wff2_h[Ldim*Cdim*Fdim];
__device__ __half g_wlm_h[(size_t)Vdim*Cdim];
__device__ __half g_xn_hi[Mdim*Cdim],  g_xn_lo[Mdim*Cdim];
__device__ __half g_ffh_hi[Mdim*Fdim], g_ffh_lo[Mdim*Fdim];
__device__ __half g_ah_h[Mdim*Cdim];
__device__ __half g_qkv_hi[Mdim*C3],   g_qkv_lo[Mdim*C3];

// ===================== asm helpers (baseline sm_80+ ISA) ====================
__device__ __forceinline__ uint32_t smem_to_u32(const void* p) {
    uint32_t a;
    asm("{ .reg .u64 t; cvta.to.shared.u64 t, %1; cvt.u32.u64 %0, t; }" : "=r"(a) : "l"(p));
    return a;
}
__device__ __forceinline__ void cp_async16(uint32_t dst, const void* src){
    asm volatile("cp.async.cg.shared.global [%0], [%1], 16;" :: "r"(dst), "l"(src));
}
#define CP_COMMIT() asm volatile("cp.async.commit_group;" ::: "memory")
#define CP_WAIT0()  asm volatile("cp.async.wait_group 0;" ::: "memory")

__device__ __forceinline__ void ldsm_x4(uint32_t* r, uint32_t addr){
    asm volatile("ldmatrix.sync.aligned.m8n8.x4.shared.b16 {%0,%1,%2,%3}, [%4];"
        : "=r"(r[0]), "=r"(r[1]), "=r"(r[2]), "=r"(r[3]) : "r"(addr));
}
__device__ __forceinline__ void ldsm_x4_t(uint32_t* r, uint32_t addr){
    asm volatile("ldmatrix.sync.aligned.m8n8.x4.trans.shared.b16 {%0,%1,%2,%3}, [%4];"
        : "=r"(r[0]), "=r"(r[1]), "=r"(r[2]), "=r"(r[3]) : "r"(addr));
}
__device__ __forceinline__ void mma_f16(float* d, const uint32_t* a,
                                        uint32_t b0, uint32_t b1){
    asm volatile("mma.sync.aligned.m16n8k16.row.col.f32.f16.f16.f32 "
        "{%0,%1,%2,%3}, {%4,%5,%6,%7}, {%8,%9}, {%0,%1,%2,%3};"
        : "+f"(d[0]), "+f"(d[1]), "+f"(d[2]), "+f"(d[3])
        : "r"(a[0]), "r"(a[1]), "r"(a[2]), "r"(a[3]), "r"(b0), "r"(b1));
}
__device__ __forceinline__ uint32_t pack_half2(float lo, float hi){
    uint32_t r;
    asm("cvt.rn.f16x2.f32 %0, %1, %2;" : "=r"(r) : "f"(hi), "f"(lo));
    return r;
}

// ===================== reductions ===========================================
__device__ __forceinline__ float blockReduceMax(float v){
    __shared__ float sh[8];
    int lid = threadIdx.x & 31, wid = threadIdx.x >> 5;
    #pragma unroll
    for (int o = 16; o > 0; o >>= 1) v = fmaxf(v, __shfl_xor_sync(0xffffffffu, v, o));
    if (lid == 0) sh[wid] = v;
    __syncthreads();
    v = sh[lid & 7];
    #pragma unroll
    for (int o = 4; o > 0; o >>= 1) v = fmaxf(v, __shfl_xor_sync(0xffffffffu, v, o));
    __syncthreads();
    return v;
}
__device__ __forceinline__ float blockReduceSum(float v){
    __shared__ float sh[8];
    int lid = threadIdx.x & 31, wid = threadIdx.x >> 5;
    #pragma unroll
    for (int o = 16; o > 0; o >>= 1) v += __shfl_xor_sync(0xffffffffu, v, o);
    if (lid == 0) sh[wid] = v;
    __syncthreads();
    v = sh[lid & 7];
    #pragma unroll
    for (int o = 4; o > 0; o >>= 1) v += __shfl_xor_sync(0xffffffffu, v, o);
    __syncthreads();
    return v;
}

// ===================== small kernels ========================================
__global__ void embed_k(const int* __restrict__ x,
                        const float* __restrict__ wte,
                        const float* __restrict__ wpe){
    int i = blockIdx.x * blockDim.x + threadIdx.x;
    if (i >= Mdim * Cdim) return;
    int c  = i % Cdim;
    int bt = i / Cdim;
    int t  = bt % Tdim;
    g_h[i] = wte[(size_t)x[bt] * Cdim + c] + wpe[(size_t)t * Cdim + c];
}

__global__ void cvt_h_k(const float* __restrict__ in, __half* __restrict__ o, long n){
    long stride = (long)gridDim.x * blockDim.x * 4;
    for (long i = ((long)blockIdx.x * blockDim.x + threadIdx.x) * 4; i < n; i += stride){
        float4 v = *(const float4*)(in + i);
        uint2 w;
        w.x = pack_half2(v.x, v.y);
        w.y = pack_half2(v.z, v.w);
        *(uint2*)(o + i) = w;
    }
}

__global__ void ln_k(const float* __restrict__ in,
                     const float* __restrict__ w,
                     const float* __restrict__ b,
                     __half* __restrict__ ohi,
                     __half* __restrict__ olo){
    int row = blockIdx.x, tid = threadIdx.x;
    const float* xp = in + (size_t)row * Cdim;
    float v[3], s = 0.f, ss = 0.f;
    #pragma unroll
    for (int i = 0; i < 3; i++){
        v[i] = xp[tid + i * 256];
        s += v[i]; ss += v[i] * v[i];
    }
    s  = blockReduceSum(s);
    ss = blockReduceSum(ss);
    float mean = s * (1.f / Cdim);
    float var  = ss * (1.f / Cdim) - mean * mean;
    float rstd = rsqrtf(var + 1e-5f);
    #pragma unroll
    for (int i = 0; i < 3; i++){
        int c = tid + i * 256;
        float y = (v[i] - mean) * rstd * w[c] + b[c];
        __half h = __float2half_rn(y);
        ohi[(size_t)row * Cdim + c] = h;
        olo[(size_t)row * Cdim + c] = __float2half_rn(y - __half2float(h));
    }
}

// ===================== fp16 2-term split GEMM (mma.sync) ====================
// C[M,N] = (Ahi+Alo)[M,K] @ B[N,K]^T.  A hi/lo fp16, B single fp16.
// N must be a multiple of 128. Split-K via gridDim.z (mode 2 only).
// modes: 1: relu(acc+bias)->hi/lo | 2: out_f atomicAdd(acc[+bias if z==0]) | 4: (acc+bias)->hi/lo
#define MAT_B   10240            /* 128 rows * 80 bytes */
#define STG_B   (3*MAT_B)
#define GT_SMEM (2*STG_B)        /* 61440 bytes */

__global__ __launch_bounds__(256, 2) void gemm_tc_k(
        const __half* __restrict__ Ahi, const __half* __restrict__ Alo,
        const __half* __restrict__ Bm,
        const float* __restrict__ bias,
        float* __restrict__ out_f,
        __half* __restrict__ out_hi, __half* __restrict__ out_lo,
        int N, int K, int mode){
    extern __shared__ char smem[];
    uint32_t sbase = smem_to_u32(smem);
    int tid = threadIdx.x, wid = tid >> 5, lane = tid & 31;
    int warpRow = wid >> 2, warpCol = wid & 3;

    long row0 = (long)blockIdx.x * 128;
    long n0   = (long)blockIdx.y * 128;
    int kspan = K / (int)gridDim.z;
    long kbase = (long)blockIdx.z * kspan;
    int nIter = kspan >> 5;

    float acc[4][4][4];
    #pragma unroll
    for (int i = 0; i < 4; i++)
        #pragma unroll
        for (int j = 0; j < 4; j++)
            #pragma unroll
            for (int q = 0; q < 4; q++) acc[i][j][q] = 0.f;

    auto issue = [&](int it){
        if (it >= nIter) return;
        long k0 = kbase + ((long)it << 5);
        uint32_t stg = sbase + (uint32_t)(it & 1) * STG_B;
        #pragma unroll
        for (int j = 0; j < 6; j++){
            int c   = tid + j * 256;          // 0..1535
            int mat = c >> 9;                  // 0:Ahi 1:Alo 2:B
            int id  = c & 511;
            int row = id >> 2;
            int c8  = (id & 3) << 3;
            const __half* src;
            if (mat < 2){
                src = (mat == 0 ? Ahi : Alo) + (row0 + row) * (long)K + k0 + c8;
            } else {
                src = Bm + (n0 + row) * (long)K + k0 + c8;
            }
            uint32_t dst = stg + (uint32_t)(mat * MAT_B + row * 80 + c8 * 2);
            cp_async16(dst, src);
        }
        CP_COMMIT();
    };

    issue(0);
    for (int it = 0; it < nIter; it++){
        CP_WAIT0();
        __syncthreads();        // data(it) visible + all warps done with compute(it-1)
        issue(it + 1);          // safely overwrites buffer of it-1

        uint32_t stg = sbase + (uint32_t)(it & 1) * STG_B;
        uint32_t aHi = stg;
        uint32_t aLo = stg + MAT_B;
        uint32_t bS  = stg + 2*MAT_B;
        uint32_t rsel = (uint32_t)(lane & 15) * 80 + (uint32_t)(lane >> 4) * 16;

        #pragma unroll
        for (int ks = 0; ks < 32; ks += 16){
            uint32_t bf[2][4];
            #pragma unroll
            for (int nj = 0; nj < 2; nj++){
                uint32_t off = (uint32_t)((warpCol*32 + nj*16) * 80 + ks*2) + rsel;
                ldsm_x4(bf[nj], bS + off);
            }
            #pragma unroll
            for (int mi = 0; mi < 4; mi++){
                uint32_t ah[4], al[4];
                uint32_t off = (uint32_t)((warpRow*64 + mi*16) * 80 + ks*2) + rsel;
                ldsm_x4(ah, aHi + off);
                ldsm_x4(al, aLo + off);
                #pragma unroll
                for (int ni = 0; ni < 4; ni++){
                    int nj = ni >> 1, w = ni & 1;
                    mma_f16(acc[mi][ni], ah, bf[nj][w], bf[nj][w+2]);
                    mma_f16(acc[mi][ni], al, bf[nj][w], bf[nj][w+2]);
                }
            }
        }
    }
    __syncthreads();

    bool addBias = (blockIdx.z == 0);
    #pragma unroll
    for (int mi = 0; mi < 4; mi++){
        long r0 = row0 + warpRow*64 + mi*16 + (lane >> 2);
        #pragma unroll
        for (int ni = 0; ni < 4; ni++){
            long c0 = n0 + warpCol*32 + ni*8 + (lane & 3)*2;
            float b0 = addBias ? bias[c0]     : 0.f;
            float b1 = addBias ? bias[c0 + 1] : 0.f;
            #pragma unroll
            for (int half = 0; half < 2; half++){
                long r  = r0 + half*8;
                long oi = r * (long)N + c0;
                float v0 = acc[mi][ni][half*2]     + b0;
                float v1 = acc[mi][ni][half*2 + 1] + b1;
                if (mode == 2){
                    atomicAdd(out_f + oi,     v0);
                    atomicAdd(out_f + oi + 1, v1);
                } else {
                    if (mode == 1){
                        v0 = fmaxf(v0, 0.f);
                        v1 = fmaxf(v1, 0.f);
                    }
                    float h0 = __half2float(__float2half_rn(v0));
                    float h1 = __half2float(__float2half_rn(v1));
                    *(uint32_t*)(out_hi + oi) = pack_half2(v0, v1);
                    *(uint32_t*)(out_lo + oi) = pack_half2(v0 - h0, v1 - h1);
                }
            }
        }
    }
}

// ===================== fp16 single-term GEMM (lm_head) ======================
#define FH_MAT  10240
#define FH_STG  (2*FH_MAT)
#define FH_SMEM (2*FH_STG)       /* 40960 */

__global__ __launch_bounds__(256, 2) void gemm_f16_k(
        const __half* __restrict__ A, const __half* __restrict__ Bm,
        float* __restrict__ out_f, int N, int K){
    extern __shared__ char smem[];
    uint32_t sbase = smem_to_u32(smem);
    int tid = threadIdx.x, wid = tid >> 5, lane = tid & 31;
    int warpRow = wid >> 2, warpCol = wid & 3;

    long row0 = (long)blockIdx.x * 128;
    long n0   = (long)blockIdx.y * 128;
    int nIter = K >> 5;

    float acc[4][4][4];
    #pragma unroll
    for (int i = 0; i < 4; i++)
        #pragma unroll
        for (int j = 0; j < 4; j++)
            #pragma unroll
            for (int q = 0; q < 4; q++) acc[i][j][q] = 0.f;

    auto issue = [&](int it){
        if (it >= nIter) return;
        int k0 = it << 5;
        uint32_t stg = sbase + (uint32_t)(it & 1) * FH_STG;
        #pragma unroll
        for (int j = 0; j < 4; j++){
            int c   = tid + j * 256;
            int mat = c >> 9;
            int id  = c & 511;
            int row = id >> 2;
            int c8  = (id & 3) << 3;
            const __half* src;
            if (mat == 0){
                src = A + (row0 + row) * (long)K + k0 + c8;
            } else {
                long br = n0 + row; if (br >= N) br = 0;
                src = Bm + br * (long)K + k0 + c8;
            }
            uint32_t dst = stg + (uint32_t)(mat * FH_MAT + row * 80 + c8 * 2);
            cp_async16(dst, src);
        }
        CP_COMMIT();
    };

    issue(0);
    for (int it = 0; it < nIter; it++){
        CP_WAIT0();
        __syncthreads();
        issue(it + 1);

        uint32_t stg = sbase + (uint32_t)(it & 1) * FH_STG;
        uint32_t aS = stg;
        uint32_t bS = stg + FH_MAT;
        uint32_t rsel = (uint32_t)(lane & 15) * 80 + (uint32_t)(lane >> 4) * 16;

        #pragma unroll
        for (int ks = 0; ks < 32; ks += 16){
            uint32_t bf[2][4];
            #pragma unroll
            for (int nj = 0; nj < 2; nj++){
                uint32_t off = (uint32_t)((warpCol*32 + nj*16) * 80 + ks*2) + rsel;
                ldsm_x4(bf[nj], bS + off);
            }
            #pragma unroll
            for (int mi = 0; mi < 4; mi++){
                uint32_t af[4];
                uint32_t off = (uint32_t)((warpRow*64 + mi*16) * 80 + ks*2) + rsel;
                ldsm_x4(af, aS + off);
                #pragma unroll
                for (int ni = 0; ni < 4; ni++){
                    int nj = ni >> 1, w = ni & 1;
                    mma_f16(acc[mi][ni], af, bf[nj][w], bf[nj][w+2]);
                }
            }
        }
    }

    // scalar stores: logits base pointer may be only 4B-aligned (out+1)
    #pragma unroll
    for (int mi = 0; mi < 4; mi++){
        long r0 = row0 + warpRow*64 + mi*16 + (lane >> 2);
        #pragma unroll
        for (int ni = 0; ni < 4; ni++){
            long c0 = n0 + warpCol*32 + ni*8 + (lane & 3)*2;
            #pragma unroll
            for (int half = 0; half < 2; half++){
                long r = r0 + half*8;
                #pragma unroll
                for (int e = 0; e < 2; e++){
                    long n = c0 + e;
                    if (n < N)
                        out_f[r * (long)N + n] = acc[mi][ni][half*2 + e];
                }
            }
        }
    }
}

// ===================== flash attention (fp16 mma, hi/lo split) ==============
#define FA_QB    (128*144)
#define FA_KVMAT (64*144)
#define FA_STGB  (4*FA_KVMAT)
#define FA_SMEM  (2*FA_QB + 2*FA_STGB)   /* 110592 */

__global__ __launch_bounds__(256, 2) void flash_k(
        const __half* __restrict__ qkvh,
        const __half* __restrict__ qkvl){
    extern __shared__ char smem[];
    uint32_t sb = smem_to_u32(smem);
    uint32_t Qh = sb, Ql = sb + FA_QB;
    uint32_t kvb = sb + 2*FA_QB;

    int tid = threadIdx.x, wid = tid >> 5, lane = tid & 31;
    int g = lane >> 2, tq = lane & 3;
    int qb = (int)gridDim.x - 1 - (int)blockIdx.x;
    int bh = blockIdx.y; int bq = bh / Hdim, head = bh % Hdim;
    int q0 = qb * 128;
    long rowbase = (long)bq * Tdim;

    #pragma unroll
    for (int j = 0; j < 8; j++){
        int id = tid + j*256;
        int mat = id >> 10, rem = id & 1023;
        int row = rem >> 3, c8 = (rem & 7) << 3;
        const __half* src = (mat ? qkvl : qkvh)
            + (rowbase + q0 + row)*(long)C3 + head*Ddim + c8;
        cp_async16((mat ? Ql : Qh) + (uint32_t)(row*144 + c8*2), src);
    }

    int nkv = 2*qb + 2;
    auto issue = [&](int j){
        if (j >= nkv) return;
        int s0 = j * 64;
        uint32_t stg = kvb + (uint32_t)(j & 1) * FA_STGB;
        #pragma unroll
        for (int jj = 0; jj < 8; jj++){
            int id = tid + jj*256;
            int mat = id >> 9, rem = id & 511;
            int row = rem >> 3, c8 = (rem & 7) << 3;
            const __half* base = (mat & 1) ? qkvl : qkvh;
            int coff = (mat < 2) ? Cdim : 2*Cdim;
            const __half* src = base
                + (rowbase + s0 + row)*(long)C3 + coff + head*Ddim + c8;
            cp_async16(stg + (uint32_t)(mat*FA_KVMAT + row*144 + c8*2), src);
        }
        CP_COMMIT();
    };

    float mrow[2] = {-1e30f, -1e30f};
    float lrow[2] = {0.f, 0.f};
    float oacc[8][4];
    #pragma unroll
    for (int i = 0; i < 8; i++)
        #pragma unroll
        for (int e = 0; e < 4; e++) oacc[i][e] = 0.f;

    int t0w = q0 + wid*16;
    uint32_t rsel16 = (uint32_t)(lane & 15)*144 + (uint32_t)(lane >> 4)*16;
    int vtsel = lane >> 3, vrt = lane & 7;
    uint32_t vrow_off = ((vtsel >> 1) ? 8u : 0u) + (uint32_t)vrt;
    uint32_t vcol_off = (vtsel & 1) ? 16u : 0u;

    issue(0);
    for (int j = 0; j < nkv; j++){
        CP_WAIT0();
        __syncthreads();        // data(j) visible + all warps done with compute(j-1)
        issue(j + 1);

        int s0 = j * 64;
        if (s0 <= t0w + 15){
            uint32_t stg = kvb + (uint32_t)(j & 1) * FA_STGB;
            uint32_t Kh = stg, Kl = stg + FA_KVMAT;
            uint32_t Vh = stg + 2*FA_KVMAT, Vl = stg + 3*FA_KVMAT;

            float S[8][4];
            #pragma unroll
            for (int i = 0; i < 8; i++)
                #pragma unroll
                for (int e = 0; e < 4; e++) S[i][e] = 0.f;

            #pragma unroll
            for (int dc = 0; dc < 4; dc++){
                uint32_t aoff = (uint32_t)(wid*16)*144 + (uint32_t)dc*32 + rsel16;
                uint32_t ah[4], al[4];
                ldsm_x4(ah, Qh + aoff);
                ldsm_x4(al, Ql + aoff);
                #pragma unroll
                for (int ng = 0; ng < 4; ng++){
                    uint32_t boff = (uint32_t)(ng*16)*144 + (uint32_t)dc*32 + rsel16;
                    uint32_t kh[4], kl[4];
                    ldsm_x4(kh, Kh + boff);
                    ldsm_x4(kl, Kl + boff);
                    #pragma unroll
                    for (int w = 0; w < 2; w++){
                        mma_f16(S[ng*2+w], ah, kh[w], kh[w+2]);
                        mma_f16(S[ng*2+w], ah, kl[w], kl[w+2]);
                        mma_f16(S[ng*2+w], al, kh[w], kh[w+2]);
                    }
                }
            }

            bool needMask = (s0 + 63 > t0w);
            #pragma unroll
            for (int ns = 0; ns < 8; ns++)
                #pragma unroll
                for (int e = 0; e < 4; e++){
                    float v = S[ns][e] * 0.125f;
                    if (needMask){
                        int t = t0w + g + (e >> 1)*8;
                        int s = s0 + ns*8 + tq*2 + (e & 1);
                        if (s > t) v = -1e30f;
                    }
                    S[ns][e] = v;
                }

            #pragma unroll
            for (int r = 0; r < 2; r++){
                float mx = -1e30f;
                #pragma unroll
                for (int ns = 0; ns < 8; ns++)
                    mx = fmaxf(mx, fmaxf(S[ns][r*2], S[ns][r*2+1]));
                mx = fmaxf(mx, __shfl_xor_sync(0xffffffffu, mx, 1));
                mx = fmaxf(mx, __shfl_xor_sync(0xffffffffu, mx, 2));
                float mnew = fmaxf(mrow[r], mx);
                float corr = __expf(mrow[r] - mnew);
                mrow[r] = mnew;
                float lsum = 0.f;
                #pragma unroll
                for (int ns = 0; ns < 8; ns++){
                    float p0 = __expf(S[ns][r*2]   - mnew);
                    float p1 = __expf(S[ns][r*2+1] - mnew);
                    S[ns][r*2] = p0; S[ns][r*2+1] = p1;
                    lsum += p0 + p1;
                }
                lsum += __shfl_xor_sync(0xffffffffu, lsum, 1);
                lsum += __shfl_xor_sync(0xffffffffu, lsum, 2);
                lrow[r] = lrow[r]*corr + lsum;
                #pragma unroll
                for (int dt = 0; dt < 8; dt++){
                    oacc[dt][r*2]   *= corr;
                    oacc[dt][r*2+1] *= corr;
                }
            }

            #pragma unroll
            for (int sc = 0; sc < 4; sc++){
                uint32_t ph[4], pl[4];
                #pragma unroll
                for (int half = 0; half < 2; half++){
                    int ns = sc*2 + half;
                    float v0 = S[ns][0], v1 = S[ns][1], v2 = S[ns][2], v3 = S[ns][3];
                    float h0 = __half2float(__float2half_rn(v0));
                    float h1 = __half2float(__float2half_rn(v1));
                    float h2 = __half2float(__float2half_rn(v2));
                    float h3 = __half2float(__float2half_rn(v3));
                    ph[half*2+0] = pack_half2(v0, v1);
                    ph[half*2+1] = pack_half2(v2, v3);
                    pl[half*2+0] = pack_half2(v0 - h0, v1 - h1);
                    pl[half*2+1] = pack_half2(v2 - h2, v3 - h3);
                }
                uint32_t vbase = (uint32_t)((sc*16 + vrow_off)*144) + vcol_off;
                #pragma unroll
                for (int dg = 0; dg < 4; dg++){
                    uint32_t vh_[4], vl_[4];
                    ldsm_x4_t(vh_, Vh + vbase + (uint32_t)dg*32);
                    ldsm_x4_t(vl_, Vl + vbase + (uint32_t)dg*32);
                    #pragma unroll
                    for (int w = 0; w < 2; w++){
                        int dt = dg*2 + w;
                        mma_f16(oacc[dt], ph, vh_[w], vh_[w+2]);
                        mma_f16(oacc[dt], ph, vl_[w], vl_[w+2]);
                        mma_f16(oacc[dt], pl, vh_[w], vh_[w+2]);
                    }
                }
            }
        }
    }

    #pragma unroll
    for (int r = 0; r < 2; r++){
        float inv = 1.f / lrow[r];
        long t = (long)t0w + g + r*8;
        float* hp = g_h + (rowbase + t)*(long)Cdim + head*Ddim;
        #pragma unroll
        for (int dt = 0; dt < 8; dt++){
            float2* p = (float2*)(hp + dt*8 + tq*2);
            float2 v = *p;
            v.x += oacc[dt][r*2]   * inv;
            v.y += oacc[dt][r*2+1] * inv;
            *p = v;
        }
    }
}

// ===================== cross-entropy (single-pass online) ===================
__global__ void loss_row_k(const float* __restrict__ logits,
                           const int* __restrict__ target){
    int row = blockIdx.x, tid = threadIdx.x;
    const float* p = logits + (size_t)row * Vdim;
    float m = -1e30f, s = 0.f;
    for (int i = tid; i < Vdim; i += 256){
        float x = p[i];
        if (x > m){
            s = s * __expf(m - x) + 1.f;
            m = x;
        } else {
            s += __expf(x - m);
        }
    }
    float mg = blockReduceMax(m);
    s *= __expf(m - mg);
    float tot = blockReduceSum(s);
    if (tid == 0){
        float lse = logf(tot) + mg;
        g_rowloss[row] = lse - p[target[row]];
    }
}
__global__ void loss_reduce_k(float* out){
    float s = 0.f;
    for (int i = threadIdx.x; i < Mdim; i += 256) s += g_rowloss[i];
    s = blockReduceSum(s);
    if (threadIdx.x == 0) out[0] = s / (float)Mdim;
}

// ===================== launch ===============================================
extern "C" void kernel_launch(void* const* d_in, const int* in_sizes, int n_in,
                              void* d_out, int out_size){
    const int*   x      = (const int*)  d_in[0];
    const int*   target = (const int*)  d_in[1];
    const float* wte    = (const float*)d_in[2];
    const float* wpe    = (const float*)d_in[3];
    const float* ln1_w  = (const float*)d_in[4];
    const float* ln1_b  = (const float*)d_in[5];
    const float* attn_w = (const float*)d_in[6];
    const float* attn_b = (const float*)d_in[7];
    const float* ln2_w  = (const float*)d_in[8];
    const float* ln2_b  = (const float*)d_in[9];
    const float* ff1_w  = (const float*)d_in[10];
    const float* ff1_b  = (const float*)d_in[11];
    const float* ff2_w  = (const float*)d_in[12];
    const float* ff2_b  = (const float*)d_in[13];
    const float* lm_w   = (const float*)d_in[14];

    float* out = (float*)d_out;
    bool has_loss = ((long long)out_size == (long long)Mdim * Vdim + 1);
    float* logits = has_loss ? out + 1 : out;

    cudaFuncSetAttribute(gemm_tc_k,  cudaFuncAttributeMaxDynamicSharedMemorySize, GT_SMEM);
    cudaFuncSetAttribute(gemm_f16_k, cudaFuncAttributeMaxDynamicSharedMemorySize, FH_SMEM);
    cudaFuncSetAttribute(flash_k,    cudaFuncAttributeMaxDynamicSharedMemorySize, FA_SMEM);

    float* ph;
    cudaGetSymbolAddress((void**)&ph, g_h);
    __half *wqk,*wf1,*wf2,*wlm;
    __half *xnh,*xnl,*fhh,*fhl,*qvh,*qvl,*ah_h;
    cudaGetSymbolAddress((void**)&wqk, g_wqkv_h);
    cudaGetSymbolAddress((void**)&wf1, g_wff1_h);
    cudaGetSymbolAddress((void**)&wf2, g_wff2_h);
    cudaGetSymbolAddress((void**)&wlm, g_wlm_h);
    cudaGetSymbolAddress((void**)&xnh, g_xn_hi);   cudaGetSymbolAddress((void**)&xnl, g_xn_lo);
    cudaGetSymbolAddress((void**)&fhh, g_ffh_hi);  cudaGetSymbolAddress((void**)&fhl, g_ffh_lo);
    cudaGetSymbolAddress((void**)&ah_h, g_ah_h);
    cudaGetSymbolAddress((void**)&qvh, g_qkv_hi);  cudaGetSymbolAddress((void**)&qvl, g_qkv_lo);

    cvt_h_k<<<2048, 256>>>(attn_w, wqk, (long)Ldim*C3*Cdim);
    cvt_h_k<<<2048, 256>>>(ff1_w,  wf1, (long)Ldim*Fdim*Cdim);
    cvt_h_k<<<2048, 256>>>(ff2_w,  wf2, (long)Ldim*Cdim*Fdim);
    cvt_h_k<<<4096, 256>>>(lm_w,   wlm, (long)Vdim*Cdim);

    embed_k<<<(Mdim*Cdim + 255)/256, 256>>>(x, wte, wpe);

    for (int l = 0; l < Ldim; l++){
        ln_k<<<Mdim, 256>>>(ph, ln1_w + (size_t)l*Cdim, ln1_b + (size_t)l*Cdim, xnh, xnl);

        gemm_tc_k<<<dim3(Mdim/128, C3/128, 1), 256, GT_SMEM>>>(
            xnh, xnl, wqk + (size_t)l*C3*Cdim,
            attn_b + (size_t)l*C3, nullptr, qvh, qvl, C3, Cdim, 4);

        flash_k<<<dim3(Tdim/128, Bdim*Hdim), 256, FA_SMEM>>>(qvh, qvl);

        ln_k<<<Mdim, 256>>>(ph, ln2_w + (size_t)l*Cdim, ln2_b + (size_t)l*Cdim, xnh, xnl);

        gemm_tc_k<<<dim3(Mdim/128, Fdim/128, 1), 256, GT_SMEM>>>(
            xnh, xnl, wf1 + (size_t)l*Fdim*Cdim,
            ff1_b + (size_t)l*Fdim, nullptr, fhh, fhl, Fdim, Cdim, 1);

        // split-K x2: 384 CTAs (fills the resident slots)
        gemm_tc_k<<<dim3(Mdim/128, Cdim/128, 2), 256, GT_SMEM>>>(
            fhh, fhl, wf2 + (size_t)l*Cdim*Fdim,
            ff2_b + (size_t)l*Cdim, ph, nullptr, nullptr, Cdim, Fdim, 2);
    }

    cvt_h_k<<<2048, 256>>>(ph, ah_h, (long)Mdim*Cdim);

    gemm_f16_k<<<dim3(Mdim/128, (Vdim + 127)/128), 256, FH_SMEM>>>(
        ah_h, wlm, logits, Vdim, Cdim);

    loss_row_k<<<Mdim, 256>>>(logits, target);
    if (has_loss)
        loss_reduce_k<<<1, 256>>>(out);
}

// round 11
// speedup vs baseline: 1.1208x; 1.1208x over previous
#include <cuda_runtime.h>
#include <cuda_bf16.h>
#include <cuda_fp16.h>
#include <cstdint>
#include <math.h>

#define Bdim 2
#define Tdim 2048
#define Cdim 768
#define Hdim 12
#define Ddim 64
#define Ldim 6
#define Vdim 50257
#define Mdim (Bdim*Tdim)      /* 4096 */
#define C3   (3*Cdim)         /* 2304 */
#define Fdim (4*Cdim)         /* 3072 */
#define NPB  393              /* (Vdim+127)/128 logits col-blocks */

// ===================== device scratch (no allocations) ======================
__device__ float g_h  [Mdim*Cdim];
__device__ float g_rowloss[Mdim];
__device__ float g_pmax[(size_t)Mdim*NPB];
__device__ float g_psum[(size_t)Mdim*NPB];

__device__ __half g_wqkv_h[Ldim*C3*Cdim];
__device__ __half g_wff1_h[Ldim*Fdim*Cdim];
__device__ __half g_wff2_h[Ldim*Cdim*Fdim];
__device__ __half g_wlm_h[(size_t)Vdim*Cdim];
__device__ __half g_xn_hi[Mdim*Cdim],  g_xn_lo[Mdim*Cdim];
__device__ __half g_ffh_hi[Mdim*Fdim], g_ffh_lo[Mdim*Fdim];
__device__ __half g_ah_h[Mdim*Cdim];
__device__ __half g_qkv_hi[Mdim*C3],   g_qkv_lo[Mdim*C3];

// ===================== asm helpers (baseline sm_80+ ISA) ====================
__device__ __forceinline__ uint32_t smem_to_u32(const void* p) {
    uint32_t a;
    asm("{ .reg .u64 t; cvta.to.shared.u64 t, %1; cvt.u32.u64 %0, t; }" : "=r"(a) : "l"(p));
    return a;
}
__device__ __forceinline__ void cp_async16(uint32_t dst, const void* src){
    asm volatile("cp.async.cg.shared.global [%0], [%1], 16;" :: "r"(dst), "l"(src));
}
#define CP_COMMIT() asm volatile("cp.async.commit_group;" ::: "memory")
#define CP_WAIT0()  asm volatile("cp.async.wait_group 0;" ::: "memory")

__device__ __forceinline__ void ldsm_x4(uint32_t* r, uint32_t addr){
    asm volatile("ldmatrix.sync.aligned.m8n8.x4.shared.b16 {%0,%1,%2,%3}, [%4];"
        : "=r"(r[0]), "=r"(r[1]), "=r"(r[2]), "=r"(r[3]) : "r"(addr));
}
__device__ __forceinline__ void ldsm_x4_t(uint32_t* r, uint32_t addr){
    asm volatile("ldmatrix.sync.aligned.m8n8.x4.trans.shared.b16 {%0,%1,%2,%3}, [%4];"
        : "=r"(r[0]), "=r"(r[1]), "=r"(r[2]), "=r"(r[3]) : "r"(addr));
}
__device__ __forceinline__ void mma_f16(float* d, const uint32_t* a,
                                        uint32_t b0, uint32_t b1){
    asm volatile("mma.sync.aligned.m16n8k16.row.col.f32.f16.f16.f32 "
        "{%0,%1,%2,%3}, {%4,%5,%6,%7}, {%8,%9}, {%0,%1,%2,%3};"
        : "+f"(d[0]), "+f"(d[1]), "+f"(d[2]), "+f"(d[3])
        : "r"(a[0]), "r"(a[1]), "r"(a[2]), "r"(a[3]), "r"(b0), "r"(b1));
}
__device__ __forceinline__ uint32_t pack_half2(float lo, float hi){
    uint32_t r;
    asm("cvt.rn.f16x2.f32 %0, %1, %2;" : "=r"(r) : "f"(hi), "f"(lo));
    return r;
}

// ===================== reductions ===========================================
__device__ __forceinline__ float blockReduceMax(float v){
    __shared__ float sh[8];
    int lid = threadIdx.x & 31, wid = threadIdx.x >> 5;
    #pragma unroll
    for (int o = 16; o > 0; o >>= 1) v = fmaxf(v, __shfl_xor_sync(0xffffffffu, v, o));
    if (lid == 0) sh[wid] = v;
    __syncthreads();
    v = sh[lid & 7];
    #pragma unroll
    for (int o = 4; o > 0; o >>= 1) v = fmaxf(v, __shfl_xor_sync(0xffffffffu, v, o));
    __syncthreads();
    return v;
}
__device__ __forceinline__ float blockReduceSum(float v){
    __shared__ float sh[8];
    int lid = threadIdx.x & 31, wid = threadIdx.x >> 5;
    #pragma unroll
    for (int o = 16; o > 0; o >>= 1) v += __shfl_xor_sync(0xffffffffu, v, o);
    if (lid == 0) sh[wid] = v;
    __syncthreads();
    v = sh[lid & 7];
    #pragma unroll
    for (int o = 4; o > 0; o >>= 1) v += __shfl_xor_sync(0xffffffffu, v, o);
    __syncthreads();
    return v;
}

// ===================== small kernels ========================================
__global__ void embed_k(const int* __restrict__ x,
                        const float* __restrict__ wte,
                        const float* __restrict__ wpe){
    int i = blockIdx.x * blockDim.x + threadIdx.x;
    if (i >= Mdim * Cdim) return;
    int c  = i % Cdim;
    int bt = i / Cdim;
    int t  = bt % Tdim;
    g_h[i] = wte[(size_t)x[bt] * Cdim + c] + wpe[(size_t)t * Cdim + c];
}

__global__ void cvt_h_k(const float* __restrict__ in, __half* __restrict__ o, long n){
    long stride = (long)gridDim.x * blockDim.x * 4;
    for (long i = ((long)blockIdx.x * blockDim.x + threadIdx.x) * 4; i < n; i += stride){
        float4 v = *(const float4*)(in + i);
        uint2 w;
        w.x = pack_half2(v.x, v.y);
        w.y = pack_half2(v.z, v.w);
        *(uint2*)(o + i) = w;
    }
}

// warp-per-row layernorm: block 256 = 8 rows, shuffle-only reductions
__global__ void ln_k(const float* __restrict__ in,
                     const float* __restrict__ w,
                     const float* __restrict__ b,
                     __half* __restrict__ ohi,
                     __half* __restrict__ olo){
    int warp = threadIdx.x >> 5, lane = threadIdx.x & 31;
    int row = blockIdx.x * 8 + warp;
    const float* xp = in + (size_t)row * Cdim;
    float4 v[6];
    float s = 0.f, ss = 0.f;
    #pragma unroll
    for (int k = 0; k < 6; k++){
        v[k] = *(const float4*)(xp + lane*4 + k*128);
        s  += v[k].x + v[k].y + v[k].z + v[k].w;
        ss += v[k].x*v[k].x + v[k].y*v[k].y + v[k].z*v[k].z + v[k].w*v[k].w;
    }
    #pragma unroll
    for (int o = 16; o > 0; o >>= 1){
        s  += __shfl_xor_sync(0xffffffffu, s,  o);
        ss += __shfl_xor_sync(0xffffffffu, ss, o);
    }
    float mean = s * (1.f / Cdim);
    float var  = ss * (1.f / Cdim) - mean * mean;
    float rstd = rsqrtf(var + 1e-5f);
    #pragma unroll
    for (int k = 0; k < 6; k++){
        int c = lane*4 + k*128;
        float y0 = (v[k].x - mean) * rstd * w[c]   + b[c];
        float y1 = (v[k].y - mean) * rstd * w[c+1] + b[c+1];
        float y2 = (v[k].z - mean) * rstd * w[c+2] + b[c+2];
        float y3 = (v[k].w - mean) * rstd * w[c+3] + b[c+3];
        float h0 = __half2float(__float2half_rn(y0));
        float h1 = __half2float(__float2half_rn(y1));
        float h2 = __half2float(__float2half_rn(y2));
        float h3 = __half2float(__float2half_rn(y3));
        uint2 hw, lw;
        hw.x = pack_half2(y0, y1);       hw.y = pack_half2(y2, y3);
        lw.x = pack_half2(y0-h0, y1-h1); lw.y = pack_half2(y2-h2, y3-h3);
        *(uint2*)(ohi + (size_t)row*Cdim + c) = hw;
        *(uint2*)(olo + (size_t)row*Cdim + c) = lw;
    }
}

// ===================== fp16 2-term split GEMM (mma.sync) ====================
// C[M,N] = (Ahi+Alo)[M,K] @ B[N,K]^T.  A hi/lo fp16, B single fp16.
// N multiple of 128. Split-K via gridDim.z (mode 2 only).
// modes: 1: relu(acc+bias)->hi/lo | 2: out_f atomicAdd(acc[+bias if z==0]) | 4: (acc+bias)->hi/lo
#define MAT_B   10240            /* 128 rows * 80 bytes */
#define STG_B   (3*MAT_B)
#define GT_SMEM (2*STG_B)        /* 61440 bytes */

__global__ __launch_bounds__(256, 2) void gemm_tc_k(
        const __half* __restrict__ Ahi, const __half* __restrict__ Alo,
        const __half* __restrict__ Bm,
        const float* __restrict__ bias,
        float* __restrict__ out_f,
        __half* __restrict__ out_hi, __half* __restrict__ out_lo,
        int N, int K, int mode){
    extern __shared__ char smem[];
    uint32_t sbase = smem_to_u32(smem);
    int tid = threadIdx.x, wid = tid >> 5, lane = tid & 31;
    int warpRow = wid >> 2, warpCol = wid & 3;

    long row0 = (long)blockIdx.x * 128;
    long n0   = (long)blockIdx.y * 128;
    int kspan = K / (int)gridDim.z;
    long kbase = (long)blockIdx.z * kspan;
    int nIter = kspan >> 5;

    float acc[4][4][4];
    #pragma unroll
    for (int i = 0; i < 4; i++)
        #pragma unroll
        for (int j = 0; j < 4; j++)
            #pragma unroll
            for (int q = 0; q < 4; q++) acc[i][j][q] = 0.f;

    auto issue = [&](int it){
        if (it >= nIter) return;
        long k0 = kbase + ((long)it << 5);
        uint32_t stg = sbase + (uint32_t)(it & 1) * STG_B;
        #pragma unroll
        for (int j = 0; j < 6; j++){
            int c   = tid + j * 256;
            int mat = c >> 9;
            int id  = c & 511;
            int row = id >> 2;
            int c8  = (id & 3) << 3;
            const __half* src;
            if (mat < 2){
                src = (mat == 0 ? Ahi : Alo) + (row0 + row) * (long)K + k0 + c8;
            } else {
                src = Bm + (n0 + row) * (long)K + k0 + c8;
            }
            uint32_t dst = stg + (uint32_t)(mat * MAT_B + row * 80 + c8 * 2);
            cp_async16(dst, src);
        }
        CP_COMMIT();
    };

    issue(0);
    for (int it = 0; it < nIter; it++){
        CP_WAIT0();
        __syncthreads();
        issue(it + 1);

        uint32_t stg = sbase + (uint32_t)(it & 1) * STG_B;
        uint32_t aHi = stg;
        uint32_t aLo = stg + MAT_B;
        uint32_t bS  = stg + 2*MAT_B;
        uint32_t rsel = (uint32_t)(lane & 15) * 80 + (uint32_t)(lane >> 4) * 16;

        #pragma unroll
        for (int ks = 0; ks < 32; ks += 16){
            uint32_t bf[2][4];
            #pragma unroll
            for (int nj = 0; nj < 2; nj++){
                uint32_t off = (uint32_t)((warpCol*32 + nj*16) * 80 + ks*2) + rsel;
                ldsm_x4(bf[nj], bS + off);
            }
            #pragma unroll
            for (int mi = 0; mi < 4; mi++){
                uint32_t ah[4], al[4];
                uint32_t off = (uint32_t)((warpRow*64 + mi*16) * 80 + ks*2) + rsel;
                ldsm_x4(ah, aHi + off);
                ldsm_x4(al, aLo + off);
                #pragma unroll
                for (int ni = 0; ni < 4; ni++){
                    int nj = ni >> 1, w = ni & 1;
                    mma_f16(acc[mi][ni], ah, bf[nj][w], bf[nj][w+2]);
                    mma_f16(acc[mi][ni], al, bf[nj][w], bf[nj][w+2]);
                }
            }
        }
    }
    __syncthreads();

    bool addBias = (blockIdx.z == 0);
    #pragma unroll
    for (int mi = 0; mi < 4; mi++){
        long r0 = row0 + warpRow*64 + mi*16 + (lane >> 2);
        #pragma unroll
        for (int ni = 0; ni < 4; ni++){
            long c0 = n0 + warpCol*32 + ni*8 + (lane & 3)*2;
            float b0 = addBias ? bias[c0]     : 0.f;
            float b1 = addBias ? bias[c0 + 1] : 0.f;
            #pragma unroll
            for (int half = 0; half < 2; half++){
                long r  = r0 + half*8;
                long oi = r * (long)N + c0;
                float v0 = acc[mi][ni][half*2]     + b0;
                float v1 = acc[mi][ni][half*2 + 1] + b1;
                if (mode == 2){
                    atomicAdd(out_f + oi,     v0);
                    atomicAdd(out_f + oi + 1, v1);
                } else {
                    if (mode == 1){
                        v0 = fmaxf(v0, 0.f);
                        v1 = fmaxf(v1, 0.f);
                    }
                    float h0 = __half2float(__float2half_rn(v0));
                    float h1 = __half2float(__float2half_rn(v1));
                    *(uint32_t*)(out_hi + oi) = pack_half2(v0, v1);
                    *(uint32_t*)(out_lo + oi) = pack_half2(v0 - h0, v1 - h1);
                }
            }
        }
    }
}

// ===================== fp16 single-term GEMM + fused LSE partials ===========
#define FH_MAT  10240
#define FH_STG  (2*FH_MAT)
#define FH_SMEM (2*FH_STG)       /* 40960 */

__global__ __launch_bounds__(256, 2) void gemm_f16_k(
        const __half* __restrict__ A, const __half* __restrict__ Bm,
        float* __restrict__ out_f,
        float* __restrict__ pmax, float* __restrict__ psum,
        int N, int K){
    extern __shared__ char smem[];
    uint32_t sbase = smem_to_u32(smem);
    int tid = threadIdx.x, wid = tid >> 5, lane = tid & 31;
    int warpRow = wid >> 2, warpCol = wid & 3;

    long row0 = (long)blockIdx.x * 128;
    long n0   = (long)blockIdx.y * 128;
    int nIter = K >> 5;

    float acc[4][4][4];
    #pragma unroll
    for (int i = 0; i < 4; i++)
        #pragma unroll
        for (int j = 0; j < 4; j++)
            #pragma unroll
            for (int q = 0; q < 4; q++) acc[i][j][q] = 0.f;

    auto issue = [&](int it){
        if (it >= nIter) return;
        int k0 = it << 5;
        uint32_t stg = sbase + (uint32_t)(it & 1) * FH_STG;
        #pragma unroll
        for (int j = 0; j < 4; j++){
            int c   = tid + j * 256;
            int mat = c >> 9;
            int id  = c & 511;
            int row = id >> 2;
            int c8  = (id & 3) << 3;
            const __half* src;
            if (mat == 0){
                src = A + (row0 + row) * (long)K + k0 + c8;
            } else {
                long br = n0 + row; if (br >= N) br = 0;
                src = Bm + br * (long)K + k0 + c8;
            }
            uint32_t dst = stg + (uint32_t)(mat * FH_MAT + row * 80 + c8 * 2);
            cp_async16(dst, src);
        }
        CP_COMMIT();
    };

    issue(0);
    for (int it = 0; it < nIter; it++){
        CP_WAIT0();
        __syncthreads();
        issue(it + 1);

        uint32_t stg = sbase + (uint32_t)(it & 1) * FH_STG;
        uint32_t aS = stg;
        uint32_t bS = stg + FH_MAT;
        uint32_t rsel = (uint32_t)(lane & 15) * 80 + (uint32_t)(lane >> 4) * 16;

        #pragma unroll
        for (int ks = 0; ks < 32; ks += 16){
            uint32_t bf[2][4];
            #pragma unroll
            for (int nj = 0; nj < 2; nj++){
                uint32_t off = (uint32_t)((warpCol*32 + nj*16) * 80 + ks*2) + rsel;
                ldsm_x4(bf[nj], bS + off);
            }
            #pragma unroll
            for (int mi = 0; mi < 4; mi++){
                uint32_t af[4];
                uint32_t off = (uint32_t)((warpRow*64 + mi*16) * 80 + ks*2) + rsel;
                ldsm_x4(af, aS + off);
                #pragma unroll
                for (int ni = 0; ni < 4; ni++){
                    int nj = ni >> 1, w = ni & 1;
                    mma_f16(acc[mi][ni], af, bf[nj][w], bf[nj][w+2]);
                }
            }
        }
    }

    // scalar stores: logits base pointer may be only 4B-aligned (out+1)
    #pragma unroll
    for (int mi = 0; mi < 4; mi++){
        long r0 = row0 + warpRow*64 + mi*16 + (lane >> 2);
        #pragma unroll
        for (int ni = 0; ni < 4; ni++){
            long c0 = n0 + warpCol*32 + ni*8 + (lane & 3)*2;
            #pragma unroll
            for (int half = 0; half < 2; half++){
                long r = r0 + half*8;
                #pragma unroll
                for (int e = 0; e < 2; e++){
                    long n = c0 + e;
                    if (n < N)
                        out_f[r * (long)N + n] = acc[mi][ni][half*2 + e];
                }
            }
        }
    }

    // fused LSE partials for this 128x128 block
    __syncthreads();                       // stage buffers now reusable
    float* pm_s = (float*)smem;            // [128][4]
    float* ps_s = (float*)smem + 512;      // [128][4]
    #pragma unroll
    for (int mi = 0; mi < 4; mi++){
        #pragma unroll
        for (int half = 0; half < 2; half++){
            int lr = warpRow*64 + mi*16 + (lane >> 2) + half*8;
            float vv[8];
            float lm = -1e30f;
            #pragma unroll
            for (int ni = 0; ni < 4; ni++)
                #pragma unroll
                for (int e = 0; e < 2; e++){
                    long n = n0 + warpCol*32 + ni*8 + (lane & 3)*2 + e;
                    float t = (n < N) ? acc[mi][ni][half*2 + e] : -1e30f;
                    vv[ni*2 + e] = t;
                    lm = fmaxf(lm, t);
                }
            lm = fmaxf(lm, __shfl_xor_sync(0xffffffffu, lm, 1));
            lm = fmaxf(lm, __shfl_xor_sync(0xffffffffu, lm, 2));
            float ls = 0.f;
            #pragma unroll
            for (int q = 0; q < 8; q++) ls += __expf(vv[q] - lm);
            ls += __shfl_xor_sync(0xffffffffu, ls, 1);
            ls += __shfl_xor_sync(0xffffffffu, ls, 2);
            if ((lane & 3) == 0){
                pm_s[lr*4 + warpCol] = lm;
                ps_s[lr*4 + warpCol] = ls;
            }
        }
    }
    __syncthreads();
    if (tid < 128){
        float m0 = pm_s[tid*4], m1 = pm_s[tid*4+1], m2 = pm_s[tid*4+2], m3 = pm_s[tid*4+3];
        float M = fmaxf(fmaxf(m0, m1), fmaxf(m2, m3));
        float S = ps_s[tid*4]  *__expf(m0 - M) + ps_s[tid*4+1]*__expf(m1 - M)
                + ps_s[tid*4+2]*__expf(m2 - M) + ps_s[tid*4+3]*__expf(m3 - M);
        long r = row0 + tid;
        pmax[r*NPB + blockIdx.y] = M;
        psum[r*NPB + blockIdx.y] = S;
    }
}

// ===================== flash attention (fp16 mma, 2-term) ===================
#define FA_QB    (128*144)
#define FA_KVMAT (64*144)
#define FA_STGB  (2*FA_KVMAT)
#define FA_SMEM  (2*FA_QB + 2*FA_STGB)   /* 73728 */

__global__ __launch_bounds__(256, 2) void flash_k(
        const __half* __restrict__ qkvh,
        const __half* __restrict__ qkvl){
    extern __shared__ char smem[];
    uint32_t sb = smem_to_u32(smem);
    uint32_t Qh = sb, Ql = sb + FA_QB;
    uint32_t kvb = sb + 2*FA_QB;

    int tid = threadIdx.x, wid = tid >> 5, lane = tid & 31;
    int g = lane >> 2, tq = lane & 3;
    int qb = (int)gridDim.x - 1 - (int)blockIdx.x;
    int bh = blockIdx.y; int bq = bh / Hdim, head = bh % Hdim;
    int q0 = qb * 128;
    long rowbase = (long)bq * Tdim;

    #pragma unroll
    for (int j = 0; j < 8; j++){
        int id = tid + j*256;
        int mat = id >> 10, rem = id & 1023;
        int row = rem >> 3, c8 = (rem & 7) << 3;
        const __half* src = (mat ? qkvl : qkvh)
            + (rowbase + q0 + row)*(long)C3 + head*Ddim + c8;
        cp_async16((mat ? Ql : Qh) + (uint32_t)(row*144 + c8*2), src);
    }

    int nkv = 2*qb + 2;
    auto issue = [&](int j){
        if (j >= nkv) return;
        int s0 = j * 64;
        uint32_t stg = kvb + (uint32_t)(j & 1) * FA_STGB;
        #pragma unroll
        for (int jj = 0; jj < 4; jj++){
            int id = tid + jj*256;
            int mat = id >> 9, rem = id & 511;    // 0:K_hi 1:V_hi
            int row = rem >> 3, c8 = (rem & 7) << 3;
            int coff = mat ? 2*Cdim : Cdim;
            const __half* src = qkvh
                + (rowbase + s0 + row)*(long)C3 + coff + head*Ddim + c8;
            cp_async16(stg + (uint32_t)(mat*FA_KVMAT + row*144 + c8*2), src);
        }
        CP_COMMIT();
    };

    float mrow[2] = {-1e30f, -1e30f};
    float lrow[2] = {0.f, 0.f};
    float oacc[8][4];
    #pragma unroll
    for (int i = 0; i < 8; i++)
        #pragma unroll
        for (int e = 0; e < 4; e++) oacc[i][e] = 0.f;

    int t0w = q0 + wid*16;
    uint32_t rsel16 = (uint32_t)(lane & 15)*144 + (uint32_t)(lane >> 4)*16;
    int vtsel = lane >> 3, vrt = lane & 7;
    uint32_t vrow_off = ((vtsel >> 1) ? 8u : 0u) + (uint32_t)vrt;
    uint32_t vcol_off = (vtsel & 1) ? 16u : 0u;

    issue(0);
    for (int j = 0; j < nkv; j++){
        CP_WAIT0();
        __syncthreads();
        issue(j + 1);

        int s0 = j * 64;
        if (s0 <= t0w + 15){
            uint32_t stg = kvb + (uint32_t)(j & 1) * FA_STGB;
            uint32_t Kh = stg;
            uint32_t Vh = stg + FA_KVMAT;

            float S[8][4];
            #pragma unroll
            for (int i = 0; i < 8; i++)
                #pragma unroll
                for (int e = 0; e < 4; e++) S[i][e] = 0.f;

            #pragma unroll
            for (int dc = 0; dc < 4; dc++){
                uint32_t aoff = (uint32_t)(wid*16)*144 + (uint32_t)dc*32 + rsel16;
                uint32_t ah[4], al[4];
                ldsm_x4(ah, Qh + aoff);
                ldsm_x4(al, Ql + aoff);
                #pragma unroll
                for (int ng = 0; ng < 4; ng++){
                    uint32_t boff = (uint32_t)(ng*16)*144 + (uint32_t)dc*32 + rsel16;
                    uint32_t kh[4];
                    ldsm_x4(kh, Kh + boff);
                    #pragma unroll
                    for (int w = 0; w < 2; w++){
                        mma_f16(S[ng*2+w], ah, kh[w], kh[w+2]);
                        mma_f16(S[ng*2+w], al, kh[w], kh[w+2]);
                    }
                }
            }

            bool needMask = (s0 + 63 > t0w);
            #pragma unroll
            for (int ns = 0; ns < 8; ns++)
                #pragma unroll
                for (int e = 0; e < 4; e++){
                    float v = S[ns][e] * 0.125f;
                    if (needMask){
                        int t = t0w + g + (e >> 1)*8;
                        int s = s0 + ns*8 + tq*2 + (e & 1);
                        if (s > t) v = -1e30f;
                    }
                    S[ns][e] = v;
                }

            #pragma unroll
            for (int r = 0; r < 2; r++){
                float mx = -1e30f;
                #pragma unroll
                for (int ns = 0; ns < 8; ns++)
                    mx = fmaxf(mx, fmaxf(S[ns][r*2], S[ns][r*2+1]));
                mx = fmaxf(mx, __shfl_xor_sync(0xffffffffu, mx, 1));
                mx = fmaxf(mx, __shfl_xor_sync(0xffffffffu, mx, 2));
                float mnew = fmaxf(mrow[r], mx);
                float corr = __expf(mrow[r] - mnew);
                mrow[r] = mnew;
                float lsum = 0.f;
                #pragma unroll
                for (int ns = 0; ns < 8; ns++){
                    float p0 = __expf(S[ns][r*2]   - mnew);
                    float p1 = __expf(S[ns][r*2+1] - mnew);
                    S[ns][r*2] = p0; S[ns][r*2+1] = p1;
                    lsum += p0 + p1;
                }
                lsum += __shfl_xor_sync(0xffffffffu, lsum, 1);
                lsum += __shfl_xor_sync(0xffffffffu, lsum, 2);
                lrow[r] = lrow[r]*corr + lsum;
                #pragma unroll
                for (int dt = 0; dt < 8; dt++){
                    oacc[dt][r*2]   *= corr;
                    oacc[dt][r*2+1] *= corr;
                }
            }

            #pragma unroll
            for (int sc = 0; sc < 4; sc++){
                uint32_t ph[4], pl[4];
                #pragma unroll
                for (int half = 0; half < 2; half++){
                    int ns = sc*2 + half;
                    float v0 = S[ns][0], v1 = S[ns][1], v2 = S[ns][2], v3 = S[ns][3];
                    float h0 = __half2float(__float2half_rn(v0));
                    float h1 = __half2float(__float2half_rn(v1));
                    float h2 = __half2float(__float2half_rn(v2));
                    float h3 = __half2float(__float2half_rn(v3));
                    ph[half*2+0] = pack_half2(v0, v1);
                    ph[half*2+1] = pack_half2(v2, v3);
                    pl[half*2+0] = pack_half2(v0 - h0, v1 - h1);
                    pl[half*2+1] = pack_half2(v2 - h2, v3 - h3);
                }
                uint32_t vbase = (uint32_t)((sc*16 + vrow_off)*144) + vcol_off;
                #pragma unroll
                for (int dg = 0; dg < 4; dg++){
                    uint32_t vh_[4];
                    ldsm_x4_t(vh_, Vh + vbase + (uint32_t)dg*32);
                    #pragma unroll
                    for (int w = 0; w < 2; w++){
                        int dt = dg*2 + w;
                        mma_f16(oacc[dt], ph, vh_[w], vh_[w+2]);
                        mma_f16(oacc[dt], pl, vh_[w], vh_[w+2]);
                    }
                }
            }
        }
    }

    #pragma unroll
    for (int r = 0; r < 2; r++){
        float inv = 1.f / lrow[r];
        long t = (long)t0w + g + r*8;
        float* hp = g_h + (rowbase + t)*(long)Cdim + head*Ddim;
        #pragma unroll
        for (int dt = 0; dt < 8; dt++){
            float2* p = (float2*)(hp + dt*8 + tq*2);
            float2 v = *p;
            v.x += oacc[dt][r*2]   * inv;
            v.y += oacc[dt][r*2+1] * inv;
            *p = v;
        }
    }
}

// ===================== loss from LSE partials ================================
__global__ void loss_row2_k(const float* __restrict__ logits,
                            const int* __restrict__ target){
    int row = blockIdx.x, tid = threadIdx.x;
    const float* pm = g_pmax + (size_t)row * NPB;
    const float* ps = g_psum + (size_t)row * NPB;
    float m = -1e30f, s = 0.f;
    for (int i = tid; i < NPB; i += 256){
        float im = pm[i], is = ps[i];
        if (im > m){
            s = s * __expf(m - im) + is;
            m = im;
        } else {
            s += is * __expf(im - m);
        }
    }
    float mg = blockReduceMax(m);
    s *= __expf(m - mg);
    float tot = blockReduceSum(s);
    if (tid == 0){
        float lse = logf(tot) + mg;
        g_rowloss[row] = lse - logits[(size_t)row * Vdim + target[row]];
    }
}
__global__ void loss_reduce_k(float* out){
    float s = 0.f;
    for (int i = threadIdx.x; i < Mdim; i += 256) s += g_rowloss[i];
    s = blockReduceSum(s);
    if (threadIdx.x == 0) out[0] = s / (float)Mdim;
}

// ===================== launch ===============================================
extern "C" void kernel_launch(void* const* d_in, const int* in_sizes, int n_in,
                              void* d_out, int out_size){
    const int*   x      = (const int*)  d_in[0];
    const int*   target = (const int*)  d_in[1];
    const float* wte    = (const float*)d_in[2];
    const float* wpe    = (const float*)d_in[3];
    const float* ln1_w  = (const float*)d_in[4];
    const float* ln1_b  = (const float*)d_in[5];
    const float* attn_w = (const float*)d_in[6];
    const float* attn_b = (const float*)d_in[7];
    const float* ln2_w  = (const float*)d_in[8];
    const float* ln2_b  = (const float*)d_in[9];
    const float* ff1_w  = (const float*)d_in[10];
    const float* ff1_b  = (const float*)d_in[11];
    const float* ff2_w  = (const float*)d_in[12];
    const float* ff2_b  = (const float*)d_in[13];
    const float* lm_w   = (const float*)d_in[14];

    float* out = (float*)d_out;
    bool has_loss = ((long long)out_size == (long long)Mdim * Vdim + 1);
    float* logits = has_loss ? out + 1 : out;

    cudaFuncSetAttribute(gemm_tc_k,  cudaFuncAttributeMaxDynamicSharedMemorySize, GT_SMEM);
    cudaFuncSetAttribute(gemm_f16_k, cudaFuncAttributeMaxDynamicSharedMemorySize, FH_SMEM);
    cudaFuncSetAttribute(flash_k,    cudaFuncAttributeMaxDynamicSharedMemorySize, FA_SMEM);

    float* ph;
    cudaGetSymbolAddress((void**)&ph, g_h);
    __half *wqk,*wf1,*wf2,*wlm;
    __half *xnh,*xnl,*fhh,*fhl,*qvh,*qvl,*ah_h;
    float *ppm,*pps;
    cudaGetSymbolAddress((void**)&wqk, g_wqkv_h);
    cudaGetSymbolAddress((void**)&wf1, g_wff1_h);
    cudaGetSymbolAddress((void**)&wf2, g_wff2_h);
    cudaGetSymbolAddress((void**)&wlm, g_wlm_h);
    cudaGetSymbolAddress((void**)&xnh, g_xn_hi);   cudaGetSymbolAddress((void**)&xnl, g_xn_lo);
    cudaGetSymbolAddress((void**)&fhh, g_ffh_hi);  cudaGetSymbolAddress((void**)&fhl, g_ffh_lo);
    cudaGetSymbolAddress((void**)&ah_h, g_ah_h);
    cudaGetSymbolAddress((void**)&qvh, g_qkv_hi);  cudaGetSymbolAddress((void**)&qvl, g_qkv_lo);
    cudaGetSymbolAddress((void**)&ppm, g_pmax);    cudaGetSymbolAddress((void**)&pps, g_psum);

    cvt_h_k<<<2048, 256>>>(attn_w, wqk, (long)Ldim*C3*Cdim);
    cvt_h_k<<<2048, 256>>>(ff1_w,  wf1, (long)Ldim*Fdim*Cdim);
    cvt_h_k<<<2048, 256>>>(ff2_w,  wf2, (long)Ldim*Cdim*Fdim);
    cvt_h_k<<<4096, 256>>>(lm_w,   wlm, (long)Vdim*Cdim);

    embed_k<<<(Mdim*Cdim + 255)/256, 256>>>(x, wte, wpe);

    for (int l = 0; l < Ldim; l++){
        ln_k<<<Mdim/8, 256>>>(ph, ln1_w + (size_t)l*Cdim, ln1_b + (size_t)l*Cdim, xnh, xnl);

        gemm_tc_k<<<dim3(Mdim/128, C3/128, 1), 256, GT_SMEM>>>(
            xnh, xnl, wqk + (size_t)l*C3*Cdim,
            attn_b + (size_t)l*C3, nullptr, qvh, qvl, C3, Cdim, 4);

        flash_k<<<dim3(Tdim/128, Bdim*Hdim), 256, FA_SMEM>>>(qvh, qvl);

        ln_k<<<Mdim/8, 256>>>(ph, ln2_w + (size_t)l*Cdim, ln2_b + (size_t)l*Cdim, xnh, xnl);

        gemm_tc_k<<<dim3(Mdim/128, Fdim/128, 1), 256, GT_SMEM>>>(
            xnh, xnl, wf1 + (size_t)l*Fdim*Cdim,
            ff1_b + (size_t)l*Fdim, nullptr, fhh, fhl, Fdim, Cdim, 1);

        gemm_tc_k<<<dim3(Mdim/128, Cdim/128, 2), 256, GT_SMEM>>>(
            fhh, fhl, wf2 + (size_t)l*Cdim*Fdim,
            ff2_b + (size_t)l*Cdim, ph, nullptr, nullptr, Cdim, Fdim, 2);
    }

    cvt_h_k<<<2048, 256>>>(ph, ah_h, (long)Mdim*Cdim);

    gemm_f16_k<<<dim3(Mdim/128, NPB), 256, FH_SMEM>>>(
        ah_h, wlm, logits, ppm, pps, Vdim, Cdim);

    loss_row2_k<<<Mdim, 256>>>(logits, target);
    if (has_loss)
        loss_reduce_k<<<1, 256>>>(out);
}

// round 12
// speedup vs baseline: 1.5331x; 1.3678x over previous
#include <cuda_runtime.h>
#include <cuda_bf16.h>
#include <cuda_fp16.h>
#include <cstdint>
#include <math.h>

#define Bdim 2
#define Tdim 2048
#define Cdim 768
#define Hdim 12
#define Ddim 64
#define Ldim 6
#define Vdim 50257
#define Mdim (Bdim*Tdim)      /* 4096 */
#define C3   (3*Cdim)         /* 2304 */
#define Fdim (4*Cdim)         /* 3072 */
#define NPB  393              /* (Vdim+127)/128 logits col-blocks */

// ===================== device scratch (no allocations) ======================
__device__ float g_h  [Mdim*Cdim];
__device__ float g_rowloss[Mdim];
__device__ float g_pmax[(size_t)Mdim*NPB];
__device__ float g_psum[(size_t)Mdim*NPB];

__device__ __half g_wqkv_h[Ldim*C3*Cdim];
__device__ __half g_wff1_h[Ldim*Fdim*Cdim];
__device__ __half g_wff2_h[Ldim*Cdim*Fdim];
__device__ __half g_wlm_h[(size_t)Vdim*Cdim];
__device__ __half g_xn [Mdim*Cdim];
__device__ __half g_ffh[Mdim*Fdim];
__device__ __half g_ah [Mdim*Cdim];
__device__ __half g_qkv[Mdim*C3];

// ===================== asm helpers (baseline sm_80+ ISA) ====================
__device__ __forceinline__ uint32_t smem_to_u32(const void* p) {
    uint32_t a;
    asm("{ .reg .u64 t; cvta.to.shared.u64 t, %1; cvt.u32.u64 %0, t; }" : "=r"(a) : "l"(p));
    return a;
}
__device__ __forceinline__ void cp_async16(uint32_t dst, const void* src){
    asm volatile("cp.async.cg.shared.global [%0], [%1], 16;" :: "r"(dst), "l"(src));
}
#define CP_COMMIT() asm volatile("cp.async.commit_group;" ::: "memory")
#define CP_WAIT0()  asm volatile("cp.async.wait_group 0;" ::: "memory")

__device__ __forceinline__ void ldsm_x4(uint32_t* r, uint32_t addr){
    asm volatile("ldmatrix.sync.aligned.m8n8.x4.shared.b16 {%0,%1,%2,%3}, [%4];"
        : "=r"(r[0]), "=r"(r[1]), "=r"(r[2]), "=r"(r[3]) : "r"(addr));
}
__device__ __forceinline__ void ldsm_x4_t(uint32_t* r, uint32_t addr){
    asm volatile("ldmatrix.sync.aligned.m8n8.x4.trans.shared.b16 {%0,%1,%2,%3}, [%4];"
        : "=r"(r[0]), "=r"(r[1]), "=r"(r[2]), "=r"(r[3]) : "r"(addr));
}
__device__ __forceinline__ void mma_f16(float* d, const uint32_t* a,
                                        uint32_t b0, uint32_t b1){
    asm volatile("mma.sync.aligned.m16n8k16.row.col.f32.f16.f16.f32 "
        "{%0,%1,%2,%3}, {%4,%5,%6,%7}, {%8,%9}, {%0,%1,%2,%3};"
        : "+f"(d[0]), "+f"(d[1]), "+f"(d[2]), "+f"(d[3])
        : "r"(a[0]), "r"(a[1]), "r"(a[2]), "r"(a[3]), "r"(b0), "r"(b1));
}
__device__ __forceinline__ uint32_t pack_half2(float lo, float hi){
    uint32_t r;
    asm("cvt.rn.f16x2.f32 %0, %1, %2;" : "=r"(r) : "f"(hi), "f"(lo));
    return r;
}

// ===================== reductions ===========================================
__device__ __forceinline__ float blockReduceMax(float v){
    __shared__ float sh[8];
    int lid = threadIdx.x & 31, wid = threadIdx.x >> 5;
    #pragma unroll
    for (int o = 16; o > 0; o >>= 1) v = fmaxf(v, __shfl_xor_sync(0xffffffffu, v, o));
    if (lid == 0) sh[wid] = v;
    __syncthreads();
    v = sh[lid & 7];
    #pragma unroll
    for (int o = 4; o > 0; o >>= 1) v = fmaxf(v, __shfl_xor_sync(0xffffffffu, v, o));
    __syncthreads();
    return v;
}
__device__ __forceinline__ float blockReduceSum(float v){
    __shared__ float sh[8];
    int lid = threadIdx.x & 31, wid = threadIdx.x >> 5;
    #pragma unroll
    for (int o = 16; o > 0; o >>= 1) v += __shfl_xor_sync(0xffffffffu, v, o);
    if (lid == 0) sh[wid] = v;
    __syncthreads();
    v = sh[lid & 7];
    #pragma unroll
    for (int o = 4; o > 0; o >>= 1) v += __shfl_xor_sync(0xffffffffu, v, o);
    __syncthreads();
    return v;
}

// ===================== small kernels ========================================
__global__ void embed_k(const int* __restrict__ x,
                        const float* __restrict__ wte,
                        const float* __restrict__ wpe){
    int i = blockIdx.x * blockDim.x + threadIdx.x;
    if (i >= Mdim * Cdim) return;
    int c  = i % Cdim;
    int bt = i / Cdim;
    int t  = bt % Tdim;
    g_h[i] = wte[(size_t)x[bt] * Cdim + c] + wpe[(size_t)t * Cdim + c];
}

__global__ void cvt_h_k(const float* __restrict__ in, __half* __restrict__ o, long n){
    long stride = (long)gridDim.x * blockDim.x * 4;
    for (long i = ((long)blockIdx.x * blockDim.x + threadIdx.x) * 4; i < n; i += stride){
        float4 v = *(const float4*)(in + i);
        uint2 w;
        w.x = pack_half2(v.x, v.y);
        w.y = pack_half2(v.z, v.w);
        *(uint2*)(o + i) = w;
    }
}

// warp-per-row layernorm -> single fp16 output
__global__ void ln_k(const float* __restrict__ in,
                     const float* __restrict__ w,
                     const float* __restrict__ b,
                     __half* __restrict__ oh){
    int warp = threadIdx.x >> 5, lane = threadIdx.x & 31;
    int row = blockIdx.x * 8 + warp;
    const float* xp = in + (size_t)row * Cdim;
    float4 v[6];
    float s = 0.f, ss = 0.f;
    #pragma unroll
    for (int k = 0; k < 6; k++){
        v[k] = *(const float4*)(xp + lane*4 + k*128);
        s  += v[k].x + v[k].y + v[k].z + v[k].w;
        ss += v[k].x*v[k].x + v[k].y*v[k].y + v[k].z*v[k].z + v[k].w*v[k].w;
    }
    #pragma unroll
    for (int o = 16; o > 0; o >>= 1){
        s  += __shfl_xor_sync(0xffffffffu, s,  o);
        ss += __shfl_xor_sync(0xffffffffu, ss, o);
    }
    float mean = s * (1.f / Cdim);
    float var  = ss * (1.f / Cdim) - mean * mean;
    float rstd = rsqrtf(var + 1e-5f);
    #pragma unroll
    for (int k = 0; k < 6; k++){
        int c = lane*4 + k*128;
        float y0 = (v[k].x - mean) * rstd * w[c]   + b[c];
        float y1 = (v[k].y - mean) * rstd * w[c+1] + b[c+1];
        float y2 = (v[k].z - mean) * rstd * w[c+2] + b[c+2];
        float y3 = (v[k].w - mean) * rstd * w[c+3] + b[c+3];
        uint2 hw;
        hw.x = pack_half2(y0, y1);
        hw.y = pack_half2(y2, y3);
        *(uint2*)(oh + (size_t)row*Cdim + c) = hw;
    }
}

// ===================== unified fp16 1-term GEMM (mma.sync) ==================
// C[M,N] = A[M,K] @ B[N,K]^T. Split-K via gridDim.z (mode 2 only).
// modes: 0: out_f = acc (bounds-checked) + LSE partials (lm_head)
//        1: out_h = relu(acc+bias) fp16
//        2: atomicAdd(out_f, acc [+bias if z==0])
//        3: out_h = acc+bias fp16
#define G1_MAT  10240            /* 128 rows * 80 bytes */
#define G1_STG  (2*G1_MAT)
#define G1_SMEM (2*G1_STG)       /* 40960 */

__global__ __launch_bounds__(256, 2) void gemm_1t_k(
        const __half* __restrict__ A, const __half* __restrict__ Bm,
        const float* __restrict__ bias,
        float* __restrict__ out_f, __half* __restrict__ out_h,
        float* __restrict__ pmax, float* __restrict__ psum,
        int N, int K, int mode){
    extern __shared__ char smem[];
    uint32_t sbase = smem_to_u32(smem);
    int tid = threadIdx.x, wid = tid >> 5, lane = tid & 31;
    int warpRow = wid >> 2, warpCol = wid & 3;

    long row0 = (long)blockIdx.x * 128;
    long n0   = (long)blockIdx.y * 128;
    int kspan = K / (int)gridDim.z;
    long kbase = (long)blockIdx.z * kspan;
    int nIter = kspan >> 5;

    float acc[4][4][4];
    #pragma unroll
    for (int i = 0; i < 4; i++)
        #pragma unroll
        for (int j = 0; j < 4; j++)
            #pragma unroll
            for (int q = 0; q < 4; q++) acc[i][j][q] = 0.f;

    auto issue = [&](int it){
        if (it >= nIter) return;
        long k0 = kbase + ((long)it << 5);
        uint32_t stg = sbase + (uint32_t)(it & 1) * G1_STG;
        #pragma unroll
        for (int j = 0; j < 4; j++){
            int c   = tid + j * 256;          // 0..1023
            int mat = c >> 9;                  // 0:A 1:B
            int id  = c & 511;
            int row = id >> 2;
            int c8  = (id & 3) << 3;
            const __half* src;
            if (mat == 0){
                src = A + (row0 + row) * (long)K + k0 + c8;
            } else {
                long br = n0 + row; if (br >= N) br = 0;
                src = Bm + br * (long)K + k0 + c8;
            }
            uint32_t dst = stg + (uint32_t)(mat * G1_MAT + row * 80 + c8 * 2);
            cp_async16(dst, src);
        }
        CP_COMMIT();
    };

    issue(0);
    for (int it = 0; it < nIter; it++){
        CP_WAIT0();
        __syncthreads();        // data(it) visible + all warps done with compute(it-1)
        issue(it + 1);

        uint32_t stg = sbase + (uint32_t)(it & 1) * G1_STG;
        uint32_t aS = stg;
        uint32_t bS = stg + G1_MAT;
        uint32_t rsel = (uint32_t)(lane & 15) * 80 + (uint32_t)(lane >> 4) * 16;

        #pragma unroll
        for (int ks = 0; ks < 32; ks += 16){
            uint32_t bf[2][4];
            #pragma unroll
            for (int nj = 0; nj < 2; nj++){
                uint32_t off = (uint32_t)((warpCol*32 + nj*16) * 80 + ks*2) + rsel;
                ldsm_x4(bf[nj], bS + off);
            }
            #pragma unroll
            for (int mi = 0; mi < 4; mi++){
                uint32_t af[4];
                uint32_t off = (uint32_t)((warpRow*64 + mi*16) * 80 + ks*2) + rsel;
                ldsm_x4(af, aS + off);
                #pragma unroll
                for (int ni = 0; ni < 4; ni++){
                    int nj = ni >> 1, w = ni & 1;
                    mma_f16(acc[mi][ni], af, bf[nj][w], bf[nj][w+2]);
                }
            }
        }
    }

    if (mode == 0){
        // scalar stores: logits base pointer may be only 4B-aligned (out+1)
        #pragma unroll
        for (int mi = 0; mi < 4; mi++){
            long r0 = row0 + warpRow*64 + mi*16 + (lane >> 2);
            #pragma unroll
            for (int ni = 0; ni < 4; ni++){
                long c0 = n0 + warpCol*32 + ni*8 + (lane & 3)*2;
                #pragma unroll
                for (int half = 0; half < 2; half++){
                    long r = r0 + half*8;
                    #pragma unroll
                    for (int e = 0; e < 2; e++){
                        long n = c0 + e;
                        if (n < N)
                            out_f[r * (long)N + n] = acc[mi][ni][half*2 + e];
                    }
                }
            }
        }
        // fused LSE partials for this 128x128 block
        __syncthreads();
        float* pm_s = (float*)smem;            // [128][4]
        float* ps_s = (float*)smem + 512;      // [128][4]
        #pragma unroll
        for (int mi = 0; mi < 4; mi++){
            #pragma unroll
            for (int half = 0; half < 2; half++){
                int lr = warpRow*64 + mi*16 + (lane >> 2) + half*8;
                float vv[8];
                float lm = -1e30f;
                #pragma unroll
                for (int ni = 0; ni < 4; ni++)
                    #pragma unroll
                    for (int e = 0; e < 2; e++){
                        long n = n0 + warpCol*32 + ni*8 + (lane & 3)*2 + e;
                        float t = (n < N) ? acc[mi][ni][half*2 + e] : -1e30f;
                        vv[ni*2 + e] = t;
                        lm = fmaxf(lm, t);
                    }
                lm = fmaxf(lm, __shfl_xor_sync(0xffffffffu, lm, 1));
                lm = fmaxf(lm, __shfl_xor_sync(0xffffffffu, lm, 2));
                float ls = 0.f;
                #pragma unroll
                for (int q = 0; q < 8; q++) ls += __expf(vv[q] - lm);
                ls += __shfl_xor_sync(0xffffffffu, ls, 1);
                ls += __shfl_xor_sync(0xffffffffu, ls, 2);
                if ((lane & 3) == 0){
                    pm_s[lr*4 + warpCol] = lm;
                    ps_s[lr*4 + warpCol] = ls;
                }
            }
        }
        __syncthreads();
        if (tid < 128){
            float m0 = pm_s[tid*4], m1 = pm_s[tid*4+1], m2 = pm_s[tid*4+2], m3 = pm_s[tid*4+3];
            float M = fmaxf(fmaxf(m0, m1), fmaxf(m2, m3));
            float S = ps_s[tid*4]  *__expf(m0 - M) + ps_s[tid*4+1]*__expf(m1 - M)
                    + ps_s[tid*4+2]*__expf(m2 - M) + ps_s[tid*4+3]*__expf(m3 - M);
            long r = row0 + tid;
            pmax[r*NPB + blockIdx.y] = M;
            psum[r*NPB + blockIdx.y] = S;
        }
        return;
    }

    bool addBias = (blockIdx.z == 0);
    #pragma unroll
    for (int mi = 0; mi < 4; mi++){
        long r0 = row0 + warpRow*64 + mi*16 + (lane >> 2);
        #pragma unroll
        for (int ni = 0; ni < 4; ni++){
            long c0 = n0 + warpCol*32 + ni*8 + (lane & 3)*2;
            float b0 = addBias ? bias[c0]     : 0.f;
            float b1 = addBias ? bias[c0 + 1] : 0.f;
            #pragma unroll
            for (int half = 0; half < 2; half++){
                long r  = r0 + half*8;
                long oi = r * (long)N + c0;
                float v0 = acc[mi][ni][half*2]     + b0;
                float v1 = acc[mi][ni][half*2 + 1] + b1;
                if (mode == 2){
                    atomicAdd(out_f + oi,     v0);
                    atomicAdd(out_f + oi + 1, v1);
                } else {
                    if (mode == 1){
                        v0 = fmaxf(v0, 0.f);
                        v1 = fmaxf(v1, 0.f);
                    }
                    *(uint32_t*)(out_h + oi) = pack_half2(v0, v1);
                }
            }
        }
    }
}

// ===================== flash attention (fp16 mma, 1-term) ===================
#define FA_QB    (128*144)
#define FA_KVMAT (64*144)
#define FA_STGB  (2*FA_KVMAT)
#define FA_SMEM  (FA_QB + 2*FA_STGB)     /* 55296 */

__global__ __launch_bounds__(256, 2) void flash_k(const __half* __restrict__ qkv){
    extern __shared__ char smem[];
    uint32_t sb = smem_to_u32(smem);
    uint32_t Qs = sb;
    uint32_t kvb = sb + FA_QB;

    int tid = threadIdx.x, wid = tid >> 5, lane = tid & 31;
    int g = lane >> 2, tq = lane & 3;
    int qb = (int)gridDim.x - 1 - (int)blockIdx.x;
    int bh = blockIdx.y; int bq = bh / Hdim, head = bh % Hdim;
    int q0 = qb * 128;
    long rowbase = (long)bq * Tdim;

    #pragma unroll
    for (int j = 0; j < 4; j++){
        int id = tid + j*256;                 // 0..1023
        int row = id >> 3, c8 = (id & 7) << 3;
        const __half* src = qkv + (rowbase + q0 + row)*(long)C3 + head*Ddim + c8;
        cp_async16(Qs + (uint32_t)(row*144 + c8*2), src);
    }

    int nkv = 2*qb + 2;
    auto issue = [&](int j){
        if (j >= nkv) return;
        int s0 = j * 64;
        uint32_t stg = kvb + (uint32_t)(j & 1) * FA_STGB;
        #pragma unroll
        for (int jj = 0; jj < 4; jj++){
            int id = tid + jj*256;            // 0..1023
            int mat = id >> 9, rem = id & 511;  // 0:K 1:V
            int row = rem >> 3, c8 = (rem & 7) << 3;
            int coff = mat ? 2*Cdim : Cdim;
            const __half* src = qkv
                + (rowbase + s0 + row)*(long)C3 + coff + head*Ddim + c8;
            cp_async16(stg + (uint32_t)(mat*FA_KVMAT + row*144 + c8*2), src);
        }
        CP_COMMIT();
    };

    float mrow[2] = {-1e30f, -1e30f};
    float lrow[2] = {0.f, 0.f};
    float oacc[8][4];
    #pragma unroll
    for (int i = 0; i < 8; i++)
        #pragma unroll
        for (int e = 0; e < 4; e++) oacc[i][e] = 0.f;

    int t0w = q0 + wid*16;
    uint32_t rsel16 = (uint32_t)(lane & 15)*144 + (uint32_t)(lane >> 4)*16;
    int vtsel = lane >> 3, vrt = lane & 7;
    uint32_t vrow_off = ((vtsel >> 1) ? 8u : 0u) + (uint32_t)vrt;
    uint32_t vcol_off = (vtsel & 1) ? 16u : 0u;

    issue(0);
    for (int j = 0; j < nkv; j++){
        CP_WAIT0();
        __syncthreads();
        issue(j + 1);

        int s0 = j * 64;
        if (s0 <= t0w + 15){
            uint32_t stg = kvb + (uint32_t)(j & 1) * FA_STGB;
            uint32_t Kh = stg;
            uint32_t Vh = stg + FA_KVMAT;

            float S[8][4];
            #pragma unroll
            for (int i = 0; i < 8; i++)
                #pragma unroll
                for (int e = 0; e < 4; e++) S[i][e] = 0.f;

            #pragma unroll
            for (int dc = 0; dc < 4; dc++){
                uint32_t aoff = (uint32_t)(wid*16)*144 + (uint32_t)dc*32 + rsel16;
                uint32_t ah[4];
                ldsm_x4(ah, Qs + aoff);
                #pragma unroll
                for (int ng = 0; ng < 4; ng++){
                    uint32_t boff = (uint32_t)(ng*16)*144 + (uint32_t)dc*32 + rsel16;
                    uint32_t kh[4];
                    ldsm_x4(kh, Kh + boff);
                    #pragma unroll
                    for (int w = 0; w < 2; w++)
                        mma_f16(S[ng*2+w], ah, kh[w], kh[w+2]);
                }
            }

            bool needMask = (s0 + 63 > t0w);
            #pragma unroll
            for (int ns = 0; ns < 8; ns++)
                #pragma unroll
                for (int e = 0; e < 4; e++){
                    float v = S[ns][e] * 0.125f;
                    if (needMask){
                        int t = t0w + g + (e >> 1)*8;
                        int s = s0 + ns*8 + tq*2 + (e & 1);
                        if (s > t) v = -1e30f;
                    }
                    S[ns][e] = v;
                }

            #pragma unroll
            for (int r = 0; r < 2; r++){
                float mx = -1e30f;
                #pragma unroll
                for (int ns = 0; ns < 8; ns++)
                    mx = fmaxf(mx, fmaxf(S[ns][r*2], S[ns][r*2+1]));
                mx = fmaxf(mx, __shfl_xor_sync(0xffffffffu, mx, 1));
                mx = fmaxf(mx, __shfl_xor_sync(0xffffffffu, mx, 2));
                float mnew = fmaxf(mrow[r], mx);
                float corr = __expf(mrow[r] - mnew);
                mrow[r] = mnew;
                float lsum = 0.f;
                #pragma unroll
                for (int ns = 0; ns < 8; ns++){
                    float p0 = __expf(S[ns][r*2]   - mnew);
                    float p1 = __expf(S[ns][r*2+1] - mnew);
                    S[ns][r*2] = p0; S[ns][r*2+1] = p1;
                    lsum += p0 + p1;
                }
                lsum += __shfl_xor_sync(0xffffffffu, lsum, 1);
                lsum += __shfl_xor_sync(0xffffffffu, lsum, 2);
                lrow[r] = lrow[r]*corr + lsum;
                #pragma unroll
                for (int dt = 0; dt < 8; dt++){
                    oacc[dt][r*2]   *= corr;
                    oacc[dt][r*2+1] *= corr;
                }
            }

            #pragma unroll
            for (int sc = 0; sc < 4; sc++){
                uint32_t ph[4];
                #pragma unroll
                for (int half = 0; half < 2; half++){
                    int ns = sc*2 + half;
                    ph[half*2+0] = pack_half2(S[ns][0], S[ns][1]);
                    ph[half*2+1] = pack_half2(S[ns][2], S[ns][3]);
                }
                uint32_t vbase = (uint32_t)((sc*16 + vrow_off)*144) + vcol_off;
                #pragma unroll
                for (int dg = 0; dg < 4; dg++){
                    uint32_t vh_[4];
                    ldsm_x4_t(vh_, Vh + vbase + (uint32_t)dg*32);
                    #pragma unroll
                    for (int w = 0; w < 2; w++)
                        mma_f16(oacc[dg*2 + w], ph, vh_[w], vh_[w+2]);
                }
            }
        }
    }

    #pragma unroll
    for (int r = 0; r < 2; r++){
        float inv = 1.f / lrow[r];
        long t = (long)t0w + g + r*8;
        float* hp = g_h + (rowbase + t)*(long)Cdim + head*Ddim;
        #pragma unroll
        for (int dt = 0; dt < 8; dt++){
            float2* p = (float2*)(hp + dt*8 + tq*2);
            float2 v = *p;
            v.x += oacc[dt][r*2]   * inv;
            v.y += oacc[dt][r*2+1] * inv;
            *p = v;
        }
    }
}

// ===================== loss from LSE partials ================================
__global__ void loss_row2_k(const float* __restrict__ logits,
                            const int* __restrict__ target){
    int row = blockIdx.x, tid = threadIdx.x;
    const float* pm = g_pmax + (size_t)row * NPB;
    const float* ps = g_psum + (size_t)row * NPB;
    float m = -1e30f, s = 0.f;
    for (int i = tid; i < NPB; i += 256){
        float im = pm[i], is = ps[i];
        if (im > m){
            s = s * __expf(m - im) + is;
            m = im;
        } else {
            s += is * __expf(im - m);
        }
    }
    float mg = blockReduceMax(m);
    s *= __expf(m - mg);
    float tot = blockReduceSum(s);
    if (tid == 0){
        float lse = logf(tot) + mg;
        g_rowloss[row] = lse - logits[(size_t)row * Vdim + target[row]];
    }
}
__global__ void loss_reduce_k(float* out){
    float s = 0.f;
    for (int i = threadIdx.x; i < Mdim; i += 256) s += g_rowloss[i];
    s = blockReduceSum(s);
    if (threadIdx.x == 0) out[0] = s / (float)Mdim;
}

// ===================== launch ===============================================
extern "C" void kernel_launch(void* const* d_in, const int* in_sizes, int n_in,
                              void* d_out, int out_size){
    const int*   x      = (const int*)  d_in[0];
    const int*   target = (const int*)  d_in[1];
    const float* wte    = (const float*)d_in[2];
    const float* wpe    = (const float*)d_in[3];
    const float* ln1_w  = (const float*)d_in[4];
    const float* ln1_b  = (const float*)d_in[5];
    const float* attn_w = (const float*)d_in[6];
    const float* attn_b = (const float*)d_in[7];
    const float* ln2_w  = (const float*)d_in[8];
    const float* ln2_b  = (const float*)d_in[9];
    const float* ff1_w  = (const float*)d_in[10];
    const float* ff1_b  = (const float*)d_in[11];
    const float* ff2_w  = (const float*)d_in[12];
    const float* ff2_b  = (const float*)d_in[13];
    const float* lm_w   = (const float*)d_in[14];

    float* out = (float*)d_out;
    bool has_loss = ((long long)out_size == (long long)Mdim * Vdim + 1);
    float* logits = has_loss ? out + 1 : out;

    cudaFuncSetAttribute(gemm_1t_k, cudaFuncAttributeMaxDynamicSharedMemorySize, G1_SMEM);
    cudaFuncSetAttribute(flash_k,   cudaFuncAttributeMaxDynamicSharedMemorySize, FA_SMEM);

    float* ph;
    cudaGetSymbolAddress((void**)&ph, g_h);
    __half *wqk,*wf1,*wf2,*wlm,*xn,*ffh,*ah,*qv;
    float *ppm,*pps;
    cudaGetSymbolAddress((void**)&wqk, g_wqkv_h);
    cudaGetSymbolAddress((void**)&wf1, g_wff1_h);
    cudaGetSymbolAddress((void**)&wf2, g_wff2_h);
    cudaGetSymbolAddress((void**)&wlm, g_wlm_h);
    cudaGetSymbolAddress((void**)&xn,  g_xn);
    cudaGetSymbolAddress((void**)&ffh, g_ffh);
    cudaGetSymbolAddress((void**)&ah,  g_ah);
    cudaGetSymbolAddress((void**)&qv,  g_qkv);
    cudaGetSymbolAddress((void**)&ppm, g_pmax);
    cudaGetSymbolAddress((void**)&pps, g_psum);

    cvt_h_k<<<2048, 256>>>(attn_w, wqk, (long)Ldim*C3*Cdim);
    cvt_h_k<<<2048, 256>>>(ff1_w,  wf1, (long)Ldim*Fdim*Cdim);
    cvt_h_k<<<2048, 256>>>(ff2_w,  wf2, (long)Ldim*Cdim*Fdim);
    cvt_h_k<<<4096, 256>>>(lm_w,   wlm, (long)Vdim*Cdim);

    embed_k<<<(Mdim*Cdim + 255)/256, 256>>>(x, wte, wpe);

    for (int l = 0; l < Ldim; l++){
        ln_k<<<Mdim/8, 256>>>(ph, ln1_w + (size_t)l*Cdim, ln1_b + (size_t)l*Cdim, xn);

        gemm_1t_k<<<dim3(Mdim/128, C3/128, 1), 256, G1_SMEM>>>(
            xn, wqk + (size_t)l*C3*Cdim, attn_b + (size_t)l*C3,
            nullptr, qv, nullptr, nullptr, C3, Cdim, 3);

        flash_k<<<dim3(Tdim/128, Bdim*Hdim), 256, FA_SMEM>>>(qv);

        ln_k<<<Mdim/8, 256>>>(ph, ln2_w + (size_t)l*Cdim, ln2_b + (size_t)l*Cdim, xn);

        gemm_1t_k<<<dim3(Mdim/128, Fdim/128, 1), 256, G1_SMEM>>>(
            xn, wf1 + (size_t)l*Fdim*Cdim, ff1_b + (size_t)l*Fdim,
            nullptr, ffh, nullptr, nullptr, Fdim, Cdim, 1);

        gemm_1t_k<<<dim3(Mdim/128, Cdim/128, 2), 256, G1_SMEM>>>(
            ffh, wf2 + (size_t)l*Cdim*Fdim, ff2_b + (size_t)l*Cdim,
            ph, nullptr, nullptr, nullptr, Cdim, Fdim, 2);
    }

    cvt_h_k<<<2048, 256>>>(ph, ah, (long)Mdim*Cdim);

    gemm_1t_k<<<dim3(Mdim/128, NPB, 1), 256, G1_SMEM>>>(
        ah, wlm, nullptr, logits, nullptr, ppm, pps, Vdim, Cdim, 0);

    loss_row2_k<<<Mdim, 256>>>(logits, target);
    if (has_loss)
        loss_reduce_k<<<1, 256>>>(out);
}

// round 13
// speedup vs baseline: 1.7123x; 1.1169x over previous
#include <cuda_runtime.h>
#include <cuda_bf16.h>
#include <cuda_fp16.h>
#include <cstdint>
#include <math.h>

#define Bdim 2
#define Tdim 2048
#define Cdim 768
#define Hdim 12
#define Ddim 64
#define Ldim 6
#define Vdim 50257
#define Mdim (Bdim*Tdim)      /* 4096 */
#define C3   (3*Cdim)         /* 2304 */
#define Fdim (4*Cdim)         /* 3072 */
#define NPB  393              /* (Vdim+127)/128 logits col-blocks */

// ===================== device scratch (no allocations) ======================
__device__ float g_h  [Mdim*Cdim];
__device__ float g_rowloss[Mdim];
__device__ float g_pmax[(size_t)Mdim*NPB];
__device__ float g_psum[(size_t)Mdim*NPB];

__device__ __half g_wqkv_h[Ldim*C3*Cdim];
__device__ __half g_wff1_h[Ldim*Fdim*Cdim];
__device__ __half g_wff2_h[Ldim*Cdim*Fdim];
__device__ __half g_wlm_h[(size_t)Vdim*Cdim];
__device__ __half g_xn [Mdim*Cdim];
__device__ __half g_ffh[Mdim*Fdim];
__device__ __half g_ah [Mdim*Cdim];
__device__ __half g_qkv[Mdim*C3];

// ===================== asm helpers (baseline sm_80+ ISA) ====================
__device__ __forceinline__ uint32_t smem_to_u32(const void* p) {
    uint32_t a;
    asm("{ .reg .u64 t; cvta.to.shared.u64 t, %1; cvt.u32.u64 %0, t; }" : "=r"(a) : "l"(p));
    return a;
}
__device__ __forceinline__ void cp_async16(uint32_t dst, const void* src){
    asm volatile("cp.async.cg.shared.global [%0], [%1], 16;" :: "r"(dst), "l"(src));
}
#define CP_COMMIT() asm volatile("cp.async.commit_group;" ::: "memory")
#define CP_WAIT0()  asm volatile("cp.async.wait_group 0;" ::: "memory")

__device__ __forceinline__ void ldsm_x4(uint32_t* r, uint32_t addr){
    asm volatile("ldmatrix.sync.aligned.m8n8.x4.shared.b16 {%0,%1,%2,%3}, [%4];"
        : "=r"(r[0]), "=r"(r[1]), "=r"(r[2]), "=r"(r[3]) : "r"(addr));
}
__device__ __forceinline__ void ldsm_x4_t(uint32_t* r, uint32_t addr){
    asm volatile("ldmatrix.sync.aligned.m8n8.x4.trans.shared.b16 {%0,%1,%2,%3}, [%4];"
        : "=r"(r[0]), "=r"(r[1]), "=r"(r[2]), "=r"(r[3]) : "r"(addr));
}
__device__ __forceinline__ void mma_f16(float* d, const uint32_t* a,
                                        uint32_t b0, uint32_t b1){
    asm volatile("mma.sync.aligned.m16n8k16.row.col.f32.f16.f16.f32 "
        "{%0,%1,%2,%3}, {%4,%5,%6,%7}, {%8,%9}, {%0,%1,%2,%3};"
        : "+f"(d[0]), "+f"(d[1]), "+f"(d[2]), "+f"(d[3])
        : "r"(a[0]), "r"(a[1]), "r"(a[2]), "r"(a[3]), "r"(b0), "r"(b1));
}
__device__ __forceinline__ uint32_t pack_half2(float lo, float hi){
    uint32_t r;
    asm("cvt.rn.f16x2.f32 %0, %1, %2;" : "=r"(r) : "f"(hi), "f"(lo));
    return r;
}

// ===================== reductions ===========================================
__device__ __forceinline__ float blockReduceMax(float v){
    __shared__ float sh[8];
    int lid = threadIdx.x & 31, wid = threadIdx.x >> 5;
    #pragma unroll
    for (int o = 16; o > 0; o >>= 1) v = fmaxf(v, __shfl_xor_sync(0xffffffffu, v, o));
    if (lid == 0) sh[wid] = v;
    __syncthreads();
    v = sh[lid & 7];
    #pragma unroll
    for (int o = 4; o > 0; o >>= 1) v = fmaxf(v, __shfl_xor_sync(0xffffffffu, v, o));
    __syncthreads();
    return v;
}
__device__ __forceinline__ float blockReduceSum(float v){
    __shared__ float sh[8];
    int lid = threadIdx.x & 31, wid = threadIdx.x >> 5;
    #pragma unroll
    for (int o = 16; o > 0; o >>= 1) v += __shfl_xor_sync(0xffffffffu, v, o);
    if (lid == 0) sh[wid] = v;
    __syncthreads();
    v = sh[lid & 7];
    #pragma unroll
    for (int o = 4; o > 0; o >>= 1) v += __shfl_xor_sync(0xffffffffu, v, o);
    __syncthreads();
    return v;
}

// ===================== small kernels ========================================
__global__ void embed_k(const int* __restrict__ x,
                        const float* __restrict__ wte,
                        const float* __restrict__ wpe){
    int i = blockIdx.x * blockDim.x + threadIdx.x;
    if (i >= Mdim * Cdim) return;
    int c  = i % Cdim;
    int bt = i / Cdim;
    int t  = bt % Tdim;
    g_h[i] = wte[(size_t)x[bt] * Cdim + c] + wpe[(size_t)t * Cdim + c];
}

__global__ void cvt_h_k(const float* __restrict__ in, __half* __restrict__ o, long n){
    long stride = (long)gridDim.x * blockDim.x * 4;
    for (long i = ((long)blockIdx.x * blockDim.x + threadIdx.x) * 4; i < n; i += stride){
        float4 v = *(const float4*)(in + i);
        uint2 w;
        w.x = pack_half2(v.x, v.y);
        w.y = pack_half2(v.z, v.w);
        *(uint2*)(o + i) = w;
    }
}

// warp-per-row layernorm -> single fp16 output
__global__ void ln_k(const float* __restrict__ in,
                     const float* __restrict__ w,
                     const float* __restrict__ b,
                     __half* __restrict__ oh){
    int warp = threadIdx.x >> 5, lane = threadIdx.x & 31;
    int row = blockIdx.x * 8 + warp;
    const float* xp = in + (size_t)row * Cdim;
    float4 v[6];
    float s = 0.f, ss = 0.f;
    #pragma unroll
    for (int k = 0; k < 6; k++){
        v[k] = *(const float4*)(xp + lane*4 + k*128);
        s  += v[k].x + v[k].y + v[k].z + v[k].w;
        ss += v[k].x*v[k].x + v[k].y*v[k].y + v[k].z*v[k].z + v[k].w*v[k].w;
    }
    #pragma unroll
    for (int o = 16; o > 0; o >>= 1){
        s  += __shfl_xor_sync(0xffffffffu, s,  o);
        ss += __shfl_xor_sync(0xffffffffu, ss, o);
    }
    float mean = s * (1.f / Cdim);
    float var  = ss * (1.f / Cdim) - mean * mean;
    float rstd = rsqrtf(var + 1e-5f);
    #pragma unroll
    for (int k = 0; k < 6; k++){
        int c = lane*4 + k*128;
        float y0 = (v[k].x - mean) * rstd * w[c]   + b[c];
        float y1 = (v[k].y - mean) * rstd * w[c+1] + b[c+1];
        float y2 = (v[k].z - mean) * rstd * w[c+2] + b[c+2];
        float y3 = (v[k].w - mean) * rstd * w[c+3] + b[c+3];
        uint2 hw;
        hw.x = pack_half2(y0, y1);
        hw.y = pack_half2(y2, y3);
        *(uint2*)(oh + (size_t)row*Cdim + c) = hw;
    }
}

// ===================== unified fp16 1-term GEMM (mma.sync) ==================
// C[M,N] = A[M,K] @ B[N,K]^T. K-stage 64 (row stride 144B). Split-K via gridDim.z.
// modes: 0: out_f = acc (bounds-checked) + LSE partials (lm_head)
//        1: out_h = relu(acc+bias) fp16
//        2: atomicAdd(out_f, acc [+bias if z==0])
//        3: out_h = acc+bias fp16
#define G1_MAT  18432            /* 128 rows * 144 bytes */
#define G1_STG  (2*G1_MAT)
#define G1_SMEM (2*G1_STG)       /* 73728 */

__global__ __launch_bounds__(256, 2) void gemm_1t_k(
        const __half* __restrict__ A, const __half* __restrict__ Bm,
        const float* __restrict__ bias,
        float* __restrict__ out_f, __half* __restrict__ out_h,
        float* __restrict__ pmax, float* __restrict__ psum,
        int N, int K, int mode){
    extern __shared__ char smem[];
    uint32_t sbase = smem_to_u32(smem);
    int tid = threadIdx.x, wid = tid >> 5, lane = tid & 31;
    int warpRow = wid >> 2, warpCol = wid & 3;

    long row0 = (long)blockIdx.x * 128;
    long n0   = (long)blockIdx.y * 128;
    int kspan = K / (int)gridDim.z;
    long kbase = (long)blockIdx.z * kspan;
    int nIter = kspan >> 6;

    float acc[4][4][4];
    #pragma unroll
    for (int i = 0; i < 4; i++)
        #pragma unroll
        for (int j = 0; j < 4; j++)
            #pragma unroll
            for (int q = 0; q < 4; q++) acc[i][j][q] = 0.f;

    auto issue = [&](int it){
        if (it >= nIter) return;
        long k0 = kbase + ((long)it << 6);
        uint32_t stg = sbase + (uint32_t)(it & 1) * G1_STG;
        #pragma unroll
        for (int j = 0; j < 8; j++){
            int c   = tid + j * 256;           // 0..2047 (16B chunks)
            int mat = c >> 10;                 // 0:A 1:B
            int rem = c & 1023;
            int row = rem >> 3;                // 0..127
            int h8  = (rem & 7) << 3;          // half index 0..56
            const __half* src;
            if (mat == 0){
                src = A + (row0 + row) * (long)K + k0 + h8;
            } else {
                long br = n0 + row; if (br >= N) br = 0;
                src = Bm + br * (long)K + k0 + h8;
            }
            uint32_t dst = stg + (uint32_t)(mat * G1_MAT + row * 144 + h8 * 2);
            cp_async16(dst, src);
        }
        CP_COMMIT();
    };

    issue(0);
    for (int it = 0; it < nIter; it++){
        CP_WAIT0();
        __syncthreads();        // data(it) visible + all warps done with compute(it-1)
        issue(it + 1);

        uint32_t stg = sbase + (uint32_t)(it & 1) * G1_STG;
        uint32_t aS = stg;
        uint32_t bS = stg + G1_MAT;
        uint32_t rsel = (uint32_t)(lane & 15) * 144 + (uint32_t)(lane >> 4) * 16;

        #pragma unroll
        for (int ks = 0; ks < 64; ks += 16){
            uint32_t bf[2][4];
            #pragma unroll
            for (int nj = 0; nj < 2; nj++){
                uint32_t off = (uint32_t)((warpCol*32 + nj*16) * 144 + ks*2) + rsel;
                ldsm_x4(bf[nj], bS + off);
            }
            #pragma unroll
            for (int mi = 0; mi < 4; mi++){
                uint32_t af[4];
                uint32_t off = (uint32_t)((warpRow*64 + mi*16) * 144 + ks*2) + rsel;
                ldsm_x4(af, aS + off);
                #pragma unroll
                for (int ni = 0; ni < 4; ni++){
                    int nj = ni >> 1, w = ni & 1;
                    mma_f16(acc[mi][ni], af, bf[nj][w], bf[nj][w+2]);
                }
            }
        }
    }

    if (mode == 0){
        // scalar stores: logits base pointer may be only 4B-aligned (out+1)
        #pragma unroll
        for (int mi = 0; mi < 4; mi++){
            long r0 = row0 + warpRow*64 + mi*16 + (lane >> 2);
            #pragma unroll
            for (int ni = 0; ni < 4; ni++){
                long c0 = n0 + warpCol*32 + ni*8 + (lane & 3)*2;
                #pragma unroll
                for (int half = 0; half < 2; half++){
                    long r = r0 + half*8;
                    #pragma unroll
                    for (int e = 0; e < 2; e++){
                        long n = c0 + e;
                        if (n < N)
                            out_f[r * (long)N + n] = acc[mi][ni][half*2 + e];
                    }
                }
            }
        }
        // fused LSE partials for this 128x128 block
        __syncthreads();
        float* pm_s = (float*)smem;            // [128][4]
        float* ps_s = (float*)smem + 512;      // [128][4]
        #pragma unroll
        for (int mi = 0; mi < 4; mi++){
            #pragma unroll
            for (int half = 0; half < 2; half++){
                int lr = warpRow*64 + mi*16 + (lane >> 2) + half*8;
                float vv[8];
                float lm = -1e30f;
                #pragma unroll
                for (int ni = 0; ni < 4; ni++)
                    #pragma unroll
                    for (int e = 0; e < 2; e++){
                        long n = n0 + warpCol*32 + ni*8 + (lane & 3)*2 + e;
                        float t = (n < N) ? acc[mi][ni][half*2 + e] : -1e30f;
                        vv[ni*2 + e] = t;
                        lm = fmaxf(lm, t);
                    }
                lm = fmaxf(lm, __shfl_xor_sync(0xffffffffu, lm, 1));
                lm = fmaxf(lm, __shfl_xor_sync(0xffffffffu, lm, 2));
                float ls = 0.f;
                #pragma unroll
                for (int q = 0; q < 8; q++) ls += __expf(vv[q] - lm);
                ls += __shfl_xor_sync(0xffffffffu, ls, 1);
                ls += __shfl_xor_sync(0xffffffffu, ls, 2);
                if ((lane & 3) == 0){
                    pm_s[lr*4 + warpCol] = lm;
                    ps_s[lr*4 + warpCol] = ls;
                }
            }
        }
        __syncthreads();
        if (tid < 128){
            float m0 = pm_s[tid*4], m1 = pm_s[tid*4+1], m2 = pm_s[tid*4+2], m3 = pm_s[tid*4+3];
            float M = fmaxf(fmaxf(m0, m1), fmaxf(m2, m3));
            float S = ps_s[tid*4]  *__expf(m0 - M) + ps_s[tid*4+1]*__expf(m1 - M)
                    + ps_s[tid*4+2]*__expf(m2 - M) + ps_s[tid*4+3]*__expf(m3 - M);
            long r = row0 + tid;
            pmax[r*NPB + blockIdx.y] = M;
            psum[r*NPB + blockIdx.y] = S;
        }
        return;
    }

    bool addBias = (blockIdx.z == 0);
    #pragma unroll
    for (int mi = 0; mi < 4; mi++){
        long r0 = row0 + warpRow*64 + mi*16 + (lane >> 2);
        #pragma unroll
        for (int ni = 0; ni < 4; ni++){
            long c0 = n0 + warpCol*32 + ni*8 + (lane & 3)*2;
            float b0 = addBias ? bias[c0]     : 0.f;
            float b1 = addBias ? bias[c0 + 1] : 0.f;
            #pragma unroll
            for (int half = 0; half < 2; half++){
                long r  = r0 + half*8;
                long oi = r * (long)N + c0;
                float v0 = acc[mi][ni][half*2]     + b0;
                float v1 = acc[mi][ni][half*2 + 1] + b1;
                if (mode == 2){
                    atomicAdd(out_f + oi,     v0);
                    atomicAdd(out_f + oi + 1, v1);
                } else {
                    if (mode == 1){
                        v0 = fmaxf(v0, 0.f);
                        v1 = fmaxf(v1, 0.f);
                    }
                    *(uint32_t*)(out_h + oi) = pack_half2(v0, v1);
                }
            }
        }
    }
}

// ===================== flash attention (fp16 mma, 1-term, KV-stage 128) =====
#define FA_QB    (128*144)               /* 18432 */
#define FA_KVMAT (128*144)               /* 18432 per matrix per stage */
#define FA_STGB  (2*FA_KVMAT)            /* 36864 */
#define FA_SMEM  (FA_QB + 2*FA_STGB)     /* 92160 */

__global__ __launch_bounds__(256, 2) void flash_k(const __half* __restrict__ qkv){
    extern __shared__ char smem[];
    uint32_t sb = smem_to_u32(smem);
    uint32_t Qs = sb;
    uint32_t kvb = sb + FA_QB;

    int tid = threadIdx.x, wid = tid >> 5, lane = tid & 31;
    int g = lane >> 2, tq = lane & 3;
    int qb = (int)gridDim.x - 1 - (int)blockIdx.x;
    int bh = blockIdx.y; int bq = bh / Hdim, head = bh % Hdim;
    int q0 = qb * 128;
    long rowbase = (long)bq * Tdim;

    #pragma unroll
    for (int j = 0; j < 4; j++){
        int id = tid + j*256;                 // 0..1023
        int row = id >> 3, c8 = (id & 7) << 3;
        const __half* src = qkv + (rowbase + q0 + row)*(long)C3 + head*Ddim + c8;
        cp_async16(Qs + (uint32_t)(row*144 + c8*2), src);
    }

    int nkv = qb + 1;                         // 128-row KV stages
    auto issue = [&](int j){
        if (j >= nkv) return;
        int s0 = j * 128;
        uint32_t stg = kvb + (uint32_t)(j & 1) * FA_STGB;
        #pragma unroll
        for (int jj = 0; jj < 8; jj++){
            int id = tid + jj*256;            // 0..2047
            int mat = id >> 10, rem = id & 1023;  // 0:K 1:V
            int row = rem >> 3, c8 = (rem & 7) << 3;
            int coff = mat ? 2*Cdim : Cdim;
            const __half* src = qkv
                + (rowbase + s0 + row)*(long)C3 + coff + head*Ddim + c8;
            cp_async16(stg + (uint32_t)(mat*FA_KVMAT + row*144 + c8*2), src);
        }
        CP_COMMIT();
    };

    // log2-domain softmax: scores scaled by 0.125*log2(e)
    const float SC2 = 0.18033688f;
    float mrow[2] = {-1e30f, -1e30f};
    float lrow[2] = {0.f, 0.f};
    float oacc[8][4];
    #pragma unroll
    for (int i = 0; i < 8; i++)
        #pragma unroll
        for (int e = 0; e < 4; e++) oacc[i][e] = 0.f;

    int t0w = q0 + wid*16;
    uint32_t rsel16 = (uint32_t)(lane & 15)*144 + (uint32_t)(lane >> 4)*16;
    int vtsel = lane >> 3, vrt = lane & 7;
    uint32_t vrow_off = ((vtsel >> 1) ? 8u : 0u) + (uint32_t)vrt;
    uint32_t vcol_off = (vtsel & 1) ? 16u : 0u;

    issue(0);
    for (int j = 0; j < nkv; j++){
        CP_WAIT0();
        __syncthreads();
        issue(j + 1);

        uint32_t stg = kvb + (uint32_t)(j & 1) * FA_STGB;
        #pragma unroll
        for (int sub = 0; sub < 2; sub++){
            int s0 = j * 128 + sub * 64;
            if (s0 > t0w + 15) continue;
            uint32_t Kh = stg + (uint32_t)sub * (64*144);
            uint32_t Vh = stg + FA_KVMAT + (uint32_t)sub * (64*144);

            float S[8][4];
            #pragma unroll
            for (int i = 0; i < 8; i++)
                #pragma unroll
                for (int e = 0; e < 4; e++) S[i][e] = 0.f;

            #pragma unroll
            for (int dc = 0; dc < 4; dc++){
                uint32_t aoff = (uint32_t)(wid*16)*144 + (uint32_t)dc*32 + rsel16;
                uint32_t ah[4];
                ldsm_x4(ah, Qs + aoff);
                #pragma unroll
                for (int ng = 0; ng < 4; ng++){
                    uint32_t boff = (uint32_t)(ng*16)*144 + (uint32_t)dc*32 + rsel16;
                    uint32_t kh[4];
                    ldsm_x4(kh, Kh + boff);
                    #pragma unroll
                    for (int w = 0; w < 2; w++)
                        mma_f16(S[ng*2+w], ah, kh[w], kh[w+2]);
                }
            }

            bool needMask = (s0 + 63 > t0w);
            #pragma unroll
            for (int ns = 0; ns < 8; ns++)
                #pragma unroll
                for (int e = 0; e < 4; e++){
                    float v = S[ns][e] * SC2;
                    if (needMask){
                        int t = t0w + g + (e >> 1)*8;
                        int s = s0 + ns*8 + tq*2 + (e & 1);
                        if (s > t) v = -1e30f;
                    }
                    S[ns][e] = v;
                }

            #pragma unroll
            for (int r = 0; r < 2; r++){
                float mx = -1e30f;
                #pragma unroll
                for (int ns = 0; ns < 8; ns++)
                    mx = fmaxf(mx, fmaxf(S[ns][r*2], S[ns][r*2+1]));
                mx = fmaxf(mx, __shfl_xor_sync(0xffffffffu, mx, 1));
                mx = fmaxf(mx, __shfl_xor_sync(0xffffffffu, mx, 2));
                float mnew = fmaxf(mrow[r], mx);
                float corr = exp2f(mrow[r] - mnew);
                mrow[r] = mnew;
                float lsum = 0.f;
                #pragma unroll
                for (int ns = 0; ns < 8; ns++){
                    float p0 = exp2f(S[ns][r*2]   - mnew);
                    float p1 = exp2f(S[ns][r*2+1] - mnew);
                    S[ns][r*2] = p0; S[ns][r*2+1] = p1;
                    lsum += p0 + p1;
                }
                lsum += __shfl_xor_sync(0xffffffffu, lsum, 1);
                lsum += __shfl_xor_sync(0xffffffffu, lsum, 2);
                lrow[r] = lrow[r]*corr + lsum;
                #pragma unroll
                for (int dt = 0; dt < 8; dt++){
                    oacc[dt][r*2]   *= corr;
                    oacc[dt][r*2+1] *= corr;
                }
            }

            #pragma unroll
            for (int sc = 0; sc < 4; sc++){
                uint32_t ph[4];
                #pragma unroll
                for (int half = 0; half < 2; half++){
                    int ns = sc*2 + half;
                    ph[half*2+0] = pack_half2(S[ns][0], S[ns][1]);
                    ph[half*2+1] = pack_half2(S[ns][2], S[ns][3]);
                }
                uint32_t vbase = (uint32_t)((sc*16 + vrow_off)*144) + vcol_off;
                #pragma unroll
                for (int dg = 0; dg < 4; dg++){
                    uint32_t vh_[4];
                    ldsm_x4_t(vh_, Vh + vbase + (uint32_t)dg*32);
                    #pragma unroll
                    for (int w = 0; w < 2; w++)
                        mma_f16(oacc[dg*2 + w], ph, vh_[w], vh_[w+2]);
                }
            }
        }
    }

    #pragma unroll
    for (int r = 0; r < 2; r++){
        float inv = 1.f / lrow[r];
        long t = (long)t0w + g + r*8;
        float* hp = g_h + (rowbase + t)*(long)Cdim + head*Ddim;
        #pragma unroll
        for (int dt = 0; dt < 8; dt++){
            float2* p = (float2*)(hp + dt*8 + tq*2);
            float2 v = *p;
            v.x += oacc[dt][r*2]   * inv;
            v.y += oacc[dt][r*2+1] * inv;
            *p = v;
        }
    }
}

// ===================== loss from LSE partials ================================
__global__ void loss_row2_k(const float* __restrict__ logits,
                            const int* __restrict__ target){
    int row = blockIdx.x, tid = threadIdx.x;
    const float* pm = g_pmax + (size_t)row * NPB;
    const float* ps = g_psum + (size_t)row * NPB;
    float m = -1e30f, s = 0.f;
    for (int i = tid; i < NPB; i += 256){
        float im = pm[i], is = ps[i];
        if (im > m){
            s = s * __expf(m - im) + is;
            m = im;
        } else {
            s += is * __expf(im - m);
        }
    }
    float mg = blockReduceMax(m);
    s *= __expf(m - mg);
    float tot = blockReduceSum(s);
    if (tid == 0){
        float lse = logf(tot) + mg;
        g_rowloss[row] = lse - logits[(size_t)row * Vdim + target[row]];
    }
}
__global__ void loss_reduce_k(float* out){
    float s = 0.f;
    for (int i = threadIdx.x; i < Mdim; i += 256) s += g_rowloss[i];
    s = blockReduceSum(s);
    if (threadIdx.x == 0) out[0] = s / (float)Mdim;
}

// ===================== launch ===============================================
extern "C" void kernel_launch(void* const* d_in, const int* in_sizes, int n_in,
                              void* d_out, int out_size){
    const int*   x      = (const int*)  d_in[0];
    const int*   target = (const int*)  d_in[1];
    const float* wte    = (const float*)d_in[2];
    const float* wpe    = (const float*)d_in[3];
    const float* ln1_w  = (const float*)d_in[4];
    const float* ln1_b  = (const float*)d_in[5];
    const float* attn_w = (const float*)d_in[6];
    const float* attn_b = (const float*)d_in[7];
    const float* ln2_w  = (const float*)d_in[8];
    const float* ln2_b  = (const float*)d_in[9];
    const float* ff1_w  = (const float*)d_in[10];
    const float* ff1_b  = (const float*)d_in[11];
    const float* ff2_w  = (const float*)d_in[12];
    const float* ff2_b  = (const float*)d_in[13];
    const float* lm_w   = (const float*)d_in[14];

    float* out = (float*)d_out;
    bool has_loss = ((long long)out_size == (long long)Mdim * Vdim + 1);
    float* logits = has_loss ? out + 1 : out;

    cudaFuncSetAttribute(gemm_1t_k, cudaFuncAttributeMaxDynamicSharedMemorySize, G1_SMEM);
    cudaFuncSetAttribute(flash_k,   cudaFuncAttributeMaxDynamicSharedMemorySize, FA_SMEM);

    float* ph;
    cudaGetSymbolAddress((void**)&ph, g_h);
    __half *wqk,*wf1,*wf2,*wlm,*xn,*ffh,*ah,*qv;
    float *ppm,*pps;
    cudaGetSymbolAddress((void**)&wqk, g_wqkv_h);
    cudaGetSymbolAddress((void**)&wf1, g_wff1_h);
    cudaGetSymbolAddress((void**)&wf2, g_wff2_h);
    cudaGetSymbolAddress((void**)&wlm, g_wlm_h);
    cudaGetSymbolAddress((void**)&xn,  g_xn);
    cudaGetSymbolAddress((void**)&ffh, g_ffh);
    cudaGetSymbolAddress((void**)&ah,  g_ah);
    cudaGetSymbolAddress((void**)&qv,  g_qkv);
    cudaGetSymbolAddress((void**)&ppm, g_pmax);
    cudaGetSymbolAddress((void**)&pps, g_psum);

    cvt_h_k<<<2048, 256>>>(attn_w, wqk, (long)Ldim*C3*Cdim);
    cvt_h_k<<<2048, 256>>>(ff1_w,  wf1, (long)Ldim*Fdim*Cdim);
    cvt_h_k<<<2048, 256>>>(ff2_w,  wf2, (long)Ldim*Cdim*Fdim);
    cvt_h_k<<<4096, 256>>>(lm_w,   wlm, (long)Vdim*Cdim);

    embed_k<<<(Mdim*Cdim + 255)/256, 256>>>(x, wte, wpe);

    for (int l = 0; l < Ldim; l++){
        ln_k<<<Mdim/8, 256>>>(ph, ln1_w + (size_t)l*Cdim, ln1_b + (size_t)l*Cdim, xn);

        gemm_1t_k<<<dim3(Mdim/128, C3/128, 1), 256, G1_SMEM>>>(
            xn, wqk + (size_t)l*C3*Cdim, attn_b + (size_t)l*C3,
            nullptr, qv, nullptr, nullptr, C3, Cdim, 3);

        flash_k<<<dim3(Tdim/128, Bdim*Hdim), 256, FA_SMEM>>>(qv);

        ln_k<<<Mdim/8, 256>>>(ph, ln2_w + (size_t)l*Cdim, ln2_b + (size_t)l*Cdim, xn);

        gemm_1t_k<<<dim3(Mdim/128, Fdim/128, 1), 256, G1_SMEM>>>(
            xn, wf1 + (size_t)l*Fdim*Cdim, ff1_b + (size_t)l*Fdim,
            nullptr, ffh, nullptr, nullptr, Fdim, Cdim, 1);

        // split-K x3: 576 CTAs (1.95 waves at 2 CTA/SM, ~97% util)
        gemm_1t_k<<<dim3(Mdim/128, Cdim/128, 3), 256, G1_SMEM>>>(
            ffh, wf2 + (size_t)l*Cdim*Fdim, ff2_b + (size_t)l*Cdim,
            ph, nullptr, nullptr, nullptr, Cdim, Fdim, 2);
    }

    cvt_h_k<<<2048, 256>>>(ph, ah, (long)Mdim*Cdim);

    gemm_1t_k<<<dim3(Mdim/128, NPB, 1), 256, G1_SMEM>>>(
        ah, wlm, nullptr, logits, nullptr, ppm, pps, Vdim, Cdim, 0);

    loss_row2_k<<<Mdim, 256>>>(logits, target);
    if (has_loss)
        loss_reduce_k<<<1, 256>>>(out);
}

// round 14
// speedup vs baseline: 1.7473x; 1.0204x over previous
#include <cuda_runtime.h>
#include <cuda_bf16.h>
#include <cuda_fp16.h>
#include <cstdint>
#include <math.h>

#define Bdim 2
#define Tdim 2048
#define Cdim 768
#define Hdim 12
#define Ddim 64
#define Ldim 6
#define Vdim 50257
#define Mdim (Bdim*Tdim)      /* 4096 */
#define C3   (3*Cdim)         /* 2304 */
#define Fdim (4*Cdim)         /* 3072 */
#define NPB  393              /* (Vdim+127)/128 logits col-blocks */
#define PHB  ((long)Bdim*Hdim*Tdim)   /* 49152 partial rows per z */

// ===================== device scratch (no allocations) ======================
__device__ float g_h  [Mdim*Cdim];
__device__ float g_rowloss[Mdim];
__device__ float g_pmax[(size_t)Mdim*NPB];
__device__ float g_psum[(size_t)Mdim*NPB];

__device__ __half g_po[2*PHB*Ddim];      // normalized partial attn out
__device__ float  g_pm[2*PHB];           // partial max (log2 domain)
__device__ float  g_pl[2*PHB];           // partial sum

__device__ __half g_wqkv_h[Ldim*C3*Cdim];
__device__ __half g_wff1_h[Ldim*Fdim*Cdim];
__device__ __half g_wff2_h[Ldim*Cdim*Fdim];
__device__ __half g_wlm_h[(size_t)Vdim*Cdim];
__device__ __half g_xn [Mdim*Cdim];
__device__ __half g_ffh[Mdim*Fdim];
__device__ __half g_ah [Mdim*Cdim];
__device__ __half g_qkv[Mdim*C3];

// ===================== asm helpers (baseline sm_80+ ISA) ====================
__device__ __forceinline__ uint32_t smem_to_u32(const void* p) {
    uint32_t a;
    asm("{ .reg .u64 t; cvta.to.shared.u64 t, %1; cvt.u32.u64 %0, t; }" : "=r"(a) : "l"(p));
    return a;
}
__device__ __forceinline__ void cp_async16(uint32_t dst, const void* src){
    asm volatile("cp.async.cg.shared.global [%0], [%1], 16;" :: "r"(dst), "l"(src));
}
#define CP_COMMIT() asm volatile("cp.async.commit_group;" ::: "memory")
#define CP_WAIT0()  asm volatile("cp.async.wait_group 0;" ::: "memory")

__device__ __forceinline__ void ldsm_x4(uint32_t* r, uint32_t addr){
    asm volatile("ldmatrix.sync.aligned.m8n8.x4.shared.b16 {%0,%1,%2,%3}, [%4];"
        : "=r"(r[0]), "=r"(r[1]), "=r"(r[2]), "=r"(r[3]) : "r"(addr));
}
__device__ __forceinline__ void ldsm_x4_t(uint32_t* r, uint32_t addr){
    asm volatile("ldmatrix.sync.aligned.m8n8.x4.trans.shared.b16 {%0,%1,%2,%3}, [%4];"
        : "=r"(r[0]), "=r"(r[1]), "=r"(r[2]), "=r"(r[3]) : "r"(addr));
}
__device__ __forceinline__ void mma_f16(float* d, const uint32_t* a,
                                        uint32_t b0, uint32_t b1){
    asm volatile("mma.sync.aligned.m16n8k16.row.col.f32.f16.f16.f32 "
        "{%0,%1,%2,%3}, {%4,%5,%6,%7}, {%8,%9}, {%0,%1,%2,%3};"
        : "+f"(d[0]), "+f"(d[1]), "+f"(d[2]), "+f"(d[3])
        : "r"(a[0]), "r"(a[1]), "r"(a[2]), "r"(a[3]), "r"(b0), "r"(b1));
}
__device__ __forceinline__ uint32_t pack_half2(float lo, float hi){
    uint32_t r;
    asm("cvt.rn.f16x2.f32 %0, %1, %2;" : "=r"(r) : "f"(hi), "f"(lo));
    return r;
}

// ===================== reductions ===========================================
__device__ __forceinline__ float blockReduceMax(float v){
    __shared__ float sh[8];
    int lid = threadIdx.x & 31, wid = threadIdx.x >> 5;
    #pragma unroll
    for (int o = 16; o > 0; o >>= 1) v = fmaxf(v, __shfl_xor_sync(0xffffffffu, v, o));
    if (lid == 0) sh[wid] = v;
    __syncthreads();
    v = sh[lid & 7];
    #pragma unroll
    for (int o = 4; o > 0; o >>= 1) v = fmaxf(v, __shfl_xor_sync(0xffffffffu, v, o));
    __syncthreads();
    return v;
}
__device__ __forceinline__ float blockReduceSum(float v){
    __shared__ float sh[8];
    int lid = threadIdx.x & 31, wid = threadIdx.x >> 5;
    #pragma unroll
    for (int o = 16; o > 0; o >>= 1) v += __shfl_xor_sync(0xffffffffu, v, o);
    if (lid == 0) sh[wid] = v;
    __syncthreads();
    v = sh[lid & 7];
    #pragma unroll
    for (int o = 4; o > 0; o >>= 1) v += __shfl_xor_sync(0xffffffffu, v, o);
    __syncthreads();
    return v;
}

// ===================== small kernels ========================================
__global__ void embed_k(const int* __restrict__ x,
                        const float* __restrict__ wte,
                        const float* __restrict__ wpe){
    int i = blockIdx.x * blockDim.x + threadIdx.x;
    if (i >= Mdim * Cdim) return;
    int c  = i % Cdim;
    int bt = i / Cdim;
    int t  = bt % Tdim;
    g_h[i] = wte[(size_t)x[bt] * Cdim + c] + wpe[(size_t)t * Cdim + c];
}

__global__ void cvt_h_k(const float* __restrict__ in, __half* __restrict__ o, long n){
    long stride = (long)gridDim.x * blockDim.x * 4;
    for (long i = ((long)blockIdx.x * blockDim.x + threadIdx.x) * 4; i < n; i += stride){
        float4 v = *(const float4*)(in + i);
        uint2 w;
        w.x = pack_half2(v.x, v.y);
        w.y = pack_half2(v.z, v.w);
        *(uint2*)(o + i) = w;
    }
}

// warp-per-row layernorm -> single fp16 output (pre-attention LN)
__global__ void ln_k(const float* __restrict__ in,
                     const float* __restrict__ w,
                     const float* __restrict__ b,
                     __half* __restrict__ oh){
    int warp = threadIdx.x >> 5, lane = threadIdx.x & 31;
    int row = blockIdx.x * 8 + warp;
    const float* xp = in + (size_t)row * Cdim;
    float4 v[6];
    float s = 0.f, ss = 0.f;
    #pragma unroll
    for (int k = 0; k < 6; k++){
        v[k] = *(const float4*)(xp + lane*4 + k*128);
        s  += v[k].x + v[k].y + v[k].z + v[k].w;
        ss += v[k].x*v[k].x + v[k].y*v[k].y + v[k].z*v[k].z + v[k].w*v[k].w;
    }
    #pragma unroll
    for (int o = 16; o > 0; o >>= 1){
        s  += __shfl_xor_sync(0xffffffffu, s,  o);
        ss += __shfl_xor_sync(0xffffffffu, ss, o);
    }
    float mean = s * (1.f / Cdim);
    float var  = ss * (1.f / Cdim) - mean * mean;
    float rstd = rsqrtf(var + 1e-5f);
    #pragma unroll
    for (int k = 0; k < 6; k++){
        int c = lane*4 + k*128;
        float y0 = (v[k].x - mean) * rstd * w[c]   + b[c];
        float y1 = (v[k].y - mean) * rstd * w[c+1] + b[c+1];
        float y2 = (v[k].z - mean) * rstd * w[c+2] + b[c+2];
        float y3 = (v[k].w - mean) * rstd * w[c+3] + b[c+3];
        uint2 hw;
        hw.x = pack_half2(y0, y1);
        hw.y = pack_half2(y2, y3);
        *(uint2*)(oh + (size_t)row*Cdim + c) = hw;
    }
}

// combine flash partials + residual add + layernorm (post-attention)
__global__ void ln_att_k(float* __restrict__ hbuf,
                         const float* __restrict__ w,
                         const float* __restrict__ b,
                         __half* __restrict__ oh){
    int warp = threadIdx.x >> 5, lane = threadIdx.x & 31;
    int row = blockIdx.x * 8 + warp;          // 0..4095
    int bq = row >> 11;                        // batch
    int t  = row & 2047;
    float* xp = hbuf + (size_t)row * Cdim;
    float4 v[6];
    float s = 0.f, ss = 0.f;
    #pragma unroll
    for (int k = 0; k < 6; k++){
        int c = lane*4 + k*128;
        v[k] = *(const float4*)(xp + c);
        int head = c >> 6;
        long idx = ((long)(bq*Hdim + head) * Tdim + t);
        float m0 = g_pm[idx],       l0 = g_pl[idx];
        float m1 = g_pm[PHB + idx], l1 = g_pl[PHB + idx];
        float M  = fmaxf(m0, m1);
        float w0 = exp2f(m0 - M) * l0;
        float w1 = exp2f(m1 - M) * l1;
        float inv = 1.f / (w0 + w1);
        int d = c & 63;
        uint2 o0w = *(const uint2*)(g_po + idx*64 + d);
        uint2 o1w = *(const uint2*)(g_po + (PHB + idx)*64 + d);
        __half2 a0 = *(__half2*)&o0w.x, a1 = *(__half2*)&o0w.y;
        __half2 c0 = *(__half2*)&o1w.x, c1 = *(__half2*)&o1w.y;
        float2 f0 = __half22float2(a0), f1 = __half22float2(a1);
        float2 g0 = __half22float2(c0), g1 = __half22float2(c1);
        v[k].x += (f0.x*w0 + g0.x*w1) * inv;
        v[k].y += (f0.y*w0 + g0.y*w1) * inv;
        v[k].z += (f1.x*w0 + g1.x*w1) * inv;
        v[k].w += (f1.y*w0 + g1.y*w1) * inv;
        s  += v[k].x + v[k].y + v[k].z + v[k].w;
        ss += v[k].x*v[k].x + v[k].y*v[k].y + v[k].z*v[k].z + v[k].w*v[k].w;
    }
    #pragma unroll
    for (int o = 16; o > 0; o >>= 1){
        s  += __shfl_xor_sync(0xffffffffu, s,  o);
        ss += __shfl_xor_sync(0xffffffffu, ss, o);
    }
    float mean = s * (1.f / Cdim);
    float var  = ss * (1.f / Cdim) - mean * mean;
    float rstd = rsqrtf(var + 1e-5f);
    #pragma unroll
    for (int k = 0; k < 6; k++){
        int c = lane*4 + k*128;
        *(float4*)(xp + c) = v[k];             // residual write-back
        float y0 = (v[k].x - mean) * rstd * w[c]   + b[c];
        float y1 = (v[k].y - mean) * rstd * w[c+1] + b[c+1];
        float y2 = (v[k].z - mean) * rstd * w[c+2] + b[c+2];
        float y3 = (v[k].w - mean) * rstd * w[c+3] + b[c+3];
        uint2 hw;
        hw.x = pack_half2(y0, y1);
        hw.y = pack_half2(y2, y3);
        *(uint2*)(oh + (size_t)row*Cdim + c) = hw;
    }
}

// ===================== unified fp16 1-term GEMM (mma.sync) ==================
// C[M,N] = A[M,K] @ B[N,K]^T. K-stage 64 (row stride 144B). Split-K via gridDim.z.
// modes: 0: out_f = acc (bounds-checked) + LSE partials (lm_head)
//        1: out_h = relu(acc+bias) fp16
//        2: atomicAdd(out_f, acc [+bias if z==0])
//        3: out_h = acc+bias fp16
#define G1_MAT  18432            /* 128 rows * 144 bytes */
#define G1_STG  (2*G1_MAT)
#define G1_SMEM (2*G1_STG)       /* 73728 */

__global__ __launch_bounds__(256, 2) void gemm_1t_k(
        const __half* __restrict__ A, const __half* __restrict__ Bm,
        const float* __restrict__ bias,
        float* __restrict__ out_f, __half* __restrict__ out_h,
        float* __restrict__ pmax, float* __restrict__ psum,
        int N, int K, int mode){
    extern __shared__ char smem[];
    uint32_t sbase = smem_to_u32(smem);
    int tid = threadIdx.x, wid = tid >> 5, lane = tid & 31;
    int warpRow = wid >> 2, warpCol = wid & 3;

    long row0 = (long)blockIdx.x * 128;
    long n0   = (long)blockIdx.y * 128;
    int kspan = K / (int)gridDim.z;
    long kbase = (long)blockIdx.z * kspan;
    int nIter = kspan >> 6;

    float acc[4][4][4];
    #pragma unroll
    for (int i = 0; i < 4; i++)
        #pragma unroll
        for (int j = 0; j < 4; j++)
            #pragma unroll
            for (int q = 0; q < 4; q++) acc[i][j][q] = 0.f;

    auto issue = [&](int it){
        if (it >= nIter) return;
        long k0 = kbase + ((long)it << 6);
        uint32_t stg = sbase + (uint32_t)(it & 1) * G1_STG;
        #pragma unroll
        for (int j = 0; j < 8; j++){
            int c   = tid + j * 256;           // 0..2047 (16B chunks)
            int mat = c >> 10;                 // 0:A 1:B
            int rem = c & 1023;
            int row = rem >> 3;                // 0..127
            int h8  = (rem & 7) << 3;          // half index 0..56
            const __half* src;
            if (mat == 0){
                src = A + (row0 + row) * (long)K + k0 + h8;
            } else {
                long br = n0 + row; if (br >= N) br = 0;
                src = Bm + br * (long)K + k0 + h8;
            }
            uint32_t dst = stg + (uint32_t)(mat * G1_MAT + row * 144 + h8 * 2);
            cp_async16(dst, src);
        }
        CP_COMMIT();
    };

    issue(0);
    for (int it = 0; it < nIter; it++){
        CP_WAIT0();
        __syncthreads();        // data(it) visible + all warps done with compute(it-1)
        issue(it + 1);

        uint32_t stg = sbase + (uint32_t)(it & 1) * G1_STG;
        uint32_t aS = stg;
        uint32_t bS = stg + G1_MAT;
        uint32_t rsel = (uint32_t)(lane & 15) * 144 + (uint32_t)(lane >> 4) * 16;

        #pragma unroll
        for (int ks = 0; ks < 64; ks += 16){
            uint32_t bf[2][4];
            #pragma unroll
            for (int nj = 0; nj < 2; nj++){
                uint32_t off = (uint32_t)((warpCol*32 + nj*16) * 144 + ks*2) + rsel;
                ldsm_x4(bf[nj], bS + off);
            }
            #pragma unroll
            for (int mi = 0; mi < 4; mi++){
                uint32_t af[4];
                uint32_t off = (uint32_t)((warpRow*64 + mi*16) * 144 + ks*2) + rsel;
                ldsm_x4(af, aS + off);
                #pragma unroll
                for (int ni = 0; ni < 4; ni++){
                    int nj = ni >> 1, w = ni & 1;
                    mma_f16(acc[mi][ni], af, bf[nj][w], bf[nj][w+2]);
                }
            }
        }
    }

    if (mode == 0){
        // scalar stores: logits base pointer may be only 4B-aligned (out+1)
        #pragma unroll
        for (int mi = 0; mi < 4; mi++){
            long r0 = row0 + warpRow*64 + mi*16 + (lane >> 2);
            #pragma unroll
            for (int ni = 0; ni < 4; ni++){
                long c0 = n0 + warpCol*32 + ni*8 + (lane & 3)*2;
                #pragma unroll
                for (int half = 0; half < 2; half++){
                    long r = r0 + half*8;
                    #pragma unroll
                    for (int e = 0; e < 2; e++){
                        long n = c0 + e;
                        if (n < N)
                            out_f[r * (long)N + n] = acc[mi][ni][half*2 + e];
                    }
                }
            }
        }
        // fused LSE partials for this 128x128 block
        __syncthreads();
        float* pm_s = (float*)smem;            // [128][4]
        float* ps_s = (float*)smem + 512;      // [128][4]
        #pragma unroll
        for (int mi = 0; mi < 4; mi++){
            #pragma unroll
            for (int half = 0; half < 2; half++){
                int lr = warpRow*64 + mi*16 + (lane >> 2) + half*8;
                float vv[8];
                float lm = -1e30f;
                #pragma unroll
                for (int ni = 0; ni < 4; ni++)
                    #pragma unroll
                    for (int e = 0; e < 2; e++){
                        long n = n0 + warpCol*32 + ni*8 + (lane & 3)*2 + e;
                        float t = (n < N) ? acc[mi][ni][half*2 + e] : -1e30f;
                        vv[ni*2 + e] = t;
                        lm = fmaxf(lm, t);
                    }
                lm = fmaxf(lm, __shfl_xor_sync(0xffffffffu, lm, 1));
                lm = fmaxf(lm, __shfl_xor_sync(0xffffffffu, lm, 2));
                float ls = 0.f;
                #pragma unroll
                for (int q = 0; q < 8; q++) ls += __expf(vv[q] - lm);
                ls += __shfl_xor_sync(0xffffffffu, ls, 1);
                ls += __shfl_xor_sync(0xffffffffu, ls, 2);
                if ((lane & 3) == 0){
                    pm_s[lr*4 + warpCol] = lm;
                    ps_s[lr*4 + warpCol] = ls;
                }
            }
        }
        __syncthreads();
        if (tid < 128){
            float m0 = pm_s[tid*4], m1 = pm_s[tid*4+1], m2 = pm_s[tid*4+2], m3 = pm_s[tid*4+3];
            float M = fmaxf(fmaxf(m0, m1), fmaxf(m2, m3));
            float S = ps_s[tid*4]  *__expf(m0 - M) + ps_s[tid*4+1]*__expf(m1 - M)
                    + ps_s[tid*4+2]*__expf(m2 - M) + ps_s[tid*4+3]*__expf(m3 - M);
            long r = row0 + tid;
            pmax[r*NPB + blockIdx.y] = M;
            psum[r*NPB + blockIdx.y] = S;
        }
        return;
    }

    bool addBias = (blockIdx.z == 0);
    #pragma unroll
    for (int mi = 0; mi < 4; mi++){
        long r0 = row0 + warpRow*64 + mi*16 + (lane >> 2);
        #pragma unroll
        for (int ni = 0; ni < 4; ni++){
            long c0 = n0 + warpCol*32 + ni*8 + (lane & 3)*2;
            float b0 = addBias ? bias[c0]     : 0.f;
            float b1 = addBias ? bias[c0 + 1] : 0.f;
            #pragma unroll
            for (int half = 0; half < 2; half++){
                long r  = r0 + half*8;
                long oi = r * (long)N + c0;
                float v0 = acc[mi][ni][half*2]     + b0;
                float v1 = acc[mi][ni][half*2 + 1] + b1;
                if (mode == 2){
                    atomicAdd(out_f + oi,     v0);
                    atomicAdd(out_f + oi + 1, v1);
                } else {
                    if (mode == 1){
                        v0 = fmaxf(v0, 0.f);
                        v1 = fmaxf(v1, 0.f);
                    }
                    *(uint32_t*)(out_h + oi) = pack_half2(v0, v1);
                }
            }
        }
    }
}

// ===================== flash attention (split-KV x2, partial outputs) =======
#define FA_QB    (128*144)               /* 18432 */
#define FA_KVMAT (128*144)               /* 18432 per matrix per stage */
#define FA_STGB  (2*FA_KVMAT)            /* 36864 */
#define FA_SMEM  (FA_QB + 2*FA_STGB)     /* 92160 */

__global__ __launch_bounds__(256, 2) void flash_k(const __half* __restrict__ qkv){
    extern __shared__ char smem[];
    uint32_t sb = smem_to_u32(smem);
    uint32_t Qs = sb;
    uint32_t kvb = sb + FA_QB;

    int tid = threadIdx.x, wid = tid >> 5, lane = tid & 31;
    int g = lane >> 2, tq = lane & 3;
    int qb = (int)gridDim.x - 1 - (int)blockIdx.x;
    int bh = blockIdx.y; int bq = bh / Hdim, head = bh % Hdim;
    int z = blockIdx.z;
    int q0 = qb * 128;
    long rowbase = (long)bq * Tdim;
    int t0w = q0 + wid*16;

    int nkv = qb + 1;
    int half_n = (nkv + 1) >> 1;
    int js = z ? half_n : 0;
    int je = z ? nkv : half_n;
    int cnt = je - js;
    long pbase = (long)z * PHB + (long)bh * Tdim;

    if (cnt <= 0){
        // empty partial: m=-1e30, l=0, o=0
        #pragma unroll
        for (int r = 0; r < 2; r++){
            long t = (long)t0w + g + r*8;
            long pr = pbase + t;
            if (tq == 0){ g_pm[pr] = -1e30f; g_pl[pr] = 0.f; }
            #pragma unroll
            for (int dt = 0; dt < 8; dt++)
                *(uint32_t*)(g_po + pr*64 + dt*8 + tq*2) = 0u;
        }
        return;
    }

    #pragma unroll
    for (int j = 0; j < 4; j++){
        int id = tid + j*256;                 // 0..1023
        int row = id >> 3, c8 = (id & 7) << 3;
        const __half* src = qkv + (rowbase + q0 + row)*(long)C3 + head*Ddim + c8;
        cp_async16(Qs + (uint32_t)(row*144 + c8*2), src);
    }

    auto issue = [&](int it){
        if (it >= cnt) return;
        int s0 = (js + it) * 128;
        uint32_t stg = kvb + (uint32_t)(it & 1) * FA_STGB;
        #pragma unroll
        for (int jj = 0; jj < 8; jj++){
            int id = tid + jj*256;            // 0..2047
            int mat = id >> 10, rem = id & 1023;  // 0:K 1:V
            int row = rem >> 3, c8 = (rem & 7) << 3;
            int coff = mat ? 2*Cdim : Cdim;
            const __half* src = qkv
                + (rowbase + s0 + row)*(long)C3 + coff + head*Ddim + c8;
            cp_async16(stg + (uint32_t)(mat*FA_KVMAT + row*144 + c8*2), src);
        }
        CP_COMMIT();
    };

    // log2-domain softmax: scores scaled by 0.125*log2(e)
    const float SC2 = 0.18033688f;
    float mrow[2] = {-1e30f, -1e30f};
    float lrow[2] = {0.f, 0.f};
    float oacc[8][4];
    #pragma unroll
    for (int i = 0; i < 8; i++)
        #pragma unroll
        for (int e = 0; e < 4; e++) oacc[i][e] = 0.f;

    uint32_t rsel16 = (uint32_t)(lane & 15)*144 + (uint32_t)(lane >> 4)*16;
    int vtsel = lane >> 3, vrt = lane & 7;
    uint32_t vrow_off = ((vtsel >> 1) ? 8u : 0u) + (uint32_t)vrt;
    uint32_t vcol_off = (vtsel & 1) ? 16u : 0u;

    issue(0);
    for (int it = 0; it < cnt; it++){
        CP_WAIT0();
        __syncthreads();
        issue(it + 1);

        uint32_t stg = kvb + (uint32_t)(it & 1) * FA_STGB;
        #pragma unroll
        for (int sub = 0; sub < 2; sub++){
            int s0 = (js + it) * 128 + sub * 64;
            if (s0 > t0w + 15) continue;
            uint32_t Kh = stg + (uint32_t)sub * (64*144);
            uint32_t Vh = stg + FA_KVMAT + (uint32_t)sub * (64*144);

            float S[8][4];
            #pragma unroll
            for (int i = 0; i < 8; i++)
                #pragma unroll
                for (int e = 0; e < 4; e++) S[i][e] = 0.f;

            #pragma unroll
            for (int dc = 0; dc < 4; dc++){
                uint32_t aoff = (uint32_t)(wid*16)*144 + (uint32_t)dc*32 + rsel16;
                uint32_t ah[4];
                ldsm_x4(ah, Qs + aoff);
                #pragma unroll
                for (int ng = 0; ng < 4; ng++){
                    uint32_t boff = (uint32_t)(ng*16)*144 + (uint32_t)dc*32 + rsel16;
                    uint32_t kh[4];
                    ldsm_x4(kh, Kh + boff);
                    #pragma unroll
                    for (int w = 0; w < 2; w++)
                        mma_f16(S[ng*2+w], ah, kh[w], kh[w+2]);
                }
            }

            bool needMask = (s0 + 63 > t0w);
            #pragma unroll
            for (int ns = 0; ns < 8; ns++)
                #pragma unroll
                for (int e = 0; e < 4; e++){
                    float v = S[ns][e] * SC2;
                    if (needMask){
                        int t = t0w + g + (e >> 1)*8;
                        int s = s0 + ns*8 + tq*2 + (e & 1);
                        if (s > t) v = -1e30f;
                    }
                    S[ns][e] = v;
                }

            #pragma unroll
            for (int r = 0; r < 2; r++){
                float mx = -1e30f;
                #pragma unroll
                for (int ns = 0; ns < 8; ns++)
                    mx = fmaxf(mx, fmaxf(S[ns][r*2], S[ns][r*2+1]));
                mx = fmaxf(mx, __shfl_xor_sync(0xffffffffu, mx, 1));
                mx = fmaxf(mx, __shfl_xor_sync(0xffffffffu, mx, 2));
                float mnew = fmaxf(mrow[r], mx);
                float corr = exp2f(mrow[r] - mnew);
                mrow[r] = mnew;
                float lsum = 0.f;
                #pragma unroll
                for (int ns = 0; ns < 8; ns++){
                    float p0 = exp2f(S[ns][r*2]   - mnew);
                    float p1 = exp2f(S[ns][r*2+1] - mnew);
                    S[ns][r*2] = p0; S[ns][r*2+1] = p1;
                    lsum += p0 + p1;
                }
                lsum += __shfl_xor_sync(0xffffffffu, lsum, 1);
                lsum += __shfl_xor_sync(0xffffffffu, lsum, 2);
                lrow[r] = lrow[r]*corr + lsum;
                #pragma unroll
                for (int dt = 0; dt < 8; dt++){
                    oacc[dt][r*2]   *= corr;
                    oacc[dt][r*2+1] *= corr;
                }
            }

            #pragma unroll
            for (int sc = 0; sc < 4; sc++){
                uint32_t ph[4];
                #pragma unroll
                for (int half = 0; half < 2; half++){
                    int ns = sc*2 + half;
                    ph[half*2+0] = pack_half2(S[ns][0], S[ns][1]);
                    ph[half*2+1] = pack_half2(S[ns][2], S[ns][3]);
                }
                uint32_t vbase = (uint32_t)((sc*16 + vrow_off)*144) + vcol_off;
                #pragma unroll
                for (int dg = 0; dg < 4; dg++){
                    uint32_t vh_[4];
                    ldsm_x4_t(vh_, Vh + vbase + (uint32_t)dg*32);
                    #pragma unroll
                    for (int w = 0; w < 2; w++)
                        mma_f16(oacc[dg*2 + w], ph, vh_[w], vh_[w+2]);
                }
            }
        }
    }

    // write partials: normalized o (fp16), m (log2 domain), l
    #pragma unroll
    for (int r = 0; r < 2; r++){
        float inv = 1.f / lrow[r];
        long t = (long)t0w + g + r*8;
        long pr = pbase + t;
        if (tq == 0){ g_pm[pr] = mrow[r]; g_pl[pr] = lrow[r]; }
        #pragma unroll
        for (int dt = 0; dt < 8; dt++)
            *(uint32_t*)(g_po + pr*64 + dt*8 + tq*2) =
                pack_half2(oacc[dt][r*2] * inv, oacc[dt][r*2+1] * inv);
    }
}

// ===================== loss from LSE partials ================================
__global__ void loss_row2_k(const float* __restrict__ logits,
                            const int* __restrict__ target){
    int row = blockIdx.x, tid = threadIdx.x;
    const float* pm = g_pmax + (size_t)row * NPB;
    const float* ps = g_psum + (size_t)row * NPB;
    float m = -1e30f, s = 0.f;
    for (int i = tid; i < NPB; i += 256){
        float im = pm[i], is = ps[i];
        if (im > m){
            s = s * __expf(m - im) + is;
            m = im;
        } else {
            s += is * __expf(im - m);
        }
    }
    float mg = blockReduceMax(m);
    s *= __expf(m - mg);
    float tot = blockReduceSum(s);
    if (tid == 0){
        float lse = logf(tot) + mg;
        g_rowloss[row] = lse - logits[(size_t)row * Vdim + target[row]];
    }
}
__global__ void loss_reduce_k(float* out){
    float s = 0.f;
    for (int i = threadIdx.x; i < Mdim; i += 256) s += g_rowloss[i];
    s = blockReduceSum(s);
    if (threadIdx.x == 0) out[0] = s / (float)Mdim;
}

// ===================== launch ===============================================
extern "C" void kernel_launch(void* const* d_in, const int* in_sizes, int n_in,
                              void* d_out, int out_size){
    const int*   x      = (const int*)  d_in[0];
    const int*   target = (const int*)  d_in[1];
    const float* wte    = (const float*)d_in[2];
    const float* wpe    = (const float*)d_in[3];
    const float* ln1_w  = (const float*)d_in[4];
    const float* ln1_b  = (const float*)d_in[5];
    const float* attn_w = (const float*)d_in[6];
    const float* attn_b = (const float*)d_in[7];
    const float* ln2_w  = (const float*)d_in[8];
    const float* ln2_b  = (const float*)d_in[9];
    const float* ff1_w  = (const float*)d_in[10];
    const float* ff1_b  = (const float*)d_in[11];
    const float* ff2_w  = (const float*)d_in[12];
    const float* ff2_b  = (const float*)d_in[13];
    const float* lm_w   = (const float*)d_in[14];

    float* out = (float*)d_out;
    bool has_loss = ((long long)out_size == (long long)Mdim * Vdim + 1);
    float* logits = has_loss ? out + 1 : out;

    cudaFuncSetAttribute(gemm_1t_k, cudaFuncAttributeMaxDynamicSharedMemorySize, G1_SMEM);
    cudaFuncSetAttribute(flash_k,   cudaFuncAttributeMaxDynamicSharedMemorySize, FA_SMEM);

    float* ph;
    cudaGetSymbolAddress((void**)&ph, g_h);
    __half *wqk,*wf1,*wf2,*wlm,*xn,*ffh,*ah,*qv;
    float *ppm,*pps;
    cudaGetSymbolAddress((void**)&wqk, g_wqkv_h);
    cudaGetSymbolAddress((void**)&wf1, g_wff1_h);
    cudaGetSymbolAddress((void**)&wf2, g_wff2_h);
    cudaGetSymbolAddress((void**)&wlm, g_wlm_h);
    cudaGetSymbolAddress((void**)&xn,  g_xn);
    cudaGetSymbolAddress((void**)&ffh, g_ffh);
    cudaGetSymbolAddress((void**)&ah,  g_ah);
    cudaGetSymbolAddress((void**)&qv,  g_qkv);
    cudaGetSymbolAddress((void**)&ppm, g_pmax);
    cudaGetSymbolAddress((void**)&pps, g_psum);

    cvt_h_k<<<2048, 256>>>(attn_w, wqk, (long)Ldim*C3*Cdim);
    cvt_h_k<<<2048, 256>>>(ff1_w,  wf1, (long)Ldim*Fdim*Cdim);
    cvt_h_k<<<2048, 256>>>(ff2_w,  wf2, (long)Ldim*Cdim*Fdim);
    cvt_h_k<<<4096, 256>>>(lm_w,   wlm, (long)Vdim*Cdim);

    embed_k<<<(Mdim*Cdim + 255)/256, 256>>>(x, wte, wpe);

    for (int l = 0; l < Ldim; l++){
        ln_k<<<Mdim/8, 256>>>(ph, ln1_w + (size_t)l*Cdim, ln1_b + (size_t)l*Cdim, xn);

        gemm_1t_k<<<dim3(Mdim/128, C3/128, 1), 256, G1_SMEM>>>(
            xn, wqk + (size_t)l*C3*Cdim, attn_b + (size_t)l*C3,
            nullptr, qv, nullptr, nullptr, C3, Cdim, 3);

        // split-KV x2: balanced flash (max 8 stages/CTA instead of 16)
        flash_k<<<dim3(Tdim/128, Bdim*Hdim, 2), 256, FA_SMEM>>>(qv);

        // combine partials + residual + LN2 in one pass
        ln_att_k<<<Mdim/8, 256>>>(ph, ln2_w + (size_t)l*Cdim, ln2_b + (size_t)l*Cdim, xn);

        gemm_1t_k<<<dim3(Mdim/128, Fdim/128, 1), 256, G1_SMEM>>>(
            xn, wf1 + (size_t)l*Fdim*Cdim, ff1_b + (size_t)l*Fdim,
            nullptr, ffh, nullptr, nullptr, Fdim, Cdim, 1);

        gemm_1t_k<<<dim3(Mdim/128, Cdim/128, 3), 256, G1_SMEM>>>(
            ffh, wf2 + (size_t)l*Cdim*Fdim, ff2_b + (size_t)l*Cdim,
            ph, nullptr, nullptr, nullptr, Cdim, Fdim, 2);
    }

    cvt_h_k<<<2048, 256>>>(ph, ah, (long)Mdim*Cdim);

    gemm_1t_k<<<dim3(Mdim/128, NPB, 1), 256, G1_SMEM>>>(
        ah, wlm, nullptr, logits, nullptr, ppm, pps, Vdim, Cdim, 0);

    loss_row2_k<<<Mdim, 256>>>(logits, target);
    if (has_loss)
        loss_reduce_k<<<1, 256>>>(out);
}

// round 16
// speedup vs baseline: 1.7492x; 1.0011x over previous
#include <cuda_runtime.h>
#include <cuda_bf16.h>
#include <cuda_fp16.h>
#include <cstdint>
#include <math.h>

#define Bdim 2
#define Tdim 2048
#define Cdim 768
#define Hdim 12
#define Ddim 64
#define Ldim 6
#define Vdim 50257
#define Mdim (Bdim*Tdim)      /* 4096 */
#define C3   (3*Cdim)         /* 2304 */
#define Fdim (4*Cdim)         /* 3072 */
#define NPB  393              /* (Vdim+127)/128 logits col-blocks */
#define PHB  ((long)Bdim*Hdim*Tdim)   /* 49152 partial rows per z */

// ===================== device scratch (no allocations) ======================
__device__ float g_h  [Mdim*Cdim];
__device__ float g_rowloss[Mdim];
__device__ float g_pmax[(size_t)Mdim*NPB];
__device__ float g_psum[(size_t)Mdim*NPB];

__device__ __half g_po[2*PHB*Ddim];      // normalized partial attn out
__device__ float  g_pm[2*PHB];           // partial max (log2 domain)
__device__ float  g_pl[2*PHB];           // partial sum

__device__ __half g_wqkv_h[Ldim*C3*Cdim];
__device__ __half g_wff1_h[Ldim*Fdim*Cdim];
__device__ __half g_wff2_h[Ldim*Cdim*Fdim];
__device__ __half g_wlm_h[(size_t)Vdim*Cdim];
__device__ __half g_xn [Mdim*Cdim];
__device__ __half g_ffh[Mdim*Fdim];
__device__ __half g_ah [Mdim*Cdim];
__device__ __half g_qkv[Mdim*C3];

// ===================== asm helpers (baseline sm_80+ ISA) ====================
__device__ __forceinline__ uint32_t smem_to_u32(const void* p) {
    uint32_t a;
    asm("{ .reg .u64 t; cvta.to.shared.u64 t, %1; cvt.u32.u64 %0, t; }" : "=r"(a) : "l"(p));
    return a;
}
__device__ __forceinline__ void cp_async16(uint32_t dst, const void* src){
    asm volatile("cp.async.cg.shared.global [%0], [%1], 16;" :: "r"(dst), "l"(src));
}
#define CP_COMMIT() asm volatile("cp.async.commit_group;" ::: "memory")
#define CP_WAIT0()  asm volatile("cp.async.wait_group 0;" ::: "memory")

__device__ __forceinline__ void ldsm_x4(uint32_t* r, uint32_t addr){
    asm volatile("ldmatrix.sync.aligned.m8n8.x4.shared.b16 {%0,%1,%2,%3}, [%4];"
        : "=r"(r[0]), "=r"(r[1]), "=r"(r[2]), "=r"(r[3]) : "r"(addr));
}
__device__ __forceinline__ void ldsm_x4_t(uint32_t* r, uint32_t addr){
    asm volatile("ldmatrix.sync.aligned.m8n8.x4.trans.shared.b16 {%0,%1,%2,%3}, [%4];"
        : "=r"(r[0]), "=r"(r[1]), "=r"(r[2]), "=r"(r[3]) : "r"(addr));
}
__device__ __forceinline__ void mma_f16(float* d, const uint32_t* a,
                                        uint32_t b0, uint32_t b1){
    asm volatile("mma.sync.aligned.m16n8k16.row.col.f32.f16.f16.f32 "
        "{%0,%1,%2,%3}, {%4,%5,%6,%7}, {%8,%9}, {%0,%1,%2,%3};"
        : "+f"(d[0]), "+f"(d[1]), "+f"(d[2]), "+f"(d[3])
        : "r"(a[0]), "r"(a[1]), "r"(a[2]), "r"(a[3]), "r"(b0), "r"(b1));
}
__device__ __forceinline__ uint32_t pack_half2(float lo, float hi){
    uint32_t r;
    asm("cvt.rn.f16x2.f32 %0, %1, %2;" : "=r"(r) : "f"(hi), "f"(lo));
    return r;
}

// ===================== reductions ===========================================
__device__ __forceinline__ float blockReduceMax(float v){
    __shared__ float sh[8];
    int lid = threadIdx.x & 31, wid = threadIdx.x >> 5;
    #pragma unroll
    for (int o = 16; o > 0; o >>= 1) v = fmaxf(v, __shfl_xor_sync(0xffffffffu, v, o));
    if (lid == 0) sh[wid] = v;
    __syncthreads();
    v = sh[lid & 7];
    #pragma unroll
    for (int o = 4; o > 0; o >>= 1) v = fmaxf(v, __shfl_xor_sync(0xffffffffu, v, o));
    __syncthreads();
    return v;
}
__device__ __forceinline__ float blockReduceSum(float v){
    __shared__ float sh[8];
    int lid = threadIdx.x & 31, wid = threadIdx.x >> 5;
    #pragma unroll
    for (int o = 16; o > 0; o >>= 1) v += __shfl_xor_sync(0xffffffffu, v, o);
    if (lid == 0) sh[wid] = v;
    __syncthreads();
    v = sh[lid & 7];
    #pragma unroll
    for (int o = 4; o > 0; o >>= 1) v += __shfl_xor_sync(0xffffffffu, v, o);
    __syncthreads();
    return v;
}

// ===================== small kernels ========================================
__global__ void embed_k(const int* __restrict__ x,
                        const float* __restrict__ wte,
                        const float* __restrict__ wpe){
    int i = blockIdx.x * blockDim.x + threadIdx.x;
    if (i >= Mdim * Cdim) return;
    int c  = i % Cdim;
    int bt = i / Cdim;
    int t  = bt % Tdim;
    g_h[i] = wte[(size_t)x[bt] * Cdim + c] + wpe[(size_t)t * Cdim + c];
}

__global__ void cvt_h_k(const float* __restrict__ in, __half* __restrict__ o, long n){
    long stride = (long)gridDim.x * blockDim.x * 4;
    for (long i = ((long)blockIdx.x * blockDim.x + threadIdx.x) * 4; i < n; i += stride){
        float4 v = *(const float4*)(in + i);
        uint2 w;
        w.x = pack_half2(v.x, v.y);
        w.y = pack_half2(v.z, v.w);
        *(uint2*)(o + i) = w;
    }
}

// warp-per-2-rows layernorm -> single fp16 output (pre-attention LN)
__global__ void ln_k(const float* __restrict__ in,
                     const float* __restrict__ w,
                     const float* __restrict__ b,
                     __half* __restrict__ oh){
    int warp = threadIdx.x >> 5, lane = threadIdx.x & 31;
    int row0 = blockIdx.x * 16 + warp * 2;
    float4 v[2][6];
    float s[2] = {0.f, 0.f}, ss[2] = {0.f, 0.f};
    #pragma unroll
    for (int r = 0; r < 2; r++){
        const float* xp = in + (size_t)(row0 + r) * Cdim;
        #pragma unroll
        for (int k = 0; k < 6; k++)
            v[r][k] = *(const float4*)(xp + lane*4 + k*128);
    }
    #pragma unroll
    for (int r = 0; r < 2; r++)
        #pragma unroll
        for (int k = 0; k < 6; k++){
            s[r]  += v[r][k].x + v[r][k].y + v[r][k].z + v[r][k].w;
            ss[r] += v[r][k].x*v[r][k].x + v[r][k].y*v[r][k].y
                   + v[r][k].z*v[r][k].z + v[r][k].w*v[r][k].w;
        }
    #pragma unroll
    for (int o = 16; o > 0; o >>= 1){
        #pragma unroll
        for (int r = 0; r < 2; r++){
            s[r]  += __shfl_xor_sync(0xffffffffu, s[r],  o);
            ss[r] += __shfl_xor_sync(0xffffffffu, ss[r], o);
        }
    }
    #pragma unroll
    for (int r = 0; r < 2; r++){
        float mean = s[r] * (1.f / Cdim);
        float var  = ss[r] * (1.f / Cdim) - mean * mean;
        float rstd = rsqrtf(var + 1e-5f);
        #pragma unroll
        for (int k = 0; k < 6; k++){
            int c = lane*4 + k*128;
            float y0 = (v[r][k].x - mean) * rstd * w[c]   + b[c];
            float y1 = (v[r][k].y - mean) * rstd * w[c+1] + b[c+1];
            float y2 = (v[r][k].z - mean) * rstd * w[c+2] + b[c+2];
            float y3 = (v[r][k].w - mean) * rstd * w[c+3] + b[c+3];
            uint2 hw;
            hw.x = pack_half2(y0, y1);
            hw.y = pack_half2(y2, y3);
            *(uint2*)(oh + (size_t)(row0 + r)*Cdim + c) = hw;
        }
    }
}

// combine flash partials + residual add + layernorm (post-attention)
__global__ void ln_att_k(float* __restrict__ hbuf,
                         const float* __restrict__ w,
                         const float* __restrict__ b,
                         __half* __restrict__ oh){
    int warp = threadIdx.x >> 5, lane = threadIdx.x & 31;
    int row = blockIdx.x * 8 + warp;          // 0..4095
    int bq = row >> 11;                        // batch
    int t  = row & 2047;
    float* xp = hbuf + (size_t)row * Cdim;
    float4 v[6];
    float s = 0.f, ss = 0.f;
    #pragma unroll
    for (int k = 0; k < 6; k++){
        int c = lane*4 + k*128;
        v[k] = *(const float4*)(xp + c);
        int head = c >> 6;
        long idx = ((long)(bq*Hdim + head) * Tdim + t);
        float m0 = g_pm[idx],       l0 = g_pl[idx];
        float m1 = g_pm[PHB + idx], l1 = g_pl[PHB + idx];
        float M  = fmaxf(m0, m1);
        float w0 = exp2f(m0 - M) * l0;
        float w1 = exp2f(m1 - M) * l1;
        float inv = 1.f / (w0 + w1);
        int d = c & 63;
        uint2 o0w = *(const uint2*)(g_po + idx*64 + d);
        uint2 o1w = *(const uint2*)(g_po + (PHB + idx)*64 + d);
        __half2 a0 = *(__half2*)&o0w.x, a1 = *(__half2*)&o0w.y;
        __half2 c0 = *(__half2*)&o1w.x, c1 = *(__half2*)&o1w.y;
        float2 f0 = __half22float2(a0), f1 = __half22float2(a1);
        float2 g0 = __half22float2(c0), g1 = __half22float2(c1);
        v[k].x += (f0.x*w0 + g0.x*w1) * inv;
        v[k].y += (f0.y*w0 + g0.y*w1) * inv;
        v[k].z += (f1.x*w0 + g1.x*w1) * inv;
        v[k].w += (f1.y*w0 + g1.y*w1) * inv;
        s  += v[k].x + v[k].y + v[k].z + v[k].w;
        ss += v[k].x*v[k].x + v[k].y*v[k].y + v[k].z*v[k].z + v[k].w*v[k].w;
    }
    #pragma unroll
    for (int o = 16; o > 0; o >>= 1){
        s  += __shfl_xor_sync(0xffffffffu, s,  o);
        ss += __shfl_xor_sync(0xffffffffu, ss, o);
    }
    float mean = s * (1.f / Cdim);
    float var  = ss * (1.f / Cdim) - mean * mean;
    float rstd = rsqrtf(var + 1e-5f);
    #pragma unroll
    for (int k = 0; k < 6; k++){
        int c = lane*4 + k*128;
        *(float4*)(xp + c) = v[k];             // residual write-back
        float y0 = (v[k].x - mean) * rstd * w[c]   + b[c];
        float y1 = (v[k].y - mean) * rstd * w[c+1] + b[c+1];
        float y2 = (v[k].z - mean) * rstd * w[c+2] + b[c+2];
        float y3 = (v[k].w - mean) * rstd * w[c+3] + b[c+3];
        uint2 hw;
        hw.x = pack_half2(y0, y1);
        hw.y = pack_half2(y2, y3);
        *(uint2*)(oh + (size_t)row*Cdim + c) = hw;
    }
}

// ===================== unified fp16 1-term GEMM (mma.sync) ==================
// C[M,N] = A[M,K] @ B[N,K]^T. K-stage 64 (row stride 144B). Split-K via gridDim.z.
// modes: 0: out_f = acc (bounds-checked) + LSE partials (lm_head)
//        1: out_h = relu(acc+bias) fp16
//        2: atomicAdd(out_f, acc [+bias if z==0])
//        3: out_h = acc+bias fp16
#define G1_MAT  18432            /* 128 rows * 144 bytes */
#define G1_STG  (2*G1_MAT)
#define G1_SMEM (2*G1_STG)       /* 73728 */

__global__ __launch_bounds__(256, 2) void gemm_1t_k(
        const __half* __restrict__ A, const __half* __restrict__ Bm,
        const float* __restrict__ bias,
        float* __restrict__ out_f, __half* __restrict__ out_h,
        float* __restrict__ pmax, float* __restrict__ psum,
        int N, int K, int mode){
    extern __shared__ char smem[];
    uint32_t sbase = smem_to_u32(smem);
    int tid = threadIdx.x, wid = tid >> 5, lane = tid & 31;
    int warpRow = wid >> 2, warpCol = wid & 3;

    long row0 = (long)blockIdx.x * 128;
    long n0   = (long)blockIdx.y * 128;
    int kspan = K / (int)gridDim.z;
    long kbase = (long)blockIdx.z * kspan;
    int nIter = kspan >> 6;

    float acc[4][4][4];
    #pragma unroll
    for (int i = 0; i < 4; i++)
        #pragma unroll
        for (int j = 0; j < 4; j++)
            #pragma unroll
            for (int q = 0; q < 4; q++) acc[i][j][q] = 0.f;

    auto issue = [&](int it){
        if (it >= nIter) return;
        long k0 = kbase + ((long)it << 6);
        uint32_t stg = sbase + (uint32_t)(it & 1) * G1_STG;
        #pragma unroll
        for (int j = 0; j < 8; j++){
            int c   = tid + j * 256;           // 0..2047 (16B chunks)
            int mat = c >> 10;                 // 0:A 1:B
            int rem = c & 1023;
            int row = rem >> 3;                // 0..127
            int h8  = (rem & 7) << 3;          // half index 0..56
            const __half* src;
            if (mat == 0){
                src = A + (row0 + row) * (long)K + k0 + h8;
            } else {
                long br = n0 + row; if (br >= N) br = 0;
                src = Bm + br * (long)K + k0 + h8;
            }
            uint32_t dst = stg + (uint32_t)(mat * G1_MAT + row * 144 + h8 * 2);
            cp_async16(dst, src);
        }
        CP_COMMIT();
    };

    issue(0);
    for (int it = 0; it < nIter; it++){
        CP_WAIT0();
        __syncthreads();        // data(it) visible + all warps done with compute(it-1)
        issue(it + 1);

        uint32_t stg = sbase + (uint32_t)(it & 1) * G1_STG;
        uint32_t aS = stg;
        uint32_t bS = stg + G1_MAT;
        uint32_t rsel = (uint32_t)(lane & 15) * 144 + (uint32_t)(lane >> 4) * 16;

        #pragma unroll
        for (int ks = 0; ks < 64; ks += 16){
            uint32_t bf[2][4];
            #pragma unroll
            for (int nj = 0; nj < 2; nj++){
                uint32_t off = (uint32_t)((warpCol*32 + nj*16) * 144 + ks*2) + rsel;
                ldsm_x4(bf[nj], bS + off);
            }
            #pragma unroll
            for (int mi = 0; mi < 4; mi++){
                uint32_t af[4];
                uint32_t off = (uint32_t)((warpRow*64 + mi*16) * 144 + ks*2) + rsel;
                ldsm_x4(af, aS + off);
                #pragma unroll
                for (int ni = 0; ni < 4; ni++){
                    int nj = ni >> 1, w = ni & 1;
                    mma_f16(acc[mi][ni], af, bf[nj][w], bf[nj][w+2]);
                }
            }
        }
    }

    if (mode == 0){
        // scalar stores: logits base pointer may be only 4B-aligned (out+1)
        #pragma unroll
        for (int mi = 0; mi < 4; mi++){
            long r0 = row0 + warpRow*64 + mi*16 + (lane >> 2);
            #pragma unroll
            for (int ni = 0; ni < 4; ni++){
                long c0 = n0 + warpCol*32 + ni*8 + (lane & 3)*2;
                #pragma unroll
                for (int half = 0; half < 2; half++){
                    long r = r0 + half*8;
                    #pragma unroll
                    for (int e = 0; e < 2; e++){
                        long n = c0 + e;
                        if (n < N)
                            out_f[r * (long)N + n] = acc[mi][ni][half*2 + e];
                    }
                }
            }
        }
        // fused LSE partials for this 128x128 block
        __syncthreads();
        float* pm_s = (float*)smem;            // [128][4]
        float* ps_s = (float*)smem + 512;      // [128][4]
        #pragma unroll
        for (int mi = 0; mi < 4; mi++){
            #pragma unroll
            for (int half = 0; half < 2; half++){
                int lr = warpRow*64 + mi*16 + (lane >> 2) + half*8;
                float vv[8];
                float lm = -1e30f;
                #pragma unroll
                for (int ni = 0; ni < 4; ni++)
                    #pragma unroll
                    for (int e = 0; e < 2; e++){
                        long n = n0 + warpCol*32 + ni*8 + (lane & 3)*2 + e;
                        float t = (n < N) ? acc[mi][ni][half*2 + e] : -1e30f;
                        vv[ni*2 + e] = t;
                        lm = fmaxf(lm, t);
                    }
                lm = fmaxf(lm, __shfl_xor_sync(0xffffffffu, lm, 1));
                lm = fmaxf(lm, __shfl_xor_sync(0xffffffffu, lm, 2));
                float ls = 0.f;
                #pragma unroll
                for (int q = 0; q < 8; q++) ls += __expf(vv[q] - lm);
                ls += __shfl_xor_sync(0xffffffffu, ls, 1);
                ls += __shfl_xor_sync(0xffffffffu, ls, 2);
                if ((lane & 3) == 0){
                    pm_s[lr*4 + warpCol] = lm;
                    ps_s[lr*4 + warpCol] = ls;
                }
            }
        }
        __syncthreads();
        if (tid < 128){
            float m0 = pm_s[tid*4], m1 = pm_s[tid*4+1], m2 = pm_s[tid*4+2], m3 = pm_s[tid*4+3];
            float M = fmaxf(fmaxf(m0, m1), fmaxf(m2, m3));
            float S = ps_s[tid*4]  *__expf(m0 - M) + ps_s[tid*4+1]*__expf(m1 - M)
                    + ps_s[tid*4+2]*__expf(m2 - M) + ps_s[tid*4+3]*__expf(m3 - M);
            long r = row0 + tid;
            pmax[r*NPB + blockIdx.y] = M;
            psum[r*NPB + blockIdx.y] = S;
        }
        return;
    }

    bool addBias = (blockIdx.z == 0);
    #pragma unroll
    for (int mi = 0; mi < 4; mi++){
        long r0 = row0 + warpRow*64 + mi*16 + (lane >> 2);
        #pragma unroll
        for (int ni = 0; ni < 4; ni++){
            long c0 = n0 + warpCol*32 + ni*8 + (lane & 3)*2;
            float b0 = addBias ? bias[c0]     : 0.f;
            float b1 = addBias ? bias[c0 + 1] : 0.f;
            #pragma unroll
            for (int half = 0; half < 2; half++){
                long r  = r0 + half*8;
                long oi = r * (long)N + c0;
                float v0 = acc[mi][ni][half*2]     + b0;
                float v1 = acc[mi][ni][half*2 + 1] + b1;
                if (mode == 2){
                    atomicAdd(out_f + oi,     v0);
                    atomicAdd(out_f + oi + 1, v1);
                } else {
                    if (mode == 1){
                        v0 = fmaxf(v0, 0.f);
                        v1 = fmaxf(v1, 0.f);
                    }
                    *(uint32_t*)(out_h + oi) = pack_half2(v0, v1);
                }
            }
        }
    }
}

// ===================== flash attention (split-KV x2, partial outputs) =======
#define FA_QB    (128*144)               /* 18432 */
#define FA_KVMAT (128*144)               /* 18432 per matrix per stage */
#define FA_STGB  (2*FA_KVMAT)            /* 36864 */
#define FA_SMEM  (FA_QB + 2*FA_STGB)     /* 92160 */

__global__ __launch_bounds__(256, 2) void flash_k(const __half* __restrict__ qkv){
    extern __shared__ char smem[];
    uint32_t sb = smem_to_u32(smem);
    uint32_t Qs = sb;
    uint32_t kvb = sb + FA_QB;

    int tid = threadIdx.x, wid = tid >> 5, lane = tid & 31;
    int g = lane >> 2, tq = lane & 3;
    int qb = (int)gridDim.x - 1 - (int)blockIdx.x;
    int bh = blockIdx.y; int bq = bh / Hdim, head = bh % Hdim;
    int z = blockIdx.z;
    int q0 = qb * 128;
    long rowbase = (long)bq * Tdim;
    int t0w = q0 + wid*16;

    int nkv = qb + 1;
    int half_n = (nkv + 1) >> 1;
    int js = z ? half_n : 0;
    int je = z ? nkv : half_n;
    int cnt = je - js;
    long pbase = (long)z * PHB + (long)bh * Tdim;

    if (cnt <= 0){
        #pragma unroll
        for (int r = 0; r < 2; r++){
            long t = (long)t0w + g + r*8;
            long pr = pbase + t;
            if (tq == 0){ g_pm[pr] = -1e30f; g_pl[pr] = 0.f; }
            #pragma unroll
            for (int dt = 0; dt < 8; dt++)
                *(uint32_t*)(g_po + pr*64 + dt*8 + tq*2) = 0u;
        }
        return;
    }

    #pragma unroll
    for (int j = 0; j < 4; j++){
        int id = tid + j*256;                 // 0..1023
        int row = id >> 3, c8 = (id & 7) << 3;
        const __half* src = qkv + (rowbase + q0 + row)*(long)C3 + head*Ddim + c8;
        cp_async16(Qs + (uint32_t)(row*144 + c8*2), src);
    }

    auto issue = [&](int it){
        if (it >= cnt) return;
        int s0 = (js + it) * 128;
        uint32_t stg = kvb + (uint32_t)(it & 1) * FA_STGB;
        #pragma unroll
        for (int jj = 0; jj < 8; jj++){
            int id = tid + jj*256;            // 0..2047
            int mat = id >> 10, rem = id & 1023;  // 0:K 1:V
            int row = rem >> 3, c8 = (rem & 7) << 3;
            int coff = mat ? 2*Cdim : Cdim;
            const __half* src = qkv
                + (rowbase + s0 + row)*(long)C3 + coff + head*Ddim + c8;
            cp_async16(stg + (uint32_t)(mat*FA_KVMAT + row*144 + c8*2), src);
        }
        CP_COMMIT();
    };

    // log2-domain softmax: scores scaled by 0.125*log2(e)
    const float SC2 = 0.18033688f;
    float mrow[2] = {-1e30f, -1e30f};
    float lrow[2] = {0.f, 0.f};
    float oacc[8][4];
    #pragma unroll
    for (int i = 0; i < 8; i++)
        #pragma unroll
        for (int e = 0; e < 4; e++) oacc[i][e] = 0.f;

    uint32_t rsel16 = (uint32_t)(lane & 15)*144 + (uint32_t)(lane >> 4)*16;
    int vtsel = lane >> 3, vrt = lane & 7;
    uint32_t vrow_off = ((vtsel >> 1) ? 8u : 0u) + (uint32_t)vrt;
    uint32_t vcol_off = (vtsel & 1) ? 16u : 0u;

    issue(0);
    for (int it = 0; it < cnt; it++){
        CP_WAIT0();
        __syncthreads();
        issue(it + 1);

        uint32_t stg = kvb + (uint32_t)(it & 1) * FA_STGB;
        #pragma unroll
        for (int sub = 0; sub < 2; sub++){
            int s0 = (js + it) * 128 + sub * 64;
            if (s0 > t0w + 15) continue;
            uint32_t Kh = stg + (uint32_t)sub * (64*144);
            uint32_t Vh = stg + FA_KVMAT + (uint32_t)sub * (64*144);

            float S[8][4];
            #pragma unroll
            for (int i = 0; i < 8; i++)
                #pragma unroll
                for (int e = 0; e < 4; e++) S[i][e] = 0.f;

            #pragma unroll
            for (int dc = 0; dc < 4; dc++){
                uint32_t aoff = (uint32_t)(wid*16)*144 + (uint32_t)dc*32 + rsel16;
                uint32_t ah[4];
                ldsm_x4(ah, Qs + aoff);
                #pragma unroll
                for (int ng = 0; ng < 4; ng++){
                    uint32_t boff = (uint32_t)(ng*16)*144 + (uint32_t)dc*32 + rsel16;
                    uint32_t kh[4];
                    ldsm_x4(kh, Kh + boff);
                    #pragma unroll
                    for (int w = 0; w < 2; w++)
                        mma_f16(S[ng*2+w], ah, kh[w], kh[w+2]);
                }
            }

            bool needMask = (s0 + 63 > t0w);
            #pragma unroll
            for (int ns = 0; ns < 8; ns++)
                #pragma unroll
                for (int e = 0; e < 4; e++){
                    float v = S[ns][e] * SC2;
                    if (needMask){
                        int t = t0w + g + (e >> 1)*8;
                        int s = s0 + ns*8 + tq*2 + (e & 1);
                        if (s > t) v = -1e30f;
                    }
                    S[ns][e] = v;
                }

            #pragma unroll
            for (int r = 0; r < 2; r++){
                float mx = -1e30f;
                #pragma unroll
                for (int ns = 0; ns < 8; ns++)
                    mx = fmaxf(mx, fmaxf(S[ns][r*2], S[ns][r*2+1]));
                mx = fmaxf(mx, __shfl_xor_sync(0xffffffffu, mx, 1));
                mx = fmaxf(mx, __shfl_xor_sync(0xffffffffu, mx, 2));
                float mnew = fmaxf(mrow[r], mx);
                float corr = exp2f(mrow[r] - mnew);
                mrow[r] = mnew;
                float lsum = 0.f;
                #pragma unroll
                for (int ns = 0; ns < 8; ns++){
                    float p0 = exp2f(S[ns][r*2]   - mnew);
                    float p1 = exp2f(S[ns][r*2+1] - mnew);
                    S[ns][r*2] = p0; S[ns][r*2+1] = p1;
                    lsum += p0 + p1;
                }
                lsum += __shfl_xor_sync(0xffffffffu, lsum, 1);
                lsum += __shfl_xor_sync(0xffffffffu, lsum, 2);
                lrow[r] = lrow[r]*corr + lsum;
                #pragma unroll
                for (int dt = 0; dt < 8; dt++){
                    oacc[dt][r*2]   *= corr;
                    oacc[dt][r*2+1] *= corr;
                }
            }

            #pragma unroll
            for (int sc = 0; sc < 4; sc++){
                uint32_t ph[4];
                #pragma unroll
                for (int half = 0; half < 2; half++){
                    int ns = sc*2 + half;
                    ph[half*2+0] = pack_half2(S[ns][0], S[ns][1]);
                    ph[half*2+1] = pack_half2(S[ns][2], S[ns][3]);
                }
                uint32_t vbase = (uint32_t)((sc*16 + vrow_off)*144) + vcol_off;
                #pragma unroll
                for (int dg = 0; dg < 4; dg++){
                    uint32_t vh_[4];
                    ldsm_x4_t(vh_, Vh + vbase + (uint32_t)dg*32);
                    #pragma unroll
                    for (int w = 0; w < 2; w++)
                        mma_f16(oacc[dg*2 + w], ph, vh_[w], vh_[w+2]);
                }
            }
        }
    }

    // write partials: normalized o (fp16), m (log2 domain), l
    #pragma unroll
    for (int r = 0; r < 2; r++){
        float inv = 1.f / lrow[r];
        long t = (long)t0w + g + r*8;
        long pr = pbase + t;
        if (tq == 0){ g_pm[pr] = mrow[r]; g_pl[pr] = lrow[r]; }
        #pragma unroll
        for (int dt = 0; dt < 8; dt++)
            *(uint32_t*)(g_po + pr*64 + dt*8 + tq*2) =
                pack_half2(oacc[dt][r*2] * inv, oacc[dt][r*2+1] * inv);
    }
}

// ===================== loss from LSE partials ================================
__global__ void loss_row2_k(const float* __restrict__ logits,
                            const int* __restrict__ target){
    int row = blockIdx.x, tid = threadIdx.x;
    const float* pm = g_pmax + (size_t)row * NPB;
    const float* ps = g_psum + (size_t)row * NPB;
    float m = -1e30f, s = 0.f;
    for (int i = tid; i < NPB; i += 256){
        float im = pm[i], is = ps[i];
        if (im > m){
            s = s * __expf(m - im) + is;
            m = im;
        } else {
            s += is * __expf(im - m);
        }
    }
    float mg = blockReduceMax(m);
    s *= __expf(m - mg);
    float tot = blockReduceSum(s);
    if (tid == 0){
        float lse = logf(tot) + mg;
        g_rowloss[row] = lse - logits[(size_t)row * Vdim + target[row]];
    }
}
__global__ void loss_reduce_k(float* out){
    float s = 0.f;
    for (int i = threadIdx.x; i < Mdim; i += 256) s += g_rowloss[i];
    s = blockReduceSum(s);
    if (threadIdx.x == 0) out[0] = s / (float)Mdim;
}

// ===================== launch ===============================================
extern "C" void kernel_launch(void* const* d_in, const int* in_sizes, int n_in,
                              void* d_out, int out_size){
    const int*   x      = (const int*)  d_in[0];
    const int*   target = (const int*)  d_in[1];
    const float* wte    = (const float*)d_in[2];
    const float* wpe    = (const float*)d_in[3];
    const float* ln1_w  = (const float*)d_in[4];
    const float* ln1_b  = (const float*)d_in[5];
    const float* attn_w = (const float*)d_in[6];
    const float* attn_b = (const float*)d_in[7];
    const float* ln2_w  = (const float*)d_in[8];
    const float* ln2_b  = (const float*)d_in[9];
    const float* ff1_w  = (const float*)d_in[10];
    const float* ff1_b  = (const float*)d_in[11];
    const float* ff2_w  = (const float*)d_in[12];
    const float* ff2_b  = (const float*)d_in[13];
    const float* lm_w   = (const float*)d_in[14];

    float* out = (float*)d_out;
    bool has_loss = ((long long)out_size == (long long)Mdim * Vdim + 1);
    float* logits = has_loss ? out + 1 : out;

    cudaFuncSetAttribute(gemm_1t_k, cudaFuncAttributeMaxDynamicSharedMemorySize, G1_SMEM);
    cudaFuncSetAttribute(flash_k,   cudaFuncAttributeMaxDynamicSharedMemorySize, FA_SMEM);

    float* ph;
    cudaGetSymbolAddress((void**)&ph, g_h);
    __half *wqk,*wf1,*wf2,*wlm,*xn,*ffh,*ah,*qv;
    float *ppm,*pps;
    cudaGetSymbolAddress((void**)&wqk, g_wqkv_h);
    cudaGetSymbolAddress((void**)&wf1, g_wff1_h);
    cudaGetSymbolAddress((void**)&wf2, g_wff2_h);
    cudaGetSymbolAddress((void**)&wlm, g_wlm_h);
    cudaGetSymbolAddress((void**)&xn,  g_xn);
    cudaGetSymbolAddress((void**)&ffh, g_ffh);
    cudaGetSymbolAddress((void**)&ah,  g_ah);
    cudaGetSymbolAddress((void**)&qv,  g_qkv);
    cudaGetSymbolAddress((void**)&ppm, g_pmax);
    cudaGetSymbolAddress((void**)&pps, g_psum);

    cvt_h_k<<<2048, 256>>>(attn_w, wqk, (long)Ldim*C3*Cdim);
    cvt_h_k<<<2048, 256>>>(ff1_w,  wf1, (long)Ldim*Fdim*Cdim);
    cvt_h_k<<<2048, 256>>>(ff2_w,  wf2, (long)Ldim*Cdim*Fdim);
    cvt_h_k<<<4096, 256>>>(lm_w,   wlm, (long)Vdim*Cdim);

    embed_k<<<(Mdim*Cdim + 255)/256, 256>>>(x, wte, wpe);

    for (int l = 0; l < Ldim; l++){
        ln_k<<<Mdim/16, 256>>>(ph, ln1_w + (size_t)l*Cdim, ln1_b + (size_t)l*Cdim, xn);

        gemm_1t_k<<<dim3(Mdim/128, C3/128, 1), 256, G1_SMEM>>>(
            xn, wqk + (size_t)l*C3*Cdim, attn_b + (size_t)l*C3,
            nullptr, qv, nullptr, nullptr, C3, Cdim, 3);

        flash_k<<<dim3(Tdim/128, Bdim*Hdim, 2), 256, FA_SMEM>>>(qv);

        ln_att_k<<<Mdim/8, 256>>>(ph, ln2_w + (size_t)l*Cdim, ln2_b + (size_t)l*Cdim, xn);

        gemm_1t_k<<<dim3(Mdim/128, Fdim/128, 1), 256, G1_SMEM>>>(
            xn, wf1 + (size_t)l*Fdim*Cdim, ff1_b + (size_t)l*Fdim,
            nullptr, ffh, nullptr, nullptr, Fdim, Cdim, 1);

        gemm_1t_k<<<dim3(Mdim/128, Cdim/128, 3), 256, G1_SMEM>>>(
            ffh, wf2 + (size_t)l*Cdim*Fdim, ff2_b + (size_t)l*Cdim,
            ph, nullptr, nullptr, nullptr, Cdim, Fdim, 2);
    }

    cvt_h_k<<<2048, 256>>>(ph, ah, (long)Mdim*Cdim);

    gemm_1t_k<<<dim3(Mdim/128, NPB, 1), 256, G1_SMEM>>>(
        ah, wlm, nullptr, logits, nullptr, ppm, pps, Vdim, Cdim, 0);

    loss_row2_k<<<Mdim, 256>>>(logits, target);
    if (has_loss)
        loss_reduce_k<<<1, 256>>>(out);
}

// round 17
// speedup vs baseline: 1.7504x; 1.0007x over previous
#include <cuda_runtime.h>
#include <cuda_bf16.h>
#include <cuda_fp16.h>
#include <cstdint>
#include <math.h>

#define Bdim 2
#define Tdim 2048
#define Cdim 768
#define Hdim 12
#define Ddim 64
#define Ldim 6
#define Vdim 50257
#define Mdim (Bdim*Tdim)      /* 4096 */
#define C3   (3*Cdim)         /* 2304 */
#define Fdim (4*Cdim)         /* 3072 */
#define NPB  393              /* (Vdim+127)/128 logits col-blocks */
#define PHB  ((long)Bdim*Hdim*Tdim)   /* 49152 partial rows per z */

// ===================== device scratch (no allocations) ======================
__device__ float g_h  [Mdim*Cdim];
__device__ float g_rowloss[Mdim];
__device__ float g_pmax[(size_t)Mdim*NPB];
__device__ float g_psum[(size_t)Mdim*NPB];

__device__ __half g_po[2*PHB*Ddim];      // normalized partial attn out
__device__ float  g_pm[2*PHB];           // partial max (log2 domain)
__device__ float  g_pl[2*PHB];           // partial sum

__device__ __half g_wqkv_h[Ldim*C3*Cdim];
__device__ __half g_wff1_h[Ldim*Fdim*Cdim];
__device__ __half g_wff2_h[Ldim*Cdim*Fdim];
__device__ __half g_wlm_h[(size_t)Vdim*Cdim];
__device__ __half g_xn [Mdim*Cdim];
__device__ __half g_ffh[Mdim*Fdim];
__device__ __half g_ah [Mdim*Cdim];
__device__ __half g_qkv[Mdim*C3];

// ===================== asm helpers (baseline sm_80+ ISA) ====================
__device__ __forceinline__ uint32_t smem_to_u32(const void* p) {
    uint32_t a;
    asm("{ .reg .u64 t; cvta.to.shared.u64 t, %1; cvt.u32.u64 %0, t; }" : "=r"(a) : "l"(p));
    return a;
}
__device__ __forceinline__ void cp_async16(uint32_t dst, const void* src){
    asm volatile("cp.async.cg.shared.global [%0], [%1], 16;" :: "r"(dst), "l"(src));
}
#define CP_COMMIT() asm volatile("cp.async.commit_group;" ::: "memory")
#define CP_WAIT0()  asm volatile("cp.async.wait_group 0;" ::: "memory")

__device__ __forceinline__ void ldsm_x4(uint32_t* r, uint32_t addr){
    asm volatile("ldmatrix.sync.aligned.m8n8.x4.shared.b16 {%0,%1,%2,%3}, [%4];"
        : "=r"(r[0]), "=r"(r[1]), "=r"(r[2]), "=r"(r[3]) : "r"(addr));
}
__device__ __forceinline__ void ldsm_x4_t(uint32_t* r, uint32_t addr){
    asm volatile("ldmatrix.sync.aligned.m8n8.x4.trans.shared.b16 {%0,%1,%2,%3}, [%4];"
        : "=r"(r[0]), "=r"(r[1]), "=r"(r[2]), "=r"(r[3]) : "r"(addr));
}
__device__ __forceinline__ void mma_f16(float* d, const uint32_t* a,
                                        uint32_t b0, uint32_t b1){
    asm volatile("mma.sync.aligned.m16n8k16.row.col.f32.f16.f16.f32 "
        "{%0,%1,%2,%3}, {%4,%5,%6,%7}, {%8,%9}, {%0,%1,%2,%3};"
        : "+f"(d[0]), "+f"(d[1]), "+f"(d[2]), "+f"(d[3])
        : "r"(a[0]), "r"(a[1]), "r"(a[2]), "r"(a[3]), "r"(b0), "r"(b1));
}
__device__ __forceinline__ uint32_t pack_half2(float lo, float hi){
    uint32_t r;
    asm("cvt.rn.f16x2.f32 %0, %1, %2;" : "=r"(r) : "f"(hi), "f"(lo));
    return r;
}

// ===================== reductions ===========================================
__device__ __forceinline__ float blockReduceMax(float v){
    __shared__ float sh[8];
    int lid = threadIdx.x & 31, wid = threadIdx.x >> 5;
    #pragma unroll
    for (int o = 16; o > 0; o >>= 1) v = fmaxf(v, __shfl_xor_sync(0xffffffffu, v, o));
    if (lid == 0) sh[wid] = v;
    __syncthreads();
    v = sh[lid & 7];
    #pragma unroll
    for (int o = 4; o > 0; o >>= 1) v = fmaxf(v, __shfl_xor_sync(0xffffffffu, v, o));
    __syncthreads();
    return v;
}
__device__ __forceinline__ float blockReduceSum(float v){
    __shared__ float sh[8];
    int lid = threadIdx.x & 31, wid = threadIdx.x >> 5;
    #pragma unroll
    for (int o = 16; o > 0; o >>= 1) v += __shfl_xor_sync(0xffffffffu, v, o);
    if (lid == 0) sh[wid] = v;
    __syncthreads();
    v = sh[lid & 7];
    #pragma unroll
    for (int o = 4; o > 0; o >>= 1) v += __shfl_xor_sync(0xffffffffu, v, o);
    __syncthreads();
    return v;
}

// ===================== small kernels ========================================
__global__ void cvt_h_k(const float* __restrict__ in, __half* __restrict__ o, long n){
    long stride = (long)gridDim.x * blockDim.x * 4;
    for (long i = ((long)blockIdx.x * blockDim.x + threadIdx.x) * 4; i < n; i += stride){
        float4 v = *(const float4*)(in + i);
        uint2 w;
        w.x = pack_half2(v.x, v.y);
        w.y = pack_half2(v.z, v.w);
        *(uint2*)(o + i) = w;
    }
}

// fused embedding + layer-0 LN1: h = wte[x]+wpe -> g_h, LN(h) -> fp16 xn
__global__ void embed_ln_k(const int* __restrict__ x,
                           const float* __restrict__ wte,
                           const float* __restrict__ wpe,
                           const float* __restrict__ w,
                           const float* __restrict__ b,
                           __half* __restrict__ oh){
    int warp = threadIdx.x >> 5, lane = threadIdx.x & 31;
    int row0 = blockIdx.x * 16 + warp * 2;
    float4 v[2][6];
    float s[2] = {0.f, 0.f}, ss[2] = {0.f, 0.f};
    #pragma unroll
    for (int r = 0; r < 2; r++){
        int row = row0 + r;
        int t = row & (Tdim - 1);
        const float* te = wte + (size_t)x[row] * Cdim;
        const float* pe = wpe + (size_t)t * Cdim;
        float* hp = g_h + (size_t)row * Cdim;
        #pragma unroll
        for (int k = 0; k < 6; k++){
            int c = lane*4 + k*128;
            float4 a = *(const float4*)(te + c);
            float4 p = *(const float4*)(pe + c);
            a.x += p.x; a.y += p.y; a.z += p.z; a.w += p.w;
            v[r][k] = a;
            *(float4*)(hp + c) = a;
            s[r]  += a.x + a.y + a.z + a.w;
            ss[r] += a.x*a.x + a.y*a.y + a.z*a.z + a.w*a.w;
        }
    }
    #pragma unroll
    for (int o = 16; o > 0; o >>= 1){
        #pragma unroll
        for (int r = 0; r < 2; r++){
            s[r]  += __shfl_xor_sync(0xffffffffu, s[r],  o);
            ss[r] += __shfl_xor_sync(0xffffffffu, ss[r], o);
        }
    }
    #pragma unroll
    for (int r = 0; r < 2; r++){
        float mean = s[r] * (1.f / Cdim);
        float var  = ss[r] * (1.f / Cdim) - mean * mean;
        float rstd = rsqrtf(var + 1e-5f);
        #pragma unroll
        for (int k = 0; k < 6; k++){
            int c = lane*4 + k*128;
            float y0 = (v[r][k].x - mean) * rstd * w[c]   + b[c];
            float y1 = (v[r][k].y - mean) * rstd * w[c+1] + b[c+1];
            float y2 = (v[r][k].z - mean) * rstd * w[c+2] + b[c+2];
            float y3 = (v[r][k].w - mean) * rstd * w[c+3] + b[c+3];
            uint2 hw;
            hw.x = pack_half2(y0, y1);
            hw.y = pack_half2(y2, y3);
            *(uint2*)(oh + (size_t)(row0 + r)*Cdim + c) = hw;
        }
    }
}

// warp-per-2-rows layernorm -> single fp16 output (pre-attention LN)
__global__ void ln_k(const float* __restrict__ in,
                     const float* __restrict__ w,
                     const float* __restrict__ b,
                     __half* __restrict__ oh){
    int warp = threadIdx.x >> 5, lane = threadIdx.x & 31;
    int row0 = blockIdx.x * 16 + warp * 2;
    float4 v[2][6];
    float s[2] = {0.f, 0.f}, ss[2] = {0.f, 0.f};
    #pragma unroll
    for (int r = 0; r < 2; r++){
        const float* xp = in + (size_t)(row0 + r) * Cdim;
        #pragma unroll
        for (int k = 0; k < 6; k++)
            v[r][k] = *(const float4*)(xp + lane*4 + k*128);
    }
    #pragma unroll
    for (int r = 0; r < 2; r++)
        #pragma unroll
        for (int k = 0; k < 6; k++){
            s[r]  += v[r][k].x + v[r][k].y + v[r][k].z + v[r][k].w;
            ss[r] += v[r][k].x*v[r][k].x + v[r][k].y*v[r][k].y
                   + v[r][k].z*v[r][k].z + v[r][k].w*v[r][k].w;
        }
    #pragma unroll
    for (int o = 16; o > 0; o >>= 1){
        #pragma unroll
        for (int r = 0; r < 2; r++){
            s[r]  += __shfl_xor_sync(0xffffffffu, s[r],  o);
            ss[r] += __shfl_xor_sync(0xffffffffu, ss[r], o);
        }
    }
    #pragma unroll
    for (int r = 0; r < 2; r++){
        float mean = s[r] * (1.f / Cdim);
        float var  = ss[r] * (1.f / Cdim) - mean * mean;
        float rstd = rsqrtf(var + 1e-5f);
        #pragma unroll
        for (int k = 0; k < 6; k++){
            int c = lane*4 + k*128;
            float y0 = (v[r][k].x - mean) * rstd * w[c]   + b[c];
            float y1 = (v[r][k].y - mean) * rstd * w[c+1] + b[c+1];
            float y2 = (v[r][k].z - mean) * rstd * w[c+2] + b[c+2];
            float y3 = (v[r][k].w - mean) * rstd * w[c+3] + b[c+3];
            uint2 hw;
            hw.x = pack_half2(y0, y1);
            hw.y = pack_half2(y2, y3);
            *(uint2*)(oh + (size_t)(row0 + r)*Cdim + c) = hw;
        }
    }
}

// combine flash partials + residual add + layernorm (post-attention), 2 rows/warp
__global__ void ln_att_k(float* __restrict__ hbuf,
                         const float* __restrict__ w,
                         const float* __restrict__ b,
                         __half* __restrict__ oh){
    int warp = threadIdx.x >> 5, lane = threadIdx.x & 31;
    int row0 = blockIdx.x * 16 + warp * 2;
    float4 v[2][6];
    float s[2] = {0.f, 0.f}, ss[2] = {0.f, 0.f};
    #pragma unroll
    for (int r = 0; r < 2; r++){
        int row = row0 + r;
        int bq = row >> 11;
        int t  = row & 2047;
        float* xp = hbuf + (size_t)row * Cdim;
        #pragma unroll
        for (int k = 0; k < 6; k++){
            int c = lane*4 + k*128;
            float4 a = *(const float4*)(xp + c);
            int head = c >> 6;
            long idx = ((long)(bq*Hdim + head) * Tdim + t);
            float m0 = g_pm[idx],       l0 = g_pl[idx];
            float m1 = g_pm[PHB + idx], l1 = g_pl[PHB + idx];
            float M  = fmaxf(m0, m1);
            float w0 = exp2f(m0 - M) * l0;
            float w1 = exp2f(m1 - M) * l1;
            float inv = 1.f / (w0 + w1);
            int d = c & 63;
            uint2 o0w = *(const uint2*)(g_po + idx*64 + d);
            uint2 o1w = *(const uint2*)(g_po + (PHB + idx)*64 + d);
            __half2 a0 = *(__half2*)&o0w.x, a1 = *(__half2*)&o0w.y;
            __half2 c0 = *(__half2*)&o1w.x, c1 = *(__half2*)&o1w.y;
            float2 f0 = __half22float2(a0), f1 = __half22float2(a1);
            float2 g0 = __half22float2(c0), g1 = __half22float2(c1);
            a.x += (f0.x*w0 + g0.x*w1) * inv;
            a.y += (f0.y*w0 + g0.y*w1) * inv;
            a.z += (f1.x*w0 + g1.x*w1) * inv;
            a.w += (f1.y*w0 + g1.y*w1) * inv;
            v[r][k] = a;
            s[r]  += a.x + a.y + a.z + a.w;
            ss[r] += a.x*a.x + a.y*a.y + a.z*a.z + a.w*a.w;
        }
    }
    #pragma unroll
    for (int o = 16; o > 0; o >>= 1){
        #pragma unroll
        for (int r = 0; r < 2; r++){
            s[r]  += __shfl_xor_sync(0xffffffffu, s[r],  o);
            ss[r] += __shfl_xor_sync(0xffffffffu, ss[r], o);
        }
    }
    #pragma unroll
    for (int r = 0; r < 2; r++){
        int row = row0 + r;
        float* xp = hbuf + (size_t)row * Cdim;
        float mean = s[r] * (1.f / Cdim);
        float var  = ss[r] * (1.f / Cdim) - mean * mean;
        float rstd = rsqrtf(var + 1e-5f);
        #pragma unroll
        for (int k = 0; k < 6; k++){
            int c = lane*4 + k*128;
            *(float4*)(xp + c) = v[r][k];      // residual write-back
            float y0 = (v[r][k].x - mean) * rstd * w[c]   + b[c];
            float y1 = (v[r][k].y - mean) * rstd * w[c+1] + b[c+1];
            float y2 = (v[r][k].z - mean) * rstd * w[c+2] + b[c+2];
            float y3 = (v[r][k].w - mean) * rstd * w[c+3] + b[c+3];
            uint2 hw;
            hw.x = pack_half2(y0, y1);
            hw.y = pack_half2(y2, y3);
            *(uint2*)(oh + (size_t)row*Cdim + c) = hw;
        }
    }
}

// ===================== unified fp16 1-term GEMM (mma.sync) ==================
// C[M,N] = A[M,K] @ B[N,K]^T. K-stage 64 (row stride 144B). Split-K via gridDim.z.
// modes: 0: out_f = acc (bounds-checked) + LSE partials (lm_head)
//        1: out_h = relu(acc+bias) fp16
//        2: atomicAdd(out_f, acc [+bias if z==0])
//        3: out_h = acc+bias fp16
#define G1_MAT  18432            /* 128 rows * 144 bytes */
#define G1_STG  (2*G1_MAT)
#define G1_SMEM (2*G1_STG)       /* 73728 */

__global__ __launch_bounds__(256, 2) void gemm_1t_k(
        const __half* __restrict__ A, const __half* __restrict__ Bm,
        const float* __restrict__ bias,
        float* __restrict__ out_f, __half* __restrict__ out_h,
        float* __restrict__ pmax, float* __restrict__ psum,
        int N, int K, int mode){
    extern __shared__ char smem[];
    uint32_t sbase = smem_to_u32(smem);
    int tid = threadIdx.x, wid = tid >> 5, lane = tid & 31;
    int warpRow = wid >> 2, warpCol = wid & 3;

    long row0 = (long)blockIdx.x * 128;
    long n0   = (long)blockIdx.y * 128;
    int kspan = K / (int)gridDim.z;
    long kbase = (long)blockIdx.z * kspan;
    int nIter = kspan >> 6;

    float acc[4][4][4];
    #pragma unroll
    for (int i = 0; i < 4; i++)
        #pragma unroll
        for (int j = 0; j < 4; j++)
            #pragma unroll
            for (int q = 0; q < 4; q++) acc[i][j][q] = 0.f;

    auto issue = [&](int it){
        if (it >= nIter) return;
        long k0 = kbase + ((long)it << 6);
        uint32_t stg = sbase + (uint32_t)(it & 1) * G1_STG;
        #pragma unroll
        for (int j = 0; j < 8; j++){
            int c   = tid + j * 256;           // 0..2047 (16B chunks)
            int mat = c >> 10;                 // 0:A 1:B
            int rem = c & 1023;
            int row = rem >> 3;                // 0..127
            int h8  = (rem & 7) << 3;          // half index 0..56
            const __half* src;
            if (mat == 0){
                src = A + (row0 + row) * (long)K + k0 + h8;
            } else {
                long br = n0 + row; if (br >= N) br = 0;
                src = Bm + br * (long)K + k0 + h8;
            }
            uint32_t dst = stg + (uint32_t)(mat * G1_MAT + row * 144 + h8 * 2);
            cp_async16(dst, src);
        }
        CP_COMMIT();
    };

    issue(0);
    for (int it = 0; it < nIter; it++){
        CP_WAIT0();
        __syncthreads();        // data(it) visible + all warps done with compute(it-1)
        issue(it + 1);

        uint32_t stg = sbase + (uint32_t)(it & 1) * G1_STG;
        uint32_t aS = stg;
        uint32_t bS = stg + G1_MAT;
        uint32_t rsel = (uint32_t)(lane & 15) * 144 + (uint32_t)(lane >> 4) * 16;

        #pragma unroll
        for (int ks = 0; ks < 64; ks += 16){
            uint32_t bf[2][4];
            #pragma unroll
            for (int nj = 0; nj < 2; nj++){
                uint32_t off = (uint32_t)((warpCol*32 + nj*16) * 144 + ks*2) + rsel;
                ldsm_x4(bf[nj], bS + off);
            }
            #pragma unroll
            for (int mi = 0; mi < 4; mi++){
                uint32_t af[4];
                uint32_t off = (uint32_t)((warpRow*64 + mi*16) * 144 + ks*2) + rsel;
                ldsm_x4(af, aS + off);
                #pragma unroll
                for (int ni = 0; ni < 4; ni++){
                    int nj = ni >> 1, w = ni & 1;
                    mma_f16(acc[mi][ni], af, bf[nj][w], bf[nj][w+2]);
                }
            }
        }
    }

    if (mode == 0){
        // scalar stores: logits base pointer may be only 4B-aligned (out+1)
        #pragma unroll
        for (int mi = 0; mi < 4; mi++){
            long r0 = row0 + warpRow*64 + mi*16 + (lane >> 2);
            #pragma unroll
            for (int ni = 0; ni < 4; ni++){
                long c0 = n0 + warpCol*32 + ni*8 + (lane & 3)*2;
                #pragma unroll
                for (int half = 0; half < 2; half++){
                    long r = r0 + half*8;
                    #pragma unroll
                    for (int e = 0; e < 2; e++){
                        long n = c0 + e;
                        if (n < N)
                            out_f[r * (long)N + n] = acc[mi][ni][half*2 + e];
                    }
                }
            }
        }
        // fused LSE partials for this 128x128 block
        __syncthreads();
        float* pm_s = (float*)smem;            // [128][4]
        float* ps_s = (float*)smem + 512;      // [128][4]
        #pragma unroll
        for (int mi = 0; mi < 4; mi++){
            #pragma unroll
            for (int half = 0; half < 2; half++){
                int lr = warpRow*64 + mi*16 + (lane >> 2) + half*8;
                float vv[8];
                float lm = -1e30f;
                #pragma unroll
                for (int ni = 0; ni < 4; ni++)
                    #pragma unroll
                    for (int e = 0; e < 2; e++){
                        long n = n0 + warpCol*32 + ni*8 + (lane & 3)*2 + e;
                        float t = (n < N) ? acc[mi][ni][half*2 + e] : -1e30f;
                        vv[ni*2 + e] = t;
                        lm = fmaxf(lm, t);
                    }
                lm = fmaxf(lm, __shfl_xor_sync(0xffffffffu, lm, 1));
                lm = fmaxf(lm, __shfl_xor_sync(0xffffffffu, lm, 2));
                float ls = 0.f;
                #pragma unroll
                for (int q = 0; q < 8; q++) ls += __expf(vv[q] - lm);
                ls += __shfl_xor_sync(0xffffffffu, ls, 1);
                ls += __shfl_xor_sync(0xffffffffu, ls, 2);
                if ((lane & 3) == 0){
                    pm_s[lr*4 + warpCol] = lm;
                    ps_s[lr*4 + warpCol] = ls;
                }
            }
        }
        __syncthreads();
        if (tid < 128){
            float m0 = pm_s[tid*4], m1 = pm_s[tid*4+1], m2 = pm_s[tid*4+2], m3 = pm_s[tid*4+3];
            float M = fmaxf(fmaxf(m0, m1), fmaxf(m2, m3));
            float S = ps_s[tid*4]  *__expf(m0 - M) + ps_s[tid*4+1]*__expf(m1 - M)
                    + ps_s[tid*4+2]*__expf(m2 - M) + ps_s[tid*4+3]*__expf(m3 - M);
            long r = row0 + tid;
            pmax[r*NPB + blockIdx.y] = M;
            psum[r*NPB + blockIdx.y] = S;
        }
        return;
    }

    bool addBias = (blockIdx.z == 0);
    #pragma unroll
    for (int mi = 0; mi < 4; mi++){
        long r0 = row0 + warpRow*64 + mi*16 + (lane >> 2);
        #pragma unroll
        for (int ni = 0; ni < 4; ni++){
            long c0 = n0 + warpCol*32 + ni*8 + (lane & 3)*2;
            float b0 = addBias ? bias[c0]     : 0.f;
            float b1 = addBias ? bias[c0 + 1] : 0.f;
            #pragma unroll
            for (int half = 0; half < 2; half++){
                long r  = r0 + half*8;
                long oi = r * (long)N + c0;
                float v0 = acc[mi][ni][half*2]     + b0;
                float v1 = acc[mi][ni][half*2 + 1] + b1;
                if (mode == 2){
                    atomicAdd(out_f + oi,     v0);
                    atomicAdd(out_f + oi + 1, v1);
                } else {
                    if (mode == 1){
                        v0 = fmaxf(v0, 0.f);
                        v1 = fmaxf(v1, 0.f);
                    }
                    *(uint32_t*)(out_h + oi) = pack_half2(v0, v1);
                }
            }
        }
    }
}

// ===================== flash attention (split-KV x2, partial outputs) =======
#define FA_QB    (128*144)               /* 18432 */
#define FA_KVMAT (128*144)               /* 18432 per matrix per stage */
#define FA_STGB  (2*FA_KVMAT)            /* 36864 */
#define FA_SMEM  (FA_QB + 2*FA_STGB)     /* 92160 */

__global__ __launch_bounds__(256, 2) void flash_k(const __half* __restrict__ qkv){
    extern __shared__ char smem[];
    uint32_t sb = smem_to_u32(smem);
    uint32_t Qs = sb;
    uint32_t kvb = sb + FA_QB;

    int tid = threadIdx.x, wid = tid >> 5, lane = tid & 31;
    int g = lane >> 2, tq = lane & 3;
    int qb = (int)gridDim.x - 1 - (int)blockIdx.x;
    int bh = blockIdx.y; int bq = bh / Hdim, head = bh % Hdim;
    int z = blockIdx.z;
    int q0 = qb * 128;
    long rowbase = (long)bq * Tdim;
    int t0w = q0 + wid*16;

    int nkv = qb + 1;
    int half_n = (nkv + 1) >> 1;
    int js = z ? half_n : 0;
    int je = z ? nkv : half_n;
    int cnt = je - js;
    long pbase = (long)z * PHB + (long)bh * Tdim;

    if (cnt <= 0){
        #pragma unroll
        for (int r = 0; r < 2; r++){
            long t = (long)t0w + g + r*8;
            long pr = pbase + t;
            if (tq == 0){ g_pm[pr] = -1e30f; g_pl[pr] = 0.f; }
            #pragma unroll
            for (int dt = 0; dt < 8; dt++)
                *(uint32_t*)(g_po + pr*64 + dt*8 + tq*2) = 0u;
        }
        return;
    }

    #pragma unroll
    for (int j = 0; j < 4; j++){
        int id = tid + j*256;                 // 0..1023
        int row = id >> 3, c8 = (id & 7) << 3;
        const __half* src = qkv + (rowbase + q0 + row)*(long)C3 + head*Ddim + c8;
        cp_async16(Qs + (uint32_t)(row*144 + c8*2), src);
    }

    auto issue = [&](int it){
        if (it >= cnt) return;
        int s0 = (js + it) * 128;
        uint32_t stg = kvb + (uint32_t)(it & 1) * FA_STGB;
        #pragma unroll
        for (int jj = 0; jj < 8; jj++){
            int id = tid + jj*256;            // 0..2047
            int mat = id >> 10, rem = id & 1023;  // 0:K 1:V
            int row = rem >> 3, c8 = (rem & 7) << 3;
            int coff = mat ? 2*Cdim : Cdim;
            const __half* src = qkv
                + (rowbase + s0 + row)*(long)C3 + coff + head*Ddim + c8;
            cp_async16(stg + (uint32_t)(mat*FA_KVMAT + row*144 + c8*2), src);
        }
        CP_COMMIT();
    };

    // log2-domain softmax: scores scaled by 0.125*log2(e)
    const float SC2 = 0.18033688f;
    float mrow[2] = {-1e30f, -1e30f};
    float lrow[2] = {0.f, 0.f};
    float oacc[8][4];
    #pragma unroll
    for (int i = 0; i < 8; i++)
        #pragma unroll
        for (int e = 0; e < 4; e++) oacc[i][e] = 0.f;

    uint32_t rsel16 = (uint32_t)(lane & 15)*144 + (uint32_t)(lane >> 4)*16;
    int vtsel = lane >> 3, vrt = lane & 7;
    uint32_t vrow_off = ((vtsel >> 1) ? 8u : 0u) + (uint32_t)vrt;
    uint32_t vcol_off = (vtsel & 1) ? 16u : 0u;

    issue(0);
    for (int it = 0; it < cnt; it++){
        CP_WAIT0();
        __syncthreads();
        issue(it + 1);

        uint32_t stg = kvb + (uint32_t)(it & 1) * FA_STGB;
        #pragma unroll
        for (int sub = 0; sub < 2; sub++){
            int s0 = (js + it) * 128 + sub * 64;
            if (s0 > t0w + 15) continue;
            uint32_t Kh = stg + (uint32_t)sub * (64*144);
            uint32_t Vh = stg + FA_KVMAT + (uint32_t)sub * (64*144);

            float S[8][4];
            #pragma unroll
            for (int i = 0; i < 8; i++)
                #pragma unroll
                for (int e = 0; e < 4; e++) S[i][e] = 0.f;

            #pragma unroll
            for (int dc = 0; dc < 4; dc++){
                uint32_t aoff = (uint32_t)(wid*16)*144 + (uint32_t)dc*32 + rsel16;
                uint32_t ah[4];
                ldsm_x4(ah, Qs + aoff);
                #pragma unroll
                for (int ng = 0; ng < 4; ng++){
                    uint32_t boff = (uint32_t)(ng*16)*144 + (uint32_t)dc*32 + rsel16;
                    uint32_t kh[4];
                    ldsm_x4(kh, Kh + boff);
                    #pragma unroll
                    for (int w = 0; w < 2; w++)
                        mma_f16(S[ng*2+w], ah, kh[w], kh[w+2]);
                }
            }

            bool needMask = (s0 + 63 > t0w);
            #pragma unroll
            for (int ns = 0; ns < 8; ns++)
                #pragma unroll
                for (int e = 0; e < 4; e++){
                    float v = S[ns][e] * SC2;
                    if (needMask){
                        int t = t0w + g + (e >> 1)*8;
                        int s = s0 + ns*8 + tq*2 + (e & 1);
                        if (s > t) v = -1e30f;
                    }
                    S[ns][e] = v;
                }

            #pragma unroll
            for (int r = 0; r < 2; r++){
                float mx = -1e30f;
                #pragma unroll
                for (int ns = 0; ns < 8; ns++)
                    mx = fmaxf(mx, fmaxf(S[ns][r*2], S[ns][r*2+1]));
                mx = fmaxf(mx, __shfl_xor_sync(0xffffffffu, mx, 1));
                mx = fmaxf(mx, __shfl_xor_sync(0xffffffffu, mx, 2));
                float mnew = fmaxf(mrow[r], mx);
                float corr = exp2f(mrow[r] - mnew);
                mrow[r] = mnew;
                float lsum = 0.f;
                #pragma unroll
                for (int ns = 0; ns < 8; ns++){
                    float p0 = exp2f(S[ns][r*2]   - mnew);
                    float p1 = exp2f(S[ns][r*2+1] - mnew);
                    S[ns][r*2] = p0; S[ns][r*2+1] = p1;
                    lsum += p0 + p1;
                }
                lsum += __shfl_xor_sync(0xffffffffu, lsum, 1);
                lsum += __shfl_xor_sync(0xffffffffu, lsum, 2);
                lrow[r] = lrow[r]*corr + lsum;
                #pragma unroll
                for (int dt = 0; dt < 8; dt++){
                    oacc[dt][r*2]   *= corr;
                    oacc[dt][r*2+1] *= corr;
                }
            }

            #pragma unroll
            for (int sc = 0; sc < 4; sc++){
                uint32_t ph[4];
                #pragma unroll
                for (int half = 0; half < 2; half++){
                    int ns = sc*2 + half;
                    ph[half*2+0] = pack_half2(S[ns][0], S[ns][1]);
                    ph[half*2+1] = pack_half2(S[ns][2], S[ns][3]);
                }
                uint32_t vbase = (uint32_t)((sc*16 + vrow_off)*144) + vcol_off;
                #pragma unroll
                for (int dg = 0; dg < 4; dg++){
                    uint32_t vh_[4];
                    ldsm_x4_t(vh_, Vh + vbase + (uint32_t)dg*32);
                    #pragma unroll
                    for (int w = 0; w < 2; w++)
                        mma_f16(oacc[dg*2 + w], ph, vh_[w], vh_[w+2]);
                }
            }
        }
    }

    // write partials: normalized o (fp16), m (log2 domain), l
    #pragma unroll
    for (int r = 0; r < 2; r++){
        float inv = 1.f / lrow[r];
        long t = (long)t0w + g + r*8;
        long pr = pbase + t;
        if (tq == 0){ g_pm[pr] = mrow[r]; g_pl[pr] = lrow[r]; }
        #pragma unroll
        for (int dt = 0; dt < 8; dt++)
            *(uint32_t*)(g_po + pr*64 + dt*8 + tq*2) =
                pack_half2(oacc[dt][r*2] * inv, oacc[dt][r*2+1] * inv);
    }
}

// ===================== loss from LSE partials ================================
__global__ void loss_row2_k(const float* __restrict__ logits,
                            const int* __restrict__ target){
    int row = blockIdx.x, tid = threadIdx.x;
    const float* pm = g_pmax + (size_t)row * NPB;
    const float* ps = g_psum + (size_t)row * NPB;
    float m = -1e30f, s = 0.f;
    for (int i = tid; i < NPB; i += 256){
        float im = pm[i], is = ps[i];
        if (im > m){
            s = s * __expf(m - im) + is;
            m = im;
        } else {
            s += is * __expf(im - m);
        }
    }
    float mg = blockReduceMax(m);
    s *= __expf(m - mg);
    float tot = blockReduceSum(s);
    if (tid == 0){
        float lse = logf(tot) + mg;
        g_rowloss[row] = lse - logits[(size_t)row * Vdim + target[row]];
    }
}
__global__ void loss_reduce_k(float* out){
    float s = 0.f;
    for (int i = threadIdx.x; i < Mdim; i += 256) s += g_rowloss[i];
    s = blockReduceSum(s);
    if (threadIdx.x == 0) out[0] = s / (float)Mdim;
}

// ===================== launch ===============================================
extern "C" void kernel_launch(void* const* d_in, const int* in_sizes, int n_in,
                              void* d_out, int out_size){
    const int*   x      = (const int*)  d_in[0];
    const int*   target = (const int*)  d_in[1];
    const float* wte    = (const float*)d_in[2];
    const float* wpe    = (const float*)d_in[3];
    const float* ln1_w  = (const float*)d_in[4];
    const float* ln1_b  = (const float*)d_in[5];
    const float* attn_w = (const float*)d_in[6];
    const float* attn_b = (const float*)d_in[7];
    const float* ln2_w  = (const float*)d_in[8];
    const float* ln2_b  = (const float*)d_in[9];
    const float* ff1_w  = (const float*)d_in[10];
    const float* ff1_b  = (const float*)d_in[11];
    const float* ff2_w  = (const float*)d_in[12];
    const float* ff2_b  = (const float*)d_in[13];
    const float* lm_w   = (const float*)d_in[14];

    float* out = (float*)d_out;
    bool has_loss = ((long long)out_size == (long long)Mdim * Vdim + 1);
    float* logits = has_loss ? out + 1 : out;

    cudaFuncSetAttribute(gemm_1t_k, cudaFuncAttributeMaxDynamicSharedMemorySize, G1_SMEM);
    cudaFuncSetAttribute(flash_k,   cudaFuncAttributeMaxDynamicSharedMemorySize, FA_SMEM);

    float* ph;
    cudaGetSymbolAddress((void**)&ph, g_h);
    __half *wqk,*wf1,*wf2,*wlm,*xn,*ffh,*ah,*qv;
    float *ppm,*pps;
    cudaGetSymbolAddress((void**)&wqk, g_wqkv_h);
    cudaGetSymbolAddress((void**)&wf1, g_wff1_h);
    cudaGetSymbolAddress((void**)&wf2, g_wff2_h);
    cudaGetSymbolAddress((void**)&wlm, g_wlm_h);
    cudaGetSymbolAddress((void**)&xn,  g_xn);
    cudaGetSymbolAddress((void**)&ffh, g_ffh);
    cudaGetSymbolAddress((void**)&ah,  g_ah);
    cudaGetSymbolAddress((void**)&qv,  g_qkv);
    cudaGetSymbolAddress((void**)&ppm, g_pmax);
    cudaGetSymbolAddress((void**)&pps, g_psum);

    cvt_h_k<<<2048, 256>>>(attn_w, wqk, (long)Ldim*C3*Cdim);
    cvt_h_k<<<2048, 256>>>(ff1_w,  wf1, (long)Ldim*Fdim*Cdim);
    cvt_h_k<<<2048, 256>>>(ff2_w,  wf2, (long)Ldim*Cdim*Fdim);
    cvt_h_k<<<4096, 256>>>(lm_w,   wlm, (long)Vdim*Cdim);

    for (int l = 0; l < Ldim; l++){
        if (l == 0)
            embed_ln_k<<<Mdim/16, 256>>>(x, wte, wpe, ln1_w, ln1_b, xn);
        else
            ln_k<<<Mdim/16, 256>>>(ph, ln1_w + (size_t)l*Cdim, ln1_b + (size_t)l*Cdim, xn);

        gemm_1t_k<<<dim3(Mdim/128, C3/128, 1), 256, G1_SMEM>>>(
            xn, wqk + (size_t)l*C3*Cdim, attn_b + (size_t)l*C3,
            nullptr, qv, nullptr, nullptr, C3, Cdim, 3);

        flash_k<<<dim3(Tdim/128, Bdim*Hdim, 2), 256, FA_SMEM>>>(qv);

        ln_att_k<<<Mdim/16, 256>>>(ph, ln2_w + (size_t)l*Cdim, ln2_b + (size_t)l*Cdim, xn);

        gemm_1t_k<<<dim3(Mdim/128, Fdim/128, 1), 256, G1_SMEM>>>(
            xn, wf1 + (size_t)l*Fdim*Cdim, ff1_b + (size_t)l*Fdim,
            nullptr, ffh, nullptr, nullptr, Fdim, Cdim, 1);

        gemm_1t_k<<<dim3(Mdim/128, Cdim/128, 3), 256, G1_SMEM>>>(
            ffh, wf2 + (size_t)l*Cdim*Fdim, ff2_b + (size_t)l*Cdim,
            ph, nullptr, nullptr, nullptr, Cdim, Fdim, 2);
    }

    cvt_h_k<<<2048, 256>>>(ph, ah, (long)Mdim*Cdim);

    gemm_1t_k<<<dim3(Mdim/128, NPB, 1), 256, G1_SMEM>>>(
        ah, wlm, nullptr, logits, nullptr, ppm, pps, Vdim, Cdim, 0);

    loss_row2_k<<<Mdim, 256>>>(logits, target);
    if (has_loss)
        loss_reduce_k<<<1, 256>>>(out);
}